// round 7
// baseline (speedup 1.0000x reference)
#include <cuda_runtime.h>
#include <cuda_bf16.h>
#include <cstdint>

#define TPB 1024
static constexpr int Bn = 1024, Pn = 100, Nn = 101, EMBn = 128;
static constexpr int Hn = 8, DKn = 16;

static constexpr int STB = 40;       // bf16 row stride inside chunk tiles (80B, conflict-free)
static constexpr int CHB = 10240;    // bytes per chunk matrix: 128 rows * 40 bf16 * 2B
// ---- smem byte map ----
static constexpr int SB_H = 0;              // B chunk hi (lo at +CHB)
static constexpr int SA_H = 20480;          // A chunk hi (lo at +CHB)
static constexpr int OFF_QF = 40960;        // Q / out_concat / scores [100][132] f32
static constexpr int OFF_KF = 93760;        // K / mh                  [101][132] f32
static constexpr int OFF_VF = 147088;       // V                       [101][132] f32
static constexpr int OFF_EX = 200416;       // extras [100][4] f32
static constexpr int OFF_WQ4 = 202016;      // Wq rows 128..131  [4][128] f32
static constexpr int OFF_BC = 204064;       // bc [128] f32
static constexpr int SMEM_TOTAL = 204576;
static constexpr int LDSR = 132;            // f32 row stride

// ---------------- prep: weights -> chunk-blocked bf16 hi/lo, B^T layout ----
__device__ __nv_bfloat16 g_wt[4][40960];
__device__ float g_wq4[512];

__global__ void prep_weights(const float* __restrict__ Wq, const float* __restrict__ Wk,
                             const float* __restrict__ Wv, const float* __restrict__ Wc)
{
    const int w = blockIdx.x;
    const float* W = (w == 0) ? Wq : (w == 1) ? Wk : (w == 2) ? Wv : Wc;
    for (int idx = threadIdx.x; idx < 128 * 128; idx += blockDim.x) {
        int n = idx >> 7, k = idx & 127;
        float x = W[k * 128 + n];
        __nv_bfloat16 h = __float2bfloat16(x);
        __nv_bfloat16 l = __float2bfloat16(x - __bfloat162float(h));
        int o = (k >> 5) * 10240 + n * STB + (k & 31);
        g_wt[w][o] = h;
        g_wt[w][o + 5120] = l;
    }
    if (w == 0) {
        for (int i = threadIdx.x; i < 512; i += blockDim.x)
            g_wq4[i] = Wq[128 * 128 + i];
    }
}

// ---------------- device helpers ----------------
__device__ __forceinline__ uint32_t smem_u32(const void* p) {
    uint32_t a;
    asm("{ .reg .u64 t; cvta.to.shared.u64 t, %1; cvt.u32.u64 %0, t; }" : "=r"(a) : "l"(p));
    return a;
}
__device__ __forceinline__ float tanh10(float x) {
    x = fminf(fmaxf(x, -20.f), 20.f);
    float t = __expf(2.f * x);
    return 10.f * (t - 1.f) / (t + 1.f);
}

#define LDSM4(R0, R1, R2, R3, ADDR) \
    asm volatile("ldmatrix.sync.aligned.m8n8.x4.shared.b16 {%0,%1,%2,%3}, [%4];" \
        : "=r"(R0), "=r"(R1), "=r"(R2), "=r"(R3) : "r"(ADDR))

#define MMA16816(C, A, B0, B1) \
    asm volatile("mma.sync.aligned.m16n8k16.row.col.f32.bf16.bf16.f32 " \
        "{%0,%1,%2,%3}, {%4,%5,%6,%7}, {%8,%9}, {%0,%1,%2,%3};" \
        : "+f"((C)[0]), "+f"((C)[1]), "+f"((C)[2]), "+f"((C)[3]) \
        : "r"((A)[0]), "r"((A)[1]), "r"((A)[2]), "r"((A)[3]), "r"(B0), "r"(B1))

// build one 128x32 hi/lo bf16 chunk from f32 row-major source
__device__ __forceinline__ void build_half(
    __nv_bfloat16* __restrict__ dst, const float* __restrict__ src,
    int ld, int nrows, int k0, const float* __restrict__ biasK)
{
    for (int i = threadIdx.x; i < 1024; i += TPB) {
        int r = i >> 3, q = (i & 7) << 2;
        float4 v = make_float4(0.f, 0.f, 0.f, 0.f);
        if (r < nrows) v = *(const float4*)&src[(size_t)r * ld + k0 + q];
        if (biasK) {
            v.x += biasK[k0 + q];     v.y += biasK[k0 + q + 1];
            v.z += biasK[k0 + q + 2]; v.w += biasK[k0 + q + 3];
        }
        __nv_bfloat162 h01 = __floats2bfloat162_rn(v.x, v.y);
        __nv_bfloat162 h23 = __floats2bfloat162_rn(v.z, v.w);
        __nv_bfloat162 l01 = __floats2bfloat162_rn(v.x - __bfloat162float(h01.x),
                                                   v.y - __bfloat162float(h01.y));
        __nv_bfloat162 l23 = __floats2bfloat162_rn(v.z - __bfloat162float(h23.x),
                                                   v.w - __bfloat162float(h23.y));
        int o = r * STB + q;
        *(__nv_bfloat162*)(dst + o)            = h01;
        *(__nv_bfloat162*)(dst + o + 2)        = h23;
        *(__nv_bfloat162*)(dst + 5120 + o)     = l01;
        *(__nv_bfloat162*)(dst + 5120 + o + 2) = l23;
    }
}

// C = A @ B via mma.sync, hi/lo split (3 products, fragments loaded once).
// 32 warps: warp (wm,wn) owns rows wm*16..+15, cols wn*32..+31.
__device__ __noinline__ void gemm128(
    unsigned char* smem8, uint32_t sb,
    const float* __restrict__ Asrc, int Ald, int Anrows, const float* __restrict__ biasK,
    int wsel, const float* __restrict__ Bf32, int Bnrows,
    float* __restrict__ Cdst, int Cnrows)
{
    const int tid = threadIdx.x, w = tid >> 5, lane = tid & 31;
    const int wm = w & 7, wn = w >> 3;

    float acc[4][4];
#pragma unroll
    for (int n = 0; n < 4; n++)
#pragma unroll
        for (int j = 0; j < 4; j++) acc[n][j] = 0.f;

    const uint32_t aaddr0 = sb + SA_H +
        (uint32_t)(((wm * 16 + (lane & 15)) * STB + ((lane >> 4) << 3)) << 1);
    const uint32_t baddr0 = sb + SB_H +
        (uint32_t)(((wn * 32 + ((lane & 16) ? 8 : 0) + (lane & 7)) * STB
                    + ((lane & 8) ? 8 : 0)) << 1);

    for (int c = 0; c < 4; c++) {
        __syncthreads();
        const int k0 = c * 32;
        build_half((__nv_bfloat16*)(smem8 + SA_H), Asrc, Ald, Anrows, k0, biasK);
        if (wsel >= 0) {
            const uint4* src = (const uint4*)&g_wt[wsel][c * 10240];
            uint4* dst = (uint4*)(smem8 + SB_H);
            for (int i = tid; i < 1280; i += TPB) dst[i] = src[i];
        } else {
            build_half((__nv_bfloat16*)(smem8 + SB_H), Bf32, 128, Bnrows, k0, nullptr);
        }
        __syncthreads();

#pragma unroll
        for (int ks = 0; ks < 2; ks++) {
            const uint32_t kboff = (uint32_t)(ks * 32);   // 16 bf16 = 32B
            uint32_t aH[4], aL[4];
            LDSM4(aH[0], aH[1], aH[2], aH[3], aaddr0 + kboff);
            LDSM4(aL[0], aL[1], aL[2], aL[3], aaddr0 + kboff + CHB);
            uint32_t bH[4][2], bL[4][2];
#pragma unroll
            for (int t = 0; t < 2; t++) {
                const uint32_t ba = baddr0 + (uint32_t)(t * 16 * STB * 2) + kboff;
                uint32_t r0, r1, r2, r3;
                LDSM4(r0, r1, r2, r3, ba);
                bH[2 * t][0] = r0;     bH[2 * t][1] = r1;
                bH[2 * t + 1][0] = r2; bH[2 * t + 1][1] = r3;
                LDSM4(r0, r1, r2, r3, ba + CHB);
                bL[2 * t][0] = r0;     bL[2 * t][1] = r1;
                bL[2 * t + 1][0] = r2; bL[2 * t + 1][1] = r3;
            }
#pragma unroll
            for (int n = 0; n < 4; n++) MMA16816(acc[n], aH, bH[n][0], bH[n][1]);
#pragma unroll
            for (int n = 0; n < 4; n++) MMA16816(acc[n], aH, bL[n][0], bL[n][1]);
#pragma unroll
            for (int n = 0; n < 4; n++) MMA16816(acc[n], aL, bH[n][0], bH[n][1]);
        }
    }
    __syncthreads();
#pragma unroll
    for (int n = 0; n < 4; n++) {
        const int row = wm * 16 + (lane >> 2);
        const int col = wn * 32 + n * 8 + ((lane & 3) << 1);
        if (row < Cnrows)
            *(float2*)&Cdst[row * LDSR + col] = make_float2(acc[n][0], acc[n][1]);
        if (row + 8 < Cnrows)
            *(float2*)&Cdst[(row + 8) * LDSR + col] = make_float2(acc[n][2], acc[n][3]);
    }
    __syncthreads();
}

extern __shared__ __align__(16) unsigned char smem8[];

__global__ __launch_bounds__(TPB, 1)
void vrp_decoder_kernel(
    const float* __restrict__ eln,   const float* __restrict__ load_,
    const float* __restrict__ time_, const float* __restrict__ len_,
    const float* __restrict__ ropen, const float* __restrict__ mask,
    const float* __restrict__ nodes, const float* __restrict__ bc,
    float* __restrict__ out)
{
    const int b = blockIdx.x;
    const int tid = threadIdx.x;
    const int wid = tid >> 5, lane = tid & 31;
    const uint32_t sb = smem_u32(smem8);

    float* sQf  = (float*)(smem8 + OFF_QF);
    float* sKf  = (float*)(smem8 + OFF_KF);
    float* sVf  = (float*)(smem8 + OFF_VF);
    float* sEx  = (float*)(smem8 + OFF_EX);
    float* sWq4 = (float*)(smem8 + OFF_WQ4);
    float* sBc  = (float*)(smem8 + OFF_BC);

    // ---- stage aux ----
    for (int i = tid; i < 512; i += TPB) sWq4[i] = g_wq4[i];
    for (int i = tid; i < 128; i += TPB) sBc[i] = bc[i];
    for (int r = tid; r < Pn; r += TPB) {
        sEx[r * 4 + 0] = load_[b * Pn + r];
        sEx[r * 4 + 1] = time_[b * Pn + r];
        sEx[r * 4 + 2] = len_[b * Pn + r];
        sEx[r * 4 + 3] = ropen[b * Pn + r];
    }

    const float* gE = eln + (size_t)b * Pn * EMBn;
    const float* gN = nodes + (size_t)b * Nn * EMBn;

    // ---- Q = eln @ Wq[0:128] ----
    gemm128(smem8, sb, gE, EMBn, Pn, nullptr, 0, nullptr, 0, sQf, Pn);
    // 4-extra-feature correction
    for (int i = tid; i < Pn * 32; i += TPB) {
        int r = i >> 5, cq = (i & 31) << 2;
        float4 qv = *(float4*)&sQf[r * LDSR + cq];
        float e0 = sEx[r * 4 + 0], e1 = sEx[r * 4 + 1];
        float e2 = sEx[r * 4 + 2], e3 = sEx[r * 4 + 3];
        qv.x += e0 * sWq4[cq + 0] + e1 * sWq4[128 + cq + 0] + e2 * sWq4[256 + cq + 0] + e3 * sWq4[384 + cq + 0];
        qv.y += e0 * sWq4[cq + 1] + e1 * sWq4[128 + cq + 1] + e2 * sWq4[256 + cq + 1] + e3 * sWq4[384 + cq + 1];
        qv.z += e0 * sWq4[cq + 2] + e1 * sWq4[128 + cq + 2] + e2 * sWq4[256 + cq + 2] + e3 * sWq4[384 + cq + 2];
        qv.w += e0 * sWq4[cq + 3] + e1 * sWq4[128 + cq + 3] + e2 * sWq4[256 + cq + 3] + e3 * sWq4[384 + cq + 3];
        *(float4*)&sQf[r * LDSR + cq] = qv;
    }
    // ---- K, V = nodes @ Wk / Wv ----
    gemm128(smem8, sb, gN, EMBn, Nn, nullptr, 1, nullptr, 0, sKf, Nn);
    gemm128(smem8, sb, gN, EMBn, Nn, nullptr, 2, nullptr, 0, sVf, Nn);

    // ---- attention: work item = (row p, head h): 800 items over 32 warps.
    // Item (p,h) is the sole reader AND writer of Q[p][16h..16h+15] -> in-place safe.
    const float* gM = mask + (size_t)b * Pn * Nn;
    const int NWARP = TPB / 32;
    for (int it = wid; it < Pn * Hn; it += NWARP) {
        const int p = it >> 3, h = it & 7;
        const int ho = h * DKn;
        const float* qr = &sQf[p * LDSR + ho];

        float s[4];
#pragma unroll
        for (int j = 0; j < 4; j++) {
            const int n = lane + 32 * j;
            const int ncj = n < Nn ? n : 0;
            const float* kr = &sKf[ncj * LDSR + ho];
            float dot = 0.f;
#pragma unroll
            for (int t = 0; t < 4; t++) {
                float4 q4 = *(const float4*)&qr[4 * t];     // broadcast
                float4 k4 = *(const float4*)&kr[4 * t];
                dot += q4.x * k4.x + q4.y * k4.y + q4.z * k4.z + q4.w * k4.w;
            }
            s[j] = (n < Nn) ? (dot * 0.25f + gM[p * Nn + n]) : -INFINITY;
        }
        // softmax over n
        float mx = fmaxf(fmaxf(s[0], s[1]), fmaxf(s[2], s[3]));
#pragma unroll
        for (int off = 16; off; off >>= 1)
            mx = fmaxf(mx, __shfl_xor_sync(0xffffffffu, mx, off));
        float sum = 0.f;
#pragma unroll
        for (int j = 0; j < 4; j++) { s[j] = __expf(s[j] - mx); sum += s[j]; }
#pragma unroll
        for (int off = 16; off; off >>= 1)
            sum += __shfl_xor_sync(0xffffffffu, sum, off);
        const float inv = 1.f / sum;
#pragma unroll
        for (int j = 0; j < 4; j++) s[j] *= inv;

        // PV partials
        float v[16];
#pragma unroll
        for (int d = 0; d < 16; d++) v[d] = 0.f;
#pragma unroll
        for (int j = 0; j < 4; j++) {
            const int n = lane + 32 * j;
            const int ncj = n < Nn ? n : 0;
            const float* vr = &sVf[ncj * LDSR + ho];
            const float wj = s[j];
#pragma unroll
            for (int t = 0; t < 4; t++) {
                float4 v4 = *(const float4*)&vr[4 * t];
                v[4 * t + 0] += wj * v4.x; v[4 * t + 1] += wj * v4.y;
                v[4 * t + 2] += wj * v4.z; v[4 * t + 3] += wj * v4.w;
            }
        }
        // prefold halves, then 16-value reduce-scatter over 16 lanes
#pragma unroll
        for (int j = 0; j < 16; j++) v[j] += __shfl_xor_sync(0xffffffffu, v[j], 16);
#pragma unroll
        for (int off = 8; off >= 1; off >>= 1) {
            const bool hi = (lane & off) != 0;
#pragma unroll
            for (int j = 0; j < 8; j++) {
                if (j < off) {
                    float send = hi ? v[j] : v[j + off];
                    float keep = hi ? v[j + off] : v[j];
                    v[j] = keep + __shfl_xor_sync(0xffffffffu, send, off);
                }
            }
        }
        if (lane < 16) sQf[p * LDSR + ho + (lane & 15)] = v[0];   // in-place over Q
    }

    // ---- mh = out_concat @ Wc; C -> sKf ----
    gemm128(smem8, sb, sQf, LDSR, Pn, nullptr, 3, nullptr, 0, sKf, Pn);
    // ---- score2 = (mh + bc) @ nodes^T; C -> sQf ----
    gemm128(smem8, sb, sKf, LDSR, Pn, sBc, -1, gN, Nn, sQf, Pn);

    // ---- final: clip*tanh(score2/sqrt(128)) + mask; softmax; store (1 row/warp) ----
    const float INV_SQRT_EMB = 0.08838834764831843f;
    float* gOut = out + (size_t)b * Pn * Nn;
    for (int p = wid; p < Pn; p += NWARP) {
        float s[4];
        int nn[4];
#pragma unroll
        for (int j = 0; j < 4; j++) {
            int n = lane + 32 * j;
            nn[j] = n;
            s[j] = (n < Nn)
                 ? tanh10(sQf[p * LDSR + n] * INV_SQRT_EMB) + gM[p * Nn + n]
                 : -INFINITY;
        }
        float mx = fmaxf(fmaxf(s[0], s[1]), fmaxf(s[2], s[3]));
#pragma unroll
        for (int off = 16; off; off >>= 1)
            mx = fmaxf(mx, __shfl_xor_sync(0xffffffffu, mx, off));
        float sum = 0.f;
#pragma unroll
        for (int j = 0; j < 4; j++) { s[j] = __expf(s[j] - mx); sum += s[j]; }
#pragma unroll
        for (int off = 16; off; off >>= 1)
            sum += __shfl_xor_sync(0xffffffffu, sum, off);
        const float inv = 1.f / sum;
#pragma unroll
        for (int j = 0; j < 4; j++)
            if (nn[j] < Nn) gOut[p * Nn + nn[j]] = s[j] * inv;
    }
}

extern "C" void kernel_launch(void* const* d_in, const int* in_sizes, int n_in,
                              void* d_out, int out_size) {
    const float* eln   = (const float*)d_in[0];
    const float* load_ = (const float*)d_in[1];
    const float* time_ = (const float*)d_in[2];
    const float* len_  = (const float*)d_in[3];
    const float* ropen = (const float*)d_in[4];
    const float* mask  = (const float*)d_in[5];
    const float* nodes = (const float*)d_in[6];
    const float* Wq    = (const float*)d_in[7];
    const float* Wk    = (const float*)d_in[8];
    const float* Wv    = (const float*)d_in[9];
    const float* Wc    = (const float*)d_in[10];
    const float* bc    = (const float*)d_in[11];
    float* out = (float*)d_out;

    prep_weights<<<4, 256>>>(Wq, Wk, Wv, Wc);
    cudaFuncSetAttribute(vrp_decoder_kernel,
                         cudaFuncAttributeMaxDynamicSharedMemorySize, SMEM_TOTAL);
    vrp_decoder_kernel<<<Bn, TPB, SMEM_TOTAL>>>(
        eln, load_, time_, len_, ropen, mask, nodes, bc, out);
}

// round 8
// speedup vs baseline: 1.6061x; 1.6061x over previous
#include <cuda_runtime.h>
#include <cuda_bf16.h>
#include <cstdint>

#define TPB 512
static constexpr int Bn = 1024, Pn = 100, Nn = 101, EMBn = 128;
static constexpr int Hn = 8, DKn = 16;

static constexpr int STB = 40;       // bf16 row stride inside chunk tiles
static constexpr int CHB = 10240;    // byte offset of lo half inside a chunk buffer
// ---- smem byte map ----
// QB/KB/VB: swizzled bf16 tiles, 112 rows x 128 cols, hi at +0, lo at +28672 (57344B each)
static constexpr int QB = 0;
static constexpr int KB = 57344;          // after attention: mh f32 output [100][132]
static constexpr int VB = 114688;         // after attention: score2 f32 output [100][132]
static constexpr int HILO = 28672;        // lo offset within QB/KB/VB
static constexpr int SA_H = 172032;       // A chunk buffer (20480B)
static constexpr int SB_H = 192512;       // B chunk buffer (20480B)
static constexpr int OFF_EX  = 212992;    // extras [100][4] f32
static constexpr int OFF_WQ4 = 214592;    // Wq rows 128..131 [4][128] f32
static constexpr int OFF_BC  = 216640;    // bc [128] f32
static constexpr int SMEM_TOTAL = 217152;
static constexpr int LDSR = 132;          // f32 row stride for mh/scores buffers

// ---------------- prep: weights -> chunk-blocked bf16 hi/lo, B^T layout ----
__device__ __nv_bfloat16 g_wt[4][40960];
__device__ float g_wq4[512];

__global__ void prep_weights(const float* __restrict__ Wq, const float* __restrict__ Wk,
                             const float* __restrict__ Wv, const float* __restrict__ Wc)
{
    const int w = blockIdx.x;
    const float* W = (w == 0) ? Wq : (w == 1) ? Wk : (w == 2) ? Wv : Wc;
    for (int idx = threadIdx.x; idx < 128 * 128; idx += blockDim.x) {
        int n = idx >> 7, k = idx & 127;
        float x = W[k * 128 + n];
        __nv_bfloat16 h = __float2bfloat16(x);
        __nv_bfloat16 l = __float2bfloat16(x - __bfloat162float(h));
        int o = (k >> 5) * 10240 + n * STB + (k & 31);
        g_wt[w][o] = h;
        g_wt[w][o + 5120] = l;
    }
    if (w == 0) {
        for (int i = threadIdx.x; i < 512; i += blockDim.x)
            g_wq4[i] = Wq[128 * 128 + i];
    }
}

// ---------------- device helpers ----------------
__device__ __forceinline__ uint32_t smem_u32(const void* p) {
    uint32_t a;
    asm("{ .reg .u64 t; cvta.to.shared.u64 t, %1; cvt.u32.u64 %0, t; }" : "=r"(a) : "l"(p));
    return a;
}
__device__ __forceinline__ float tanh10(float x) {
    x = fminf(fmaxf(x, -20.f), 20.f);
    float t = __expf(2.f * x);
    return 10.f * (t - 1.f) / (t + 1.f);
}
// swizzled byte offset within a QB/KB/VB half: row r (0..111), byte col cb (0..255)
__device__ __forceinline__ uint32_t swz(int r, int cb) {
    return (uint32_t)(r * 256 + ((((cb >> 4) ^ (r & 7)) << 4) | (cb & 15)));
}

#define LDSM4(R0, R1, R2, R3, ADDR) \
    asm volatile("ldmatrix.sync.aligned.m8n8.x4.shared.b16 {%0,%1,%2,%3}, [%4];" \
        : "=r"(R0), "=r"(R1), "=r"(R2), "=r"(R3) : "r"(ADDR))
#define LDSM2(R0, R1, ADDR) \
    asm volatile("ldmatrix.sync.aligned.m8n8.x2.shared.b16 {%0,%1}, [%2];" \
        : "=r"(R0), "=r"(R1) : "r"(ADDR))
#define LDSM2T(R0, R1, ADDR) \
    asm volatile("ldmatrix.sync.aligned.m8n8.x2.trans.shared.b16 {%0,%1}, [%2];" \
        : "=r"(R0), "=r"(R1) : "r"(ADDR))
#define MMA16816(C, A, B0, B1) \
    asm volatile("mma.sync.aligned.m16n8k16.row.col.f32.bf16.bf16.f32 " \
        "{%0,%1,%2,%3}, {%4,%5,%6,%7}, {%8,%9}, {%0,%1,%2,%3};" \
        : "+f"((C)[0]), "+f"((C)[1]), "+f"((C)[2]), "+f"((C)[3]) \
        : "r"((A)[0]), "r"((A)[1]), "r"((A)[2]), "r"((A)[3]), "r"(B0), "r"(B1))

// write (v0,v1) as bf16 hi/lo pair into a swizzled tile at (row r, bf16 col c)
__device__ __forceinline__ void st_hilo(unsigned char* base, int r, int c, float v0, float v1) {
    __nv_bfloat162 h = __floats2bfloat162_rn(v0, v1);
    __nv_bfloat162 l = __floats2bfloat162_rn(v0 - __bfloat162float(h.x),
                                             v1 - __bfloat162float(h.y));
    uint32_t off = swz(r, c * 2);
    *(__nv_bfloat162*)(base + off) = h;
    *(__nv_bfloat162*)(base + HILO + off) = l;
}

// build one 128x32 hi/lo bf16 chunk from f32 row-major source
__device__ __forceinline__ void build_half(
    __nv_bfloat16* __restrict__ dst, const float* __restrict__ src,
    int ld, int nrows, int k0, const float* __restrict__ biasK)
{
    for (int i = threadIdx.x; i < 1024; i += TPB) {
        int r = i >> 3, q = (i & 7) << 2;
        float4 v = make_float4(0.f, 0.f, 0.f, 0.f);
        if (r < nrows) v = *(const float4*)&src[(size_t)r * ld + k0 + q];
        if (biasK) {
            v.x += biasK[k0 + q];     v.y += biasK[k0 + q + 1];
            v.z += biasK[k0 + q + 2]; v.w += biasK[k0 + q + 3];
        }
        __nv_bfloat162 h01 = __floats2bfloat162_rn(v.x, v.y);
        __nv_bfloat162 h23 = __floats2bfloat162_rn(v.z, v.w);
        __nv_bfloat162 l01 = __floats2bfloat162_rn(v.x - __bfloat162float(h01.x),
                                                   v.y - __bfloat162float(h01.y));
        __nv_bfloat162 l23 = __floats2bfloat162_rn(v.z - __bfloat162float(h23.x),
                                                   v.w - __bfloat162float(h23.y));
        int o = r * STB + q;
        *(__nv_bfloat162*)(dst + o)            = h01;
        *(__nv_bfloat162*)(dst + o + 2)        = h23;
        *(__nv_bfloat162*)(dst + 5120 + o)     = l01;
        *(__nv_bfloat162*)(dst + 5120 + o + 2) = l23;
    }
}

// shared GEMM mainloop core: fills acc[2][4][4] for warp (wm = w&3 rows 32, wn = w>>2 cols 32)
// A from f32 src (chunk-staged), B from g_wt[wsel] or f32 (chunk-staged).
__device__ __forceinline__ void gemm_core(
    unsigned char* smem8, uint32_t sb,
    const float* Asrc, int Ald, int Anrows, const float* biasK,
    int wsel, const float* Bf32, int Bnrows,
    float acc[2][4][4])
{
    const int tid = threadIdx.x, w = tid >> 5, lane = tid & 31;
    const int wm = w & 3, wn = w >> 2;
#pragma unroll
    for (int m = 0; m < 2; m++)
#pragma unroll
        for (int n = 0; n < 4; n++)
#pragma unroll
            for (int j = 0; j < 4; j++) acc[m][n][j] = 0.f;

    for (int c = 0; c < 4; c++) {
        __syncthreads();
        const int k0 = c * 32;
        build_half((__nv_bfloat16*)(smem8 + SA_H), Asrc, Ald, Anrows, k0, biasK);
        if (wsel >= 0) {
            const uint4* src = (const uint4*)&g_wt[wsel][c * 10240];
            uint4* dst = (uint4*)(smem8 + SB_H);
            for (int i = tid; i < 1280; i += TPB) dst[i] = src[i];
        } else {
            build_half((__nv_bfloat16*)(smem8 + SB_H), Bf32, 128, Bnrows, k0, nullptr);
        }
        __syncthreads();

#pragma unroll
        for (int ks = 0; ks < 2; ks++) {
            const int kb = ks * 16;
            uint32_t aH[2][4], aL[2][4];
#pragma unroll
            for (int m = 0; m < 2; m++) {
                uint32_t addr = sb + SA_H +
                    (uint32_t)(((wm * 32 + m * 16 + (lane & 15)) * STB
                                + kb + ((lane >> 4) << 3)) << 1);
                LDSM4(aH[m][0], aH[m][1], aH[m][2], aH[m][3], addr);
                LDSM4(aL[m][0], aL[m][1], aL[m][2], aL[m][3], addr + CHB);
            }
            uint32_t bH[4][2], bL[4][2];
#pragma unroll
            for (int t = 0; t < 2; t++) {
                const uint32_t ba = sb + SB_H +
                    (uint32_t)(((wn * 32 + t * 16 + ((lane & 16) ? 8 : 0) + (lane & 7)) * STB
                                + kb + ((lane & 8) ? 8 : 0)) << 1);
                uint32_t r0, r1, r2, r3;
                LDSM4(r0, r1, r2, r3, ba);
                bH[2 * t][0] = r0;     bH[2 * t][1] = r1;
                bH[2 * t + 1][0] = r2; bH[2 * t + 1][1] = r3;
                LDSM4(r0, r1, r2, r3, ba + CHB);
                bL[2 * t][0] = r0;     bL[2 * t][1] = r1;
                bL[2 * t + 1][0] = r2; bL[2 * t + 1][1] = r3;
            }
#pragma unroll
            for (int m = 0; m < 2; m++)
#pragma unroll
                for (int n = 0; n < 4; n++) {
                    MMA16816(acc[m][n], aH[m], bH[n][0], bH[n][1]);
                    MMA16816(acc[m][n], aH[m], bL[n][0], bL[n][1]);
                    MMA16816(acc[m][n], aL[m], bH[n][0], bH[n][1]);
                }
        }
    }
    __syncthreads();
}

extern __shared__ __align__(16) unsigned char smem8[];

__global__ __launch_bounds__(TPB, 1)
void vrp_decoder_kernel(
    const float* __restrict__ eln,   const float* __restrict__ load_,
    const float* __restrict__ time_, const float* __restrict__ len_,
    const float* __restrict__ ropen, const float* __restrict__ mask,
    const float* __restrict__ nodes, const float* __restrict__ bc,
    float* __restrict__ out)
{
    const int b = blockIdx.x;
    const int tid = threadIdx.x;
    const int wid = tid >> 5, lane = tid & 31;
    const int w_ = wid, wm = w_ & 3, wn = w_ >> 2;
    const uint32_t sb = smem_u32(smem8);

    float* sEx  = (float*)(smem8 + OFF_EX);
    float* sWq4 = (float*)(smem8 + OFF_WQ4);
    float* sBc  = (float*)(smem8 + OFF_BC);

    // ---- stage aux ----
    for (int i = tid; i < 512; i += TPB) sWq4[i] = g_wq4[i];
    for (int i = tid; i < 128; i += TPB) sBc[i] = bc[i];
    for (int r = tid; r < Pn; r += TPB) {
        sEx[r * 4 + 0] = load_[b * Pn + r];
        sEx[r * 4 + 1] = time_[b * Pn + r];
        sEx[r * 4 + 2] = len_[b * Pn + r];
        sEx[r * 4 + 3] = ropen[b * Pn + r];
    }

    const float* gE = eln + (size_t)b * Pn * EMBn;
    const float* gN = nodes + (size_t)b * Nn * EMBn;
    const float* gM = mask + (size_t)b * Pn * Nn;

    // ---- projections: Q/K/V -> swizzled bf16 hi/lo tiles ----
    {
        float acc[2][4][4];
        // Q = eln @ Wq[0:128] (+extras correction), -> QB
        gemm_core(smem8, sb, gE, EMBn, Pn, nullptr, 0, nullptr, 0, acc);
#pragma unroll
        for (int m = 0; m < 2; m++)
#pragma unroll
            for (int n = 0; n < 4; n++) {
                int row = wm * 32 + m * 16 + (lane >> 2);
                int col = wn * 32 + n * 8 + ((lane & 3) << 1);
#pragma unroll
                for (int hh = 0; hh < 2; hh++) {
                    int r = row + 8 * hh;
                    if (r >= 112) continue;
                    float v0 = acc[m][n][2 * hh], v1 = acc[m][n][2 * hh + 1];
                    if (r < Pn) {
                        float e0 = sEx[r * 4], e1 = sEx[r * 4 + 1], e2 = sEx[r * 4 + 2], e3 = sEx[r * 4 + 3];
                        v0 += e0 * sWq4[col] + e1 * sWq4[128 + col] + e2 * sWq4[256 + col] + e3 * sWq4[384 + col];
                        v1 += e0 * sWq4[col + 1] + e1 * sWq4[128 + col + 1] + e2 * sWq4[256 + col + 1] + e3 * sWq4[384 + col + 1];
                    }
                    st_hilo(smem8 + QB, r, col, v0, v1);
                }
            }
        __syncthreads();
        // K = nodes @ Wk -> KB   (pad rows are zero: build_half zero-pads A)
        gemm_core(smem8, sb, gN, EMBn, Nn, nullptr, 1, nullptr, 0, acc);
#pragma unroll
        for (int m = 0; m < 2; m++)
#pragma unroll
            for (int n = 0; n < 4; n++) {
                int row = wm * 32 + m * 16 + (lane >> 2);
                int col = wn * 32 + n * 8 + ((lane & 3) << 1);
#pragma unroll
                for (int hh = 0; hh < 2; hh++) {
                    int r = row + 8 * hh;
                    if (r < 112) st_hilo(smem8 + KB, r, col, acc[m][n][2 * hh], acc[m][n][2 * hh + 1]);
                }
            }
        __syncthreads();
        // V = nodes @ Wv -> VB
        gemm_core(smem8, sb, gN, EMBn, Nn, nullptr, 2, nullptr, 0, acc);
#pragma unroll
        for (int m = 0; m < 2; m++)
#pragma unroll
            for (int n = 0; n < 4; n++) {
                int row = wm * 32 + m * 16 + (lane >> 2);
                int col = wn * 32 + n * 8 + ((lane & 3) << 1);
#pragma unroll
                for (int hh = 0; hh < 2; hh++) {
                    int r = row + 8 * hh;
                    if (r < 112) st_hilo(smem8 + VB, r, col, acc[m][n][2 * hh], acc[m][n][2 * hh + 1]);
                }
            }
        __syncthreads();
    }

    // ---- attention via mma.sync: item = (m16-tile mi, head h), 56 items / 16 warps ----
    for (int it = wid; it < 56; it += 16) {
        const int mi = it % 7, h = it / 7;
        const int r0 = mi * 16;
        // Q A-frags (hi/lo)
        uint32_t qa = sb + QB + swz(r0 + (lane & 15), (2 * h + (lane >> 4)) << 4);
        uint32_t qh[4], ql[4];
        LDSM4(qh[0], qh[1], qh[2], qh[3], qa);
        LDSM4(ql[0], ql[1], ql[2], ql[3], qa + HILO);

        float sf[14][4];
#pragma unroll
        for (int nt = 0; nt < 14; nt++) {
            uint32_t ka = sb + KB + swz(nt * 8 + (lane & 7), (2 * h + ((lane >> 3) & 1)) << 4);
            uint32_t kh0, kh1, kl0, kl1;
            LDSM2(kh0, kh1, ka);
            LDSM2(kl0, kl1, ka + HILO);
            float c[4] = {0.f, 0.f, 0.f, 0.f};
            MMA16816(c, qh, kh0, kh1);
            MMA16816(c, qh, kl0, kl1);
            MMA16816(c, ql, kh0, kh1);
            sf[nt][0] = c[0]; sf[nt][1] = c[1]; sf[nt][2] = c[2]; sf[nt][3] = c[3];
        }
        const int rr0 = r0 + (lane >> 2), rr1 = rr0 + 8;
#pragma unroll
        for (int nt = 0; nt < 14; nt++) {
            int c0 = nt * 8 + ((lane & 3) << 1), c1 = c0 + 1;
            float m00 = (c0 < Nn) ? ((rr0 < Pn) ? gM[rr0 * Nn + c0] : 0.f) : -INFINITY;
            float m01 = (c1 < Nn) ? ((rr0 < Pn) ? gM[rr0 * Nn + c1] : 0.f) : -INFINITY;
            float m10 = (c0 < Nn) ? ((rr1 < Pn) ? gM[rr1 * Nn + c0] : 0.f) : -INFINITY;
            float m11 = (c1 < Nn) ? ((rr1 < Pn) ? gM[rr1 * Nn + c1] : 0.f) : -INFINITY;
            sf[nt][0] = sf[nt][0] * 0.25f + m00;
            sf[nt][1] = sf[nt][1] * 0.25f + m01;
            sf[nt][2] = sf[nt][2] * 0.25f + m10;
            sf[nt][3] = sf[nt][3] * 0.25f + m11;
        }
        // softmax (rows rr0 -> regs 0,1; rr1 -> regs 2,3); reduce over quad (xor 1,2)
        float mx0 = -INFINITY, mx1 = -INFINITY;
#pragma unroll
        for (int nt = 0; nt < 14; nt++) {
            mx0 = fmaxf(mx0, fmaxf(sf[nt][0], sf[nt][1]));
            mx1 = fmaxf(mx1, fmaxf(sf[nt][2], sf[nt][3]));
        }
        mx0 = fmaxf(mx0, __shfl_xor_sync(0xffffffffu, mx0, 1));
        mx0 = fmaxf(mx0, __shfl_xor_sync(0xffffffffu, mx0, 2));
        mx1 = fmaxf(mx1, __shfl_xor_sync(0xffffffffu, mx1, 1));
        mx1 = fmaxf(mx1, __shfl_xor_sync(0xffffffffu, mx1, 2));
        float sum0 = 0.f, sum1 = 0.f;
#pragma unroll
        for (int nt = 0; nt < 14; nt++) {
            sf[nt][0] = __expf(sf[nt][0] - mx0); sum0 += sf[nt][0];
            sf[nt][1] = __expf(sf[nt][1] - mx0); sum0 += sf[nt][1];
            sf[nt][2] = __expf(sf[nt][2] - mx1); sum1 += sf[nt][2];
            sf[nt][3] = __expf(sf[nt][3] - mx1); sum1 += sf[nt][3];
        }
        sum0 += __shfl_xor_sync(0xffffffffu, sum0, 1);
        sum0 += __shfl_xor_sync(0xffffffffu, sum0, 2);
        sum1 += __shfl_xor_sync(0xffffffffu, sum1, 1);
        sum1 += __shfl_xor_sync(0xffffffffu, sum1, 2);
        const float inv0 = 1.f / sum0, inv1 = 1.f / sum1;

        // PV
        float oa[2][4];
#pragma unroll
        for (int g2 = 0; g2 < 2; g2++)
#pragma unroll
            for (int j = 0; j < 4; j++) oa[g2][j] = 0.f;
#pragma unroll
        for (int kt = 0; kt < 7; kt++) {
            float p[8];
            p[0] = sf[2 * kt][0] * inv0;     p[1] = sf[2 * kt][1] * inv0;
            p[2] = sf[2 * kt][2] * inv1;     p[3] = sf[2 * kt][3] * inv1;
            p[4] = sf[2 * kt + 1][0] * inv0; p[5] = sf[2 * kt + 1][1] * inv0;
            p[6] = sf[2 * kt + 1][2] * inv1; p[7] = sf[2 * kt + 1][3] * inv1;
            uint32_t aH[4], aL[4];
#pragma unroll
            for (int q2 = 0; q2 < 4; q2++) {
                __nv_bfloat162 hh = __floats2bfloat162_rn(p[2 * q2], p[2 * q2 + 1]);
                __nv_bfloat162 ll = __floats2bfloat162_rn(p[2 * q2] - __bfloat162float(hh.x),
                                                          p[2 * q2 + 1] - __bfloat162float(hh.y));
                aH[q2] = *reinterpret_cast<uint32_t*>(&hh);
                aL[q2] = *reinterpret_cast<uint32_t*>(&ll);
            }
#pragma unroll
            for (int ng = 0; ng < 2; ng++) {
                uint32_t va = sb + VB + swz(kt * 16 + (lane & 15), (2 * h + ng) << 4);
                uint32_t vh0, vh1, vl0, vl1;
                LDSM2T(vh0, vh1, va);
                LDSM2T(vl0, vl1, va + HILO);
                MMA16816(oa[ng], aH, vh0, vh1);
                MMA16816(oa[ng], aH, vl0, vl1);
                MMA16816(oa[ng], aL, vh0, vh1);
            }
        }
        // write O in place over this item's Q slot
#pragma unroll
        for (int ng = 0; ng < 2; ng++) {
            int col = h * 16 + ng * 8 + ((lane & 3) << 1);
            st_hilo(smem8 + QB, rr0, col, oa[ng][0], oa[ng][1]);
            st_hilo(smem8 + QB, rr1, col, oa[ng][2], oa[ng][3]);
        }
    }
    __syncthreads();

    // ---- mh = O @ Wc : A direct from QB, B = Wc chunks; C(f32) -> OF (KB region) ----
    {
        float acc2[2][4][4];
#pragma unroll
        for (int t = 0; t < 2; t++)
#pragma unroll
            for (int n = 0; n < 4; n++)
#pragma unroll
                for (int j = 0; j < 4; j++) acc2[t][n][j] = 0.f;

        for (int c = 0; c < 4; c++) {
            __syncthreads();
            {
                const uint4* src = (const uint4*)&g_wt[3][c * 10240];
                uint4* dst = (uint4*)(smem8 + SB_H);
                for (int i = tid; i < 1280; i += TPB) dst[i] = src[i];
            }
            __syncthreads();
#pragma unroll
            for (int ks = 0; ks < 2; ks++) {
                const int kc = c * 2 + ks;
#pragma unroll
                for (int t = 0; t < 2; t++) {
                    const int it = wid + t * 16;
                    if (it >= 28) break;
                    const int mi = it % 7, ng = it / 7;
                    uint32_t aa = sb + QB + swz(mi * 16 + (lane & 15), (2 * kc + (lane >> 4)) << 4);
                    uint32_t ah[4], al[4];
                    LDSM4(ah[0], ah[1], ah[2], ah[3], aa);
                    LDSM4(al[0], al[1], al[2], al[3], aa + HILO);
                    uint32_t bH[4][2], bL[4][2];
#pragma unroll
                    for (int tt = 0; tt < 2; tt++) {
                        const uint32_t ba = sb + SB_H +
                            (uint32_t)(((ng * 32 + tt * 16 + ((lane & 16) ? 8 : 0) + (lane & 7)) * STB
                                        + ks * 16 + ((lane & 8) ? 8 : 0)) << 1);
                        uint32_t r0, r1, r2, r3;
                        LDSM4(r0, r1, r2, r3, ba);
                        bH[2 * tt][0] = r0;     bH[2 * tt][1] = r1;
                        bH[2 * tt + 1][0] = r2; bH[2 * tt + 1][1] = r3;
                        LDSM4(r0, r1, r2, r3, ba + CHB);
                        bL[2 * tt][0] = r0;     bL[2 * tt][1] = r1;
                        bL[2 * tt + 1][0] = r2; bL[2 * tt + 1][1] = r3;
                    }
#pragma unroll
                    for (int n = 0; n < 4; n++) {
                        MMA16816(acc2[t][n], ah, bH[n][0], bH[n][1]);
                        MMA16816(acc2[t][n], ah, bL[n][0], bL[n][1]);
                        MMA16816(acc2[t][n], al, bH[n][0], bH[n][1]);
                    }
                }
            }
        }
        __syncthreads();
        float* OF = (float*)(smem8 + KB);
#pragma unroll
        for (int t = 0; t < 2; t++) {
            const int it = wid + t * 16;
            if (it >= 28) break;
            const int mi = it % 7, ng = it / 7;
#pragma unroll
            for (int n = 0; n < 4; n++) {
                int row = mi * 16 + (lane >> 2);
                int col = ng * 32 + n * 8 + ((lane & 3) << 1);
                if (row < Pn)
                    *(float2*)&OF[row * LDSR + col] = make_float2(acc2[t][n][0], acc2[t][n][1]);
                if (row + 8 < Pn)
                    *(float2*)&OF[(row + 8) * LDSR + col] = make_float2(acc2[t][n][2], acc2[t][n][3]);
            }
        }
        __syncthreads();
    }

    // ---- score2 = (mh + bc) @ nodes^T ; C(f32) -> SC (VB region) ----
    {
        float acc[2][4][4];
        gemm_core(smem8, sb, (const float*)(smem8 + KB), LDSR, Pn, sBc, -1, gN, Nn, acc);
        float* SC = (float*)(smem8 + VB);
#pragma unroll
        for (int m = 0; m < 2; m++)
#pragma unroll
            for (int n = 0; n < 4; n++) {
                int row = wm * 32 + m * 16 + (lane >> 2);
                int col = wn * 32 + n * 8 + ((lane & 3) << 1);
                if (row < Pn)
                    *(float2*)&SC[row * LDSR + col] = make_float2(acc[m][n][0], acc[m][n][1]);
                if (row + 8 < Pn)
                    *(float2*)&SC[(row + 8) * LDSR + col] = make_float2(acc[m][n][2], acc[m][n][3]);
            }
        __syncthreads();
    }

    // ---- final: clip*tanh(score2/sqrt(128)) + mask; softmax; store ----
    const float INV_SQRT_EMB = 0.08838834764831843f;
    const float* SC = (const float*)(smem8 + VB);
    float* gOut = out + (size_t)b * Pn * Nn;
    for (int pi = wid; pi < Pn / 2; pi += 16) {
        const int p0 = 2 * pi, p1 = p0 + 1;
        float s0[4], s1[4];
        int nn[4];
#pragma unroll
        for (int j = 0; j < 4; j++) {
            int n = lane + 32 * j;
            nn[j] = n;
            if (n < Nn) {
                s0[j] = tanh10(SC[p0 * LDSR + n] * INV_SQRT_EMB) + gM[p0 * Nn + n];
                s1[j] = tanh10(SC[p1 * LDSR + n] * INV_SQRT_EMB) + gM[p1 * Nn + n];
            } else { s0[j] = -INFINITY; s1[j] = -INFINITY; }
        }
        float mx0 = fmaxf(fmaxf(s0[0], s0[1]), fmaxf(s0[2], s0[3]));
        float mx1 = fmaxf(fmaxf(s1[0], s1[1]), fmaxf(s1[2], s1[3]));
#pragma unroll
        for (int off = 16; off; off >>= 1) {
            mx0 = fmaxf(mx0, __shfl_xor_sync(0xffffffffu, mx0, off));
            mx1 = fmaxf(mx1, __shfl_xor_sync(0xffffffffu, mx1, off));
        }
        float w0[4], w1[4], sum0 = 0.f, sum1 = 0.f;
#pragma unroll
        for (int j = 0; j < 4; j++) {
            w0[j] = __expf(s0[j] - mx0); sum0 += w0[j];
            w1[j] = __expf(s1[j] - mx1); sum1 += w1[j];
        }
#pragma unroll
        for (int off = 16; off; off >>= 1) {
            sum0 += __shfl_xor_sync(0xffffffffu, sum0, off);
            sum1 += __shfl_xor_sync(0xffffffffu, sum1, off);
        }
        const float i0 = 1.f / sum0, i1 = 1.f / sum1;
#pragma unroll
        for (int j = 0; j < 4; j++) {
            if (nn[j] < Nn) {
                gOut[p0 * Nn + nn[j]] = w0[j] * i0;
                gOut[p1 * Nn + nn[j]] = w1[j] * i1;
            }
        }
    }
}

extern "C" void kernel_launch(void* const* d_in, const int* in_sizes, int n_in,
                              void* d_out, int out_size) {
    const float* eln   = (const float*)d_in[0];
    const float* load_ = (const float*)d_in[1];
    const float* time_ = (const float*)d_in[2];
    const float* len_  = (const float*)d_in[3];
    const float* ropen = (const float*)d_in[4];
    const float* mask  = (const float*)d_in[5];
    const float* nodes = (const float*)d_in[6];
    const float* Wq    = (const float*)d_in[7];
    const float* Wk    = (const float*)d_in[8];
    const float* Wv    = (const float*)d_in[9];
    const float* Wc    = (const float*)d_in[10];
    const float* bc    = (const float*)d_in[11];
    float* out = (float*)d_out;

    prep_weights<<<4, 256>>>(Wq, Wk, Wv, Wc);
    cudaFuncSetAttribute(vrp_decoder_kernel,
                         cudaFuncAttributeMaxDynamicSharedMemorySize, SMEM_TOTAL);
    vrp_decoder_kernel<<<Bn, TPB, SMEM_TOTAL>>>(
        eln, load_, time_, len_, ropen, mask, nodes, bc, out);
}

// round 9
// speedup vs baseline: 1.6355x; 1.0184x over previous
#include <cuda_runtime.h>
#include <cuda_bf16.h>
#include <cstdint>

#define TPB 512
static constexpr int Bn = 1024, Pn = 100, Nn = 101, EMBn = 128;
static constexpr int Hn = 8, DKn = 16;

static constexpr int STB = 40;       // bf16 row stride inside chunk tiles
static constexpr int CHB = 10240;    // byte offset of lo half inside a chunk buffer
// ---- smem byte map ----
// QB/KB/VB: swizzled bf16 tiles, 112 rows x 128 cols, hi at +0, lo at +28672 (57344B each)
static constexpr int QB = 0;
static constexpr int KB = 57344;          // K tiles -> mh tiles (hi/lo, +bc)
static constexpr int VB = 114688;         // V tiles -> score2 f32 output [100][132]
static constexpr int HILO = 28672;        // lo offset within QB/KB/VB
static constexpr int SA_H = 172032;       // A chunk buffer (20480B)
static constexpr int SB_H = 192512;       // B chunk buffer (20480B)
static constexpr int OFF_EX  = 212992;    // extras [100][4] f32
static constexpr int OFF_WQ4 = 214592;    // Wq rows 128..131 [4][128] f32
static constexpr int OFF_BC  = 216640;    // bc [128] f32
static constexpr int SMEM_TOTAL = 217152;
static constexpr int LDSR = 132;          // f32 row stride for scores buffer

// ---------------- prep: weights -> chunk-blocked bf16 hi/lo, B^T layout ----
__device__ __nv_bfloat16 g_wt[4][40960];
__device__ float g_wq4[512];

__global__ void prep_weights(const float* __restrict__ Wq, const float* __restrict__ Wk,
                             const float* __restrict__ Wv, const float* __restrict__ Wc)
{
    const int w = blockIdx.x;
    const float* W = (w == 0) ? Wq : (w == 1) ? Wk : (w == 2) ? Wv : Wc;
    for (int idx = threadIdx.x; idx < 128 * 128; idx += blockDim.x) {
        int n = idx >> 7, k = idx & 127;
        float x = W[k * 128 + n];
        __nv_bfloat16 h = __float2bfloat16(x);
        __nv_bfloat16 l = __float2bfloat16(x - __bfloat162float(h));
        int o = (k >> 5) * 10240 + n * STB + (k & 31);
        g_wt[w][o] = h;
        g_wt[w][o + 5120] = l;
    }
    if (w == 0) {
        for (int i = threadIdx.x; i < 512; i += blockDim.x)
            g_wq4[i] = Wq[128 * 128 + i];
    }
}

// ---------------- device helpers ----------------
__device__ __forceinline__ uint32_t smem_u32(const void* p) {
    uint32_t a;
    asm("{ .reg .u64 t; cvta.to.shared.u64 t, %1; cvt.u32.u64 %0, t; }" : "=r"(a) : "l"(p));
    return a;
}
__device__ __forceinline__ float tanh10(float x) {
    x = fminf(fmaxf(x, -20.f), 20.f);
    float t = __expf(2.f * x);
    return 10.f * (t - 1.f) / (t + 1.f);
}
// swizzled byte offset within a QB/KB/VB half: row r (0..111), byte col cb (0..255)
__device__ __forceinline__ uint32_t swz(int r, int cb) {
    return (uint32_t)(r * 256 + ((((cb >> 4) ^ (r & 7)) << 4) | (cb & 15)));
}

#define LDSM4(R0, R1, R2, R3, ADDR) \
    asm volatile("ldmatrix.sync.aligned.m8n8.x4.shared.b16 {%0,%1,%2,%3}, [%4];" \
        : "=r"(R0), "=r"(R1), "=r"(R2), "=r"(R3) : "r"(ADDR))
#define LDSM4T(R0, R1, R2, R3, ADDR) \
    asm volatile("ldmatrix.sync.aligned.m8n8.x4.trans.shared.b16 {%0,%1,%2,%3}, [%4];" \
        : "=r"(R0), "=r"(R1), "=r"(R2), "=r"(R3) : "r"(ADDR))
#define MMA16816(C, A, B0, B1) \
    asm volatile("mma.sync.aligned.m16n8k16.row.col.f32.bf16.bf16.f32 " \
        "{%0,%1,%2,%3}, {%4,%5,%6,%7}, {%8,%9}, {%0,%1,%2,%3};" \
        : "+f"((C)[0]), "+f"((C)[1]), "+f"((C)[2]), "+f"((C)[3]) \
        : "r"((A)[0]), "r"((A)[1]), "r"((A)[2]), "r"((A)[3]), "r"(B0), "r"(B1))

// write (v0,v1) as bf16 hi/lo pair into a swizzled tile at (row r, bf16 col c)
__device__ __forceinline__ void st_hilo(unsigned char* base, int r, int c, float v0, float v1) {
    __nv_bfloat162 h = __floats2bfloat162_rn(v0, v1);
    __nv_bfloat162 l = __floats2bfloat162_rn(v0 - __bfloat162float(h.x),
                                             v1 - __bfloat162float(h.y));
    uint32_t off = swz(r, c * 2);
    *(__nv_bfloat162*)(base + off) = h;
    *(__nv_bfloat162*)(base + HILO + off) = l;
}

// build one 128x32 hi/lo bf16 chunk from f32 row-major source
__device__ __forceinline__ void build_half(
    __nv_bfloat16* __restrict__ dst, const float* __restrict__ src,
    int ld, int nrows, int k0)
{
    for (int i = threadIdx.x; i < 1024; i += TPB) {
        int r = i >> 3, q = (i & 7) << 2;
        float4 v = make_float4(0.f, 0.f, 0.f, 0.f);
        if (r < nrows) v = *(const float4*)&src[(size_t)r * ld + k0 + q];
        __nv_bfloat162 h01 = __floats2bfloat162_rn(v.x, v.y);
        __nv_bfloat162 h23 = __floats2bfloat162_rn(v.z, v.w);
        __nv_bfloat162 l01 = __floats2bfloat162_rn(v.x - __bfloat162float(h01.x),
                                                   v.y - __bfloat162float(h01.y));
        __nv_bfloat162 l23 = __floats2bfloat162_rn(v.z - __bfloat162float(h23.x),
                                                   v.w - __bfloat162float(h23.y));
        int o = r * STB + q;
        *(__nv_bfloat162*)(dst + o)            = h01;
        *(__nv_bfloat162*)(dst + o + 2)        = h23;
        *(__nv_bfloat162*)(dst + 5120 + o)     = l01;
        *(__nv_bfloat162*)(dst + 5120 + o + 2) = l23;
    }
}

// GEMM mainloop: A from f32 src (chunk-staged), B = prepped weight wsel.
__device__ __forceinline__ void gemm_core(
    unsigned char* smem8, uint32_t sb,
    const float* Asrc, int Ald, int Anrows, int wsel,
    float acc[2][4][4])
{
    const int tid = threadIdx.x, w = tid >> 5, lane = tid & 31;
    const int wm = w & 3, wn = w >> 2;
#pragma unroll
    for (int m = 0; m < 2; m++)
#pragma unroll
        for (int n = 0; n < 4; n++)
#pragma unroll
            for (int j = 0; j < 4; j++) acc[m][n][j] = 0.f;

    for (int c = 0; c < 4; c++) {
        __syncthreads();
        build_half((__nv_bfloat16*)(smem8 + SA_H), Asrc, Ald, Anrows, c * 32);
        {
            const uint4* src = (const uint4*)&g_wt[wsel][c * 10240];
            uint4* dst = (uint4*)(smem8 + SB_H);
            for (int i = tid; i < 1280; i += TPB) dst[i] = src[i];
        }
        __syncthreads();

#pragma unroll
        for (int ks = 0; ks < 2; ks++) {
            const int kb = ks * 16;
            uint32_t aH[2][4], aL[2][4];
#pragma unroll
            for (int m = 0; m < 2; m++) {
                uint32_t addr = sb + SA_H +
                    (uint32_t)(((wm * 32 + m * 16 + (lane & 15)) * STB
                                + kb + ((lane >> 4) << 3)) << 1);
                LDSM4(aH[m][0], aH[m][1], aH[m][2], aH[m][3], addr);
                LDSM4(aL[m][0], aL[m][1], aL[m][2], aL[m][3], addr + CHB);
            }
            uint32_t bH[4][2], bL[4][2];
#pragma unroll
            for (int t = 0; t < 2; t++) {
                const uint32_t ba = sb + SB_H +
                    (uint32_t)(((wn * 32 + t * 16 + ((lane & 16) ? 8 : 0) + (lane & 7)) * STB
                                + kb + ((lane & 8) ? 8 : 0)) << 1);
                uint32_t r0, r1, r2, r3;
                LDSM4(r0, r1, r2, r3, ba);
                bH[2 * t][0] = r0;     bH[2 * t][1] = r1;
                bH[2 * t + 1][0] = r2; bH[2 * t + 1][1] = r3;
                LDSM4(r0, r1, r2, r3, ba + CHB);
                bL[2 * t][0] = r0;     bL[2 * t][1] = r1;
                bL[2 * t + 1][0] = r2; bL[2 * t + 1][1] = r3;
            }
#pragma unroll
            for (int m = 0; m < 2; m++)
#pragma unroll
                for (int n = 0; n < 4; n++) {
                    MMA16816(acc[m][n], aH[m], bH[n][0], bH[n][1]);
                    MMA16816(acc[m][n], aH[m], bL[n][0], bL[n][1]);
                    MMA16816(acc[m][n], aL[m], bH[n][0], bH[n][1]);
                }
        }
    }
    __syncthreads();
}

extern __shared__ __align__(16) unsigned char smem8[];

__global__ __launch_bounds__(TPB, 1)
void vrp_decoder_kernel(
    const float* __restrict__ eln,   const float* __restrict__ load_,
    const float* __restrict__ time_, const float* __restrict__ len_,
    const float* __restrict__ ropen, const float* __restrict__ mask,
    const float* __restrict__ nodes, const float* __restrict__ bc,
    float* __restrict__ out)
{
    const int b = blockIdx.x;
    const int tid = threadIdx.x;
    const int wid = tid >> 5, lane = tid & 31;
    const int wm = wid & 3, wn = wid >> 2;
    const uint32_t sb = smem_u32(smem8);

    float* sEx  = (float*)(smem8 + OFF_EX);
    float* sWq4 = (float*)(smem8 + OFF_WQ4);
    float* sBc  = (float*)(smem8 + OFF_BC);

    // ---- stage aux ----
    for (int i = tid; i < 512; i += TPB) sWq4[i] = g_wq4[i];
    for (int i = tid; i < 128; i += TPB) sBc[i] = bc[i];
    for (int r = tid; r < Pn; r += TPB) {
        sEx[r * 4 + 0] = load_[b * Pn + r];
        sEx[r * 4 + 1] = time_[b * Pn + r];
        sEx[r * 4 + 2] = len_[b * Pn + r];
        sEx[r * 4 + 3] = ropen[b * Pn + r];
    }

    const float* gE = eln + (size_t)b * Pn * EMBn;
    const float* gN = nodes + (size_t)b * Nn * EMBn;
    const float* gM = mask + (size_t)b * Pn * Nn;

    // ---- projections: Q/K/V -> swizzled bf16 hi/lo tiles ----
    {
        float acc[2][4][4];
        // Q = eln @ Wq[0:128] (+extras correction) -> QB
        gemm_core(smem8, sb, gE, EMBn, Pn, 0, acc);
#pragma unroll
        for (int m = 0; m < 2; m++)
#pragma unroll
            for (int n = 0; n < 4; n++) {
                int row = wm * 32 + m * 16 + (lane >> 2);
                int col = wn * 32 + n * 8 + ((lane & 3) << 1);
#pragma unroll
                for (int hh = 0; hh < 2; hh++) {
                    int r = row + 8 * hh;
                    if (r >= 112) continue;
                    float v0 = acc[m][n][2 * hh], v1 = acc[m][n][2 * hh + 1];
                    if (r < Pn) {
                        float e0 = sEx[r * 4], e1 = sEx[r * 4 + 1], e2 = sEx[r * 4 + 2], e3 = sEx[r * 4 + 3];
                        v0 += e0 * sWq4[col] + e1 * sWq4[128 + col] + e2 * sWq4[256 + col] + e3 * sWq4[384 + col];
                        v1 += e0 * sWq4[col + 1] + e1 * sWq4[128 + col + 1] + e2 * sWq4[256 + col + 1] + e3 * sWq4[384 + col + 1];
                    }
                    st_hilo(smem8 + QB, r, col, v0, v1);
                }
            }
        __syncthreads();
        // K = nodes @ Wk -> KB
        gemm_core(smem8, sb, gN, EMBn, Nn, 1, acc);
#pragma unroll
        for (int m = 0; m < 2; m++)
#pragma unroll
            for (int n = 0; n < 4; n++) {
                int row = wm * 32 + m * 16 + (lane >> 2);
                int col = wn * 32 + n * 8 + ((lane & 3) << 1);
#pragma unroll
                for (int hh = 0; hh < 2; hh++) {
                    int r = row + 8 * hh;
                    if (r < 112) st_hilo(smem8 + KB, r, col, acc[m][n][2 * hh], acc[m][n][2 * hh + 1]);
                }
            }
        __syncthreads();
        // V = nodes @ Wv -> VB
        gemm_core(smem8, sb, gN, EMBn, Nn, 2, acc);
#pragma unroll
        for (int m = 0; m < 2; m++)
#pragma unroll
            for (int n = 0; n < 4; n++) {
                int row = wm * 32 + m * 16 + (lane >> 2);
                int col = wn * 32 + n * 8 + ((lane & 3) << 1);
#pragma unroll
                for (int hh = 0; hh < 2; hh++) {
                    int r = row + 8 * hh;
                    if (r < 112) st_hilo(smem8 + VB, r, col, acc[m][n][2 * hh], acc[m][n][2 * hh + 1]);
                }
            }
        __syncthreads();
    }

    // ---- attention via mma.sync: item = (m16-tile mi, head h), 56 items / 16 warps ----
    for (int it = wid; it < 56; it += 16) {
        const int mi = it % 7, h = it / 7;
        const int r0 = mi * 16;
        uint32_t qa = sb + QB + swz(r0 + (lane & 15), (2 * h + (lane >> 4)) << 4);
        uint32_t qh[4], ql[4];
        LDSM4(qh[0], qh[1], qh[2], qh[3], qa);
        LDSM4(ql[0], ql[1], ql[2], ql[3], qa + HILO);

        float sf[14][4];
#pragma unroll
        for (int nt2 = 0; nt2 < 7; nt2++) {
            // pair of K n-tiles via one LDSM4 (hi) + one (lo)
            uint32_t ka = sb + KB + swz((2 * nt2 + ((lane >> 4) & 1)) * 8 + (lane & 7),
                                        (2 * h + ((lane >> 3) & 1)) << 4);
            uint32_t kh[4], kl[4];
            LDSM4(kh[0], kh[1], kh[2], kh[3], ka);
            LDSM4(kl[0], kl[1], kl[2], kl[3], ka + HILO);
            float c0[4] = {0.f, 0.f, 0.f, 0.f}, c1[4] = {0.f, 0.f, 0.f, 0.f};
            MMA16816(c0, qh, kh[0], kh[1]);
            MMA16816(c1, qh, kh[2], kh[3]);
            MMA16816(c0, qh, kl[0], kl[1]);
            MMA16816(c1, qh, kl[2], kl[3]);
            MMA16816(c0, ql, kh[0], kh[1]);
            MMA16816(c1, ql, kh[2], kh[3]);
#pragma unroll
            for (int j = 0; j < 4; j++) { sf[2 * nt2][j] = c0[j]; sf[2 * nt2 + 1][j] = c1[j]; }
        }
        const int rr0 = r0 + (lane >> 2), rr1 = rr0 + 8;
#pragma unroll
        for (int nt = 0; nt < 14; nt++) {
            int c0 = nt * 8 + ((lane & 3) << 1), c1 = c0 + 1;
            float m00 = (c0 < Nn) ? ((rr0 < Pn) ? gM[rr0 * Nn + c0] : 0.f) : -INFINITY;
            float m01 = (c1 < Nn) ? ((rr0 < Pn) ? gM[rr0 * Nn + c1] : 0.f) : -INFINITY;
            float m10 = (c0 < Nn) ? ((rr1 < Pn) ? gM[rr1 * Nn + c0] : 0.f) : -INFINITY;
            float m11 = (c1 < Nn) ? ((rr1 < Pn) ? gM[rr1 * Nn + c1] : 0.f) : -INFINITY;
            sf[nt][0] = sf[nt][0] * 0.25f + m00;
            sf[nt][1] = sf[nt][1] * 0.25f + m01;
            sf[nt][2] = sf[nt][2] * 0.25f + m10;
            sf[nt][3] = sf[nt][3] * 0.25f + m11;
        }
        float mx0 = -INFINITY, mx1 = -INFINITY;
#pragma unroll
        for (int nt = 0; nt < 14; nt++) {
            mx0 = fmaxf(mx0, fmaxf(sf[nt][0], sf[nt][1]));
            mx1 = fmaxf(mx1, fmaxf(sf[nt][2], sf[nt][3]));
        }
        mx0 = fmaxf(mx0, __shfl_xor_sync(0xffffffffu, mx0, 1));
        mx0 = fmaxf(mx0, __shfl_xor_sync(0xffffffffu, mx0, 2));
        mx1 = fmaxf(mx1, __shfl_xor_sync(0xffffffffu, mx1, 1));
        mx1 = fmaxf(mx1, __shfl_xor_sync(0xffffffffu, mx1, 2));
        float sum0 = 0.f, sum1 = 0.f;
#pragma unroll
        for (int nt = 0; nt < 14; nt++) {
            sf[nt][0] = __expf(sf[nt][0] - mx0); sum0 += sf[nt][0];
            sf[nt][1] = __expf(sf[nt][1] - mx0); sum0 += sf[nt][1];
            sf[nt][2] = __expf(sf[nt][2] - mx1); sum1 += sf[nt][2];
            sf[nt][3] = __expf(sf[nt][3] - mx1); sum1 += sf[nt][3];
        }
        sum0 += __shfl_xor_sync(0xffffffffu, sum0, 1);
        sum0 += __shfl_xor_sync(0xffffffffu, sum0, 2);
        sum1 += __shfl_xor_sync(0xffffffffu, sum1, 1);
        sum1 += __shfl_xor_sync(0xffffffffu, sum1, 2);
        const float inv0 = 1.f / sum0, inv1 = 1.f / sum1;

        // PV: 4 accumulator chains ([ng][kt-parity])
        float accP[2][2][4];
#pragma unroll
        for (int g2 = 0; g2 < 2; g2++)
#pragma unroll
            for (int pr = 0; pr < 2; pr++)
#pragma unroll
                for (int j = 0; j < 4; j++) accP[g2][pr][j] = 0.f;
#pragma unroll
        for (int kt = 0; kt < 7; kt++) {
            const int pr = kt & 1;
            float p[8];
            p[0] = sf[2 * kt][0] * inv0;     p[1] = sf[2 * kt][1] * inv0;
            p[2] = sf[2 * kt][2] * inv1;     p[3] = sf[2 * kt][3] * inv1;
            p[4] = sf[2 * kt + 1][0] * inv0; p[5] = sf[2 * kt + 1][1] * inv0;
            p[6] = sf[2 * kt + 1][2] * inv1; p[7] = sf[2 * kt + 1][3] * inv1;
            uint32_t aH[4], aL[4];
#pragma unroll
            for (int q2 = 0; q2 < 4; q2++) {
                __nv_bfloat162 hh = __floats2bfloat162_rn(p[2 * q2], p[2 * q2 + 1]);
                __nv_bfloat162 ll = __floats2bfloat162_rn(p[2 * q2] - __bfloat162float(hh.x),
                                                          p[2 * q2 + 1] - __bfloat162float(hh.y));
                aH[q2] = *reinterpret_cast<uint32_t*>(&hh);
                aL[q2] = *reinterpret_cast<uint32_t*>(&ll);
            }
            // both ng V-frags via one LDSM4T (hi) + one (lo)
            uint32_t va = sb + VB + swz(kt * 16 + (lane & 15), (2 * h + (lane >> 4)) << 4);
            uint32_t vh[4], vl[4];
            LDSM4T(vh[0], vh[1], vh[2], vh[3], va);
            LDSM4T(vl[0], vl[1], vl[2], vl[3], va + HILO);
            MMA16816(accP[0][pr], aH, vh[0], vh[1]);
            MMA16816(accP[1][pr], aH, vh[2], vh[3]);
            MMA16816(accP[0][pr], aH, vl[0], vl[1]);
            MMA16816(accP[1][pr], aH, vl[2], vl[3]);
            MMA16816(accP[0][pr], aL, vh[0], vh[1]);
            MMA16816(accP[1][pr], aL, vh[2], vh[3]);
        }
        // write O in place over this item's Q slot
#pragma unroll
        for (int ng = 0; ng < 2; ng++) {
            int col = h * 16 + ng * 8 + ((lane & 3) << 1);
            st_hilo(smem8 + QB, rr0, col, accP[ng][0][0] + accP[ng][1][0],
                                          accP[ng][0][1] + accP[ng][1][1]);
            st_hilo(smem8 + QB, rr1, col, accP[ng][0][2] + accP[ng][1][2],
                                          accP[ng][0][3] + accP[ng][1][3]);
        }
    }
    __syncthreads();

    // ---- mh = O @ Wc + bc : A from QB tiles; OUTPUT as hi/lo tiles -> KB ----
    {
        float acc2[2][4][4];
#pragma unroll
        for (int t = 0; t < 2; t++)
#pragma unroll
            for (int n = 0; n < 4; n++)
#pragma unroll
                for (int j = 0; j < 4; j++) acc2[t][n][j] = 0.f;

        for (int c = 0; c < 4; c++) {
            __syncthreads();
            {
                const uint4* src = (const uint4*)&g_wt[3][c * 10240];
                uint4* dst = (uint4*)(smem8 + SB_H);
                for (int i = tid; i < 1280; i += TPB) dst[i] = src[i];
            }
            __syncthreads();
#pragma unroll
            for (int ks = 0; ks < 2; ks++) {
                const int kc = c * 2 + ks;
#pragma unroll
                for (int t = 0; t < 2; t++) {
                    const int it = wid + t * 16;
                    if (it >= 28) break;
                    const int mi = it % 7, ng = it / 7;
                    uint32_t aa = sb + QB + swz(mi * 16 + (lane & 15), (2 * kc + (lane >> 4)) << 4);
                    uint32_t ah[4], al[4];
                    LDSM4(ah[0], ah[1], ah[2], ah[3], aa);
                    LDSM4(al[0], al[1], al[2], al[3], aa + HILO);
                    uint32_t bH[4][2], bL[4][2];
#pragma unroll
                    for (int tt = 0; tt < 2; tt++) {
                        const uint32_t ba = sb + SB_H +
                            (uint32_t)(((ng * 32 + tt * 16 + ((lane & 16) ? 8 : 0) + (lane & 7)) * STB
                                        + ks * 16 + ((lane & 8) ? 8 : 0)) << 1);
                        uint32_t r0, r1, r2, r3;
                        LDSM4(r0, r1, r2, r3, ba);
                        bH[2 * tt][0] = r0;     bH[2 * tt][1] = r1;
                        bH[2 * tt + 1][0] = r2; bH[2 * tt + 1][1] = r3;
                        LDSM4(r0, r1, r2, r3, ba + CHB);
                        bL[2 * tt][0] = r0;     bL[2 * tt][1] = r1;
                        bL[2 * tt + 1][0] = r2; bL[2 * tt + 1][1] = r3;
                    }
#pragma unroll
                    for (int n = 0; n < 4; n++) {
                        MMA16816(acc2[t][n], ah, bH[n][0], bH[n][1]);
                        MMA16816(acc2[t][n], ah, bL[n][0], bL[n][1]);
                        MMA16816(acc2[t][n], al, bH[n][0], bH[n][1]);
                    }
                }
            }
        }
        __syncthreads();
        // epilogue: mh (+bc) -> hi/lo tiles in KB (K tiles are dead)
#pragma unroll
        for (int t = 0; t < 2; t++) {
            const int it = wid + t * 16;
            if (it >= 28) break;
            const int mi = it % 7, ng = it / 7;
#pragma unroll
            for (int n = 0; n < 4; n++) {
                int row = mi * 16 + (lane >> 2);
                int col = ng * 32 + n * 8 + ((lane & 3) << 1);
                float b0 = sBc[col], b1 = sBc[col + 1];
                st_hilo(smem8 + KB, row, col, acc2[t][n][0] + b0, acc2[t][n][1] + b1);
                st_hilo(smem8 + KB, row + 8, col, acc2[t][n][2] + b0, acc2[t][n][3] + b1);
            }
        }
        __syncthreads();
    }

    // ---- score2 = mh @ nodes^T : A direct from KB tiles, B = nodes chunks; f32 -> VB ----
    {
        float acc[2][4][4];
#pragma unroll
        for (int m = 0; m < 2; m++)
#pragma unroll
            for (int n = 0; n < 4; n++)
#pragma unroll
                for (int j = 0; j < 4; j++) acc[m][n][j] = 0.f;

        for (int c = 0; c < 4; c++) {
            __syncthreads();
            build_half((__nv_bfloat16*)(smem8 + SB_H), gN, EMBn, Nn, c * 32);
            __syncthreads();
#pragma unroll
            for (int ks = 0; ks < 2; ks++) {
                const int kc = c * 2 + ks;
                uint32_t aH[2][4], aL[2][4];
#pragma unroll
                for (int m = 0; m < 2; m++) {
                    // rows 112..127 read stale smem (finite or NaN) -> those output rows are discarded
                    uint32_t aa = sb + QB + KB - QB +  // = KB
                        swz(0, 0);  // placeholder (overwritten below)
                    aa = sb + KB + swz(wm * 32 + m * 16 + (lane & 15), (2 * kc + (lane >> 4)) << 4);
                    LDSM4(aH[m][0], aH[m][1], aH[m][2], aH[m][3], aa);
                    LDSM4(aL[m][0], aL[m][1], aL[m][2], aL[m][3], aa + HILO);
                }
                uint32_t bH[4][2], bL[4][2];
#pragma unroll
                for (int t = 0; t < 2; t++) {
                    const uint32_t ba = sb + SB_H +
                        (uint32_t)(((wn * 32 + t * 16 + ((lane & 16) ? 8 : 0) + (lane & 7)) * STB
                                    + ks * 16 + ((lane & 8) ? 8 : 0)) << 1);
                    uint32_t r0, r1, r2, r3;
                    LDSM4(r0, r1, r2, r3, ba);
                    bH[2 * t][0] = r0;     bH[2 * t][1] = r1;
                    bH[2 * t + 1][0] = r2; bH[2 * t + 1][1] = r3;
                    LDSM4(r0, r1, r2, r3, ba + CHB);
                    bL[2 * t][0] = r0;     bL[2 * t][1] = r1;
                    bL[2 * t + 1][0] = r2; bL[2 * t + 1][1] = r3;
                }
#pragma unroll
                for (int m = 0; m < 2; m++)
#pragma unroll
                    for (int n = 0; n < 4; n++) {
                        MMA16816(acc[m][n], aH[m], bH[n][0], bH[n][1]);
                        MMA16816(acc[m][n], aH[m], bL[n][0], bL[n][1]);
                        MMA16816(acc[m][n], aL[m], bH[n][0], bH[n][1]);
                    }
            }
        }
        __syncthreads();
        float* SC = (float*)(smem8 + VB);
#pragma unroll
        for (int m = 0; m < 2; m++)
#pragma unroll
            for (int n = 0; n < 4; n++) {
                int row = wm * 32 + m * 16 + (lane >> 2);
                int col = wn * 32 + n * 8 + ((lane & 3) << 1);
                if (row < Pn)
                    *(float2*)&SC[row * LDSR + col] = make_float2(acc[m][n][0], acc[m][n][1]);
                if (row + 8 < Pn)
                    *(float2*)&SC[(row + 8) * LDSR + col] = make_float2(acc[m][n][2], acc[m][n][3]);
            }
        __syncthreads();
    }

    // ---- final: clip*tanh(score2/sqrt(128)) + mask; softmax; store ----
    const float INV_SQRT_EMB = 0.08838834764831843f;
    const float* SC = (const float*)(smem8 + VB);
    float* gOut = out + (size_t)b * Pn * Nn;
    for (int pi = wid; pi < Pn / 2; pi += 16) {
        const int p0 = 2 * pi, p1 = p0 + 1;
        float s0[4], s1[4];
        int nn[4];
#pragma unroll
        for (int j = 0; j < 4; j++) {
            int n = lane + 32 * j;
            nn[j] = n;
            if (n < Nn) {
                s0[j] = tanh10(SC[p0 * LDSR + n] * INV_SQRT_EMB) + gM[p0 * Nn + n];
                s1[j] = tanh10(SC[p1 * LDSR + n] * INV_SQRT_EMB) + gM[p1 * Nn + n];
            } else { s0[j] = -INFINITY; s1[j] = -INFINITY; }
        }
        float mx0 = fmaxf(fmaxf(s0[0], s0[1]), fmaxf(s0[2], s0[3]));
        float mx1 = fmaxf(fmaxf(s1[0], s1[1]), fmaxf(s1[2], s1[3]));
#pragma unroll
        for (int off = 16; off; off >>= 1) {
            mx0 = fmaxf(mx0, __shfl_xor_sync(0xffffffffu, mx0, off));
            mx1 = fmaxf(mx1, __shfl_xor_sync(0xffffffffu, mx1, off));
        }
        float w0[4], w1[4], sum0 = 0.f, sum1 = 0.f;
#pragma unroll
        for (int j = 0; j < 4; j++) {
            w0[j] = __expf(s0[j] - mx0); sum0 += w0[j];
            w1[j] = __expf(s1[j] - mx1); sum1 += w1[j];
        }
#pragma unroll
        for (int off = 16; off; off >>= 1) {
            sum0 += __shfl_xor_sync(0xffffffffu, sum0, off);
            sum1 += __shfl_xor_sync(0xffffffffu, sum1, off);
        }
        const float i0 = 1.f / sum0, i1 = 1.f / sum1;
#pragma unroll
        for (int j = 0; j < 4; j++) {
            if (nn[j] < Nn) {
                gOut[p0 * Nn + nn[j]] = w0[j] * i0;
                gOut[p1 * Nn + nn[j]] = w1[j] * i1;
            }
        }
    }
}

extern "C" void kernel_launch(void* const* d_in, const int* in_sizes, int n_in,
                              void* d_out, int out_size) {
    const float* eln   = (const float*)d_in[0];
    const float* load_ = (const float*)d_in[1];
    const float* time_ = (const float*)d_in[2];
    const float* len_  = (const float*)d_in[3];
    const float* ropen = (const float*)d_in[4];
    const float* mask  = (const float*)d_in[5];
    const float* nodes = (const float*)d_in[6];
    const float* Wq    = (const float*)d_in[7];
    const float* Wk    = (const float*)d_in[8];
    const float* Wv    = (const float*)d_in[9];
    const float* Wc    = (const float*)d_in[10];
    const float* bc    = (const float*)d_in[11];
    float* out = (float*)d_out;

    prep_weights<<<4, 256>>>(Wq, Wk, Wv, Wc);
    cudaFuncSetAttribute(vrp_decoder_kernel,
                         cudaFuncAttributeMaxDynamicSharedMemorySize, SMEM_TOTAL);
    vrp_decoder_kernel<<<Bn, TPB, SMEM_TOTAL>>>(
        eln, load_, time_, len_, ropen, mask, nodes, bc, out);
}

// round 10
// speedup vs baseline: 2.0715x; 1.2666x over previous
#include <cuda_runtime.h>
#include <cuda_fp16.h>
#include <cstdint>

#define TPB 512
static constexpr int Bn = 1024, Pn = 100, Nn = 101, EMBn = 128;
static constexpr int Hn = 8, DKn = 16;

static constexpr int STB = 40;       // fp16 row stride inside chunk tiles
static constexpr int CHB = 10240;    // byte offset of lo half inside the A chunk buffer
// ---- smem byte map ----
// Tiles: swizzled fp16, 112 rows x 128 cols; one "half" = 28672B.
static constexpr int QB = 0;              // Q/O hi+lo (57344B); later: score2 f32 [100][132]
static constexpr int KB = 57344;          // K hi only; later: mh hi
static constexpr int VB = 86016;          // V hi only; later: mh lo (== KB + HILO)
static constexpr int HILO = 28672;
static constexpr int SA_H = 114688;       // A chunk buffer hi+lo (20480B)
static constexpr int SB_H = 135168;       // B chunk buffer hi only (10240B)
static constexpr int OFF_EX  = 145408;    // extras [100][4] f32
static constexpr int OFF_WQ4 = 147008;    // Wq rows 128..131 [4][128] f32
static constexpr int OFF_BC  = 149056;    // bc [128] f32
static constexpr int SMEM_TOTAL = 149568;
static constexpr int LDSR = 132;          // f32 row stride for scores buffer

// ---------------- prep: weights -> chunk-blocked fp16 (hi only), B^T layout ----
__device__ __half g_wt[4][20480];         // 4 chunks x 5120 halfs
__device__ float g_wq4[512];

__global__ void prep_weights(const float* __restrict__ Wq, const float* __restrict__ Wk,
                             const float* __restrict__ Wv, const float* __restrict__ Wc)
{
    const int w = blockIdx.x;
    const float* W = (w == 0) ? Wq : (w == 1) ? Wk : (w == 2) ? Wv : Wc;
    for (int idx = threadIdx.x; idx < 128 * 128; idx += blockDim.x) {
        int n = idx >> 7, k = idx & 127;
        float x = W[k * 128 + n];
        g_wt[w][(k >> 5) * 5120 + n * STB + (k & 31)] = __float2half(x);
    }
    if (w == 0) {
        for (int i = threadIdx.x; i < 512; i += blockDim.x)
            g_wq4[i] = Wq[128 * 128 + i];
    }
}

// ---------------- device helpers ----------------
__device__ __forceinline__ uint32_t smem_u32(const void* p) {
    uint32_t a;
    asm("{ .reg .u64 t; cvta.to.shared.u64 t, %1; cvt.u32.u64 %0, t; }" : "=r"(a) : "l"(p));
    return a;
}
__device__ __forceinline__ float tanh10(float x) {
    x = fminf(fmaxf(x, -20.f), 20.f);
    float t = __expf(2.f * x);
    return 10.f * (t - 1.f) / (t + 1.f);
}
// swizzled byte offset within a tile half: row r (0..111), byte col cb (0..255)
__device__ __forceinline__ uint32_t swz(int r, int cb) {
    return (uint32_t)(r * 256 + ((((cb >> 4) ^ (r & 7)) << 4) | (cb & 15)));
}

#define LDSM4(R0, R1, R2, R3, ADDR) \
    asm volatile("ldmatrix.sync.aligned.m8n8.x4.shared.b16 {%0,%1,%2,%3}, [%4];" \
        : "=r"(R0), "=r"(R1), "=r"(R2), "=r"(R3) : "r"(ADDR))
#define LDSM4T(R0, R1, R2, R3, ADDR) \
    asm volatile("ldmatrix.sync.aligned.m8n8.x4.trans.shared.b16 {%0,%1,%2,%3}, [%4];" \
        : "=r"(R0), "=r"(R1), "=r"(R2), "=r"(R3) : "r"(ADDR))
#define MMA16816(C, A, B0, B1) \
    asm volatile("mma.sync.aligned.m16n8k16.row.col.f32.f16.f16.f32 " \
        "{%0,%1,%2,%3}, {%4,%5,%6,%7}, {%8,%9}, {%0,%1,%2,%3};" \
        : "+f"((C)[0]), "+f"((C)[1]), "+f"((C)[2]), "+f"((C)[3]) \
        : "r"((A)[0]), "r"((A)[1]), "r"((A)[2]), "r"((A)[3]), "r"(B0), "r"(B1))

__device__ __forceinline__ void cvt_hilo(float a, float b, uint32_t& hi, uint32_t& lo) {
    __half2 h = __floats2half2_rn(a, b);
    __half2 l = __floats2half2_rn(a - __low2float(h), b - __high2float(h));
    hi = *reinterpret_cast<uint32_t*>(&h);
    lo = *reinterpret_cast<uint32_t*>(&l);
}
// write (v0,v1) as fp16 hi/lo pair into a swizzled tile at (row r, fp16 col c)
__device__ __forceinline__ void st_hilo(unsigned char* base, int r, int c, float v0, float v1) {
    uint32_t hi, lo;
    cvt_hilo(v0, v1, hi, lo);
    uint32_t off = swz(r, c * 2);
    *(uint32_t*)(base + off) = hi;
    *(uint32_t*)(base + HILO + off) = lo;
}
// write (v0,v1) as fp16 (hi only)
__device__ __forceinline__ void st_hi(unsigned char* base, int r, int c, float v0, float v1) {
    __half2 h = __floats2half2_rn(v0, v1);
    *(__half2*)(base + swz(r, c * 2)) = h;
}

// build one 128x32 hi/lo fp16 A-chunk from f32 row-major source
__device__ __forceinline__ void build_hilo(
    __half* __restrict__ dst, const float* __restrict__ src,
    int ld, int nrows, int k0)
{
    for (int i = threadIdx.x; i < 1024; i += TPB) {
        int r = i >> 3, q = (i & 7) << 2;
        float4 v = make_float4(0.f, 0.f, 0.f, 0.f);
        if (r < nrows) v = *(const float4*)&src[(size_t)r * ld + k0 + q];
        uint32_t h01, l01, h23, l23;
        cvt_hilo(v.x, v.y, h01, l01);
        cvt_hilo(v.z, v.w, h23, l23);
        int o = r * STB + q;
        *(uint32_t*)(dst + o)            = h01;
        *(uint32_t*)(dst + o + 2)        = h23;
        *(uint32_t*)(dst + 5120 + o)     = l01;
        *(uint32_t*)(dst + 5120 + o + 2) = l23;
    }
}
// build one 128x32 fp16 (hi only) B-chunk from f32 row-major source
__device__ __forceinline__ void build_hi(
    __half* __restrict__ dst, const float* __restrict__ src,
    int ld, int nrows, int k0)
{
    for (int i = threadIdx.x; i < 1024; i += TPB) {
        int r = i >> 3, q = (i & 7) << 2;
        float4 v = make_float4(0.f, 0.f, 0.f, 0.f);
        if (r < nrows) v = *(const float4*)&src[(size_t)r * ld + k0 + q];
        __half2 h01 = __floats2half2_rn(v.x, v.y);
        __half2 h23 = __floats2half2_rn(v.z, v.w);
        int o = r * STB + q;
        *(__half2*)(dst + o)     = h01;
        *(__half2*)(dst + o + 2) = h23;
    }
}

// GEMM mainloop: A (f32 src, split hi/lo) @ B (prepped fp16 weight wsel). 2 products.
__device__ __forceinline__ void gemm_core(
    unsigned char* smem8, uint32_t sb,
    const float* Asrc, int Ald, int Anrows, int wsel,
    float acc[2][4][4])
{
    const int tid = threadIdx.x, w = tid >> 5, lane = tid & 31;
    const int wm = w & 3, wn = w >> 2;
#pragma unroll
    for (int m = 0; m < 2; m++)
#pragma unroll
        for (int n = 0; n < 4; n++)
#pragma unroll
            for (int j = 0; j < 4; j++) acc[m][n][j] = 0.f;

    for (int c = 0; c < 4; c++) {
        __syncthreads();
        build_hilo((__half*)(smem8 + SA_H), Asrc, Ald, Anrows, c * 32);
        {
            const uint4* src = (const uint4*)&g_wt[wsel][c * 5120];
            uint4* dst = (uint4*)(smem8 + SB_H);
            for (int i = tid; i < 640; i += TPB) dst[i] = src[i];
        }
        __syncthreads();

#pragma unroll
        for (int ks = 0; ks < 2; ks++) {
            const int kb = ks * 16;
            uint32_t aH[2][4], aL[2][4];
#pragma unroll
            for (int m = 0; m < 2; m++) {
                uint32_t addr = sb + SA_H +
                    (uint32_t)(((wm * 32 + m * 16 + (lane & 15)) * STB
                                + kb + ((lane >> 4) << 3)) << 1);
                LDSM4(aH[m][0], aH[m][1], aH[m][2], aH[m][3], addr);
                LDSM4(aL[m][0], aL[m][1], aL[m][2], aL[m][3], addr + CHB);
            }
            uint32_t bH[4][2];
#pragma unroll
            for (int t = 0; t < 2; t++) {
                const uint32_t ba = sb + SB_H +
                    (uint32_t)(((wn * 32 + t * 16 + ((lane & 16) ? 8 : 0) + (lane & 7)) * STB
                                + kb + ((lane & 8) ? 8 : 0)) << 1);
                uint32_t r0, r1, r2, r3;
                LDSM4(r0, r1, r2, r3, ba);
                bH[2 * t][0] = r0;     bH[2 * t][1] = r1;
                bH[2 * t + 1][0] = r2; bH[2 * t + 1][1] = r3;
            }
#pragma unroll
            for (int m = 0; m < 2; m++)
#pragma unroll
                for (int n = 0; n < 4; n++) {
                    MMA16816(acc[m][n], aH[m], bH[n][0], bH[n][1]);
                    MMA16816(acc[m][n], aL[m], bH[n][0], bH[n][1]);
                }
        }
    }
    __syncthreads();
}

extern __shared__ __align__(16) unsigned char smem8[];

__global__ __launch_bounds__(TPB, 1)
void vrp_decoder_kernel(
    const float* __restrict__ eln,   const float* __restrict__ load_,
    const float* __restrict__ time_, const float* __restrict__ len_,
    const float* __restrict__ ropen, const float* __restrict__ mask,
    const float* __restrict__ nodes, const float* __restrict__ bc,
    float* __restrict__ out)
{
    const int b = blockIdx.x;
    const int tid = threadIdx.x;
    const int wid = tid >> 5, lane = tid & 31;
    const int wm = wid & 3, wn = wid >> 2;
    const uint32_t sb = smem_u32(smem8);

    float* sEx  = (float*)(smem8 + OFF_EX);
    float* sWq4 = (float*)(smem8 + OFF_WQ4);
    float* sBc  = (float*)(smem8 + OFF_BC);

    // ---- stage aux ----
    for (int i = tid; i < 512; i += TPB) sWq4[i] = g_wq4[i];
    for (int i = tid; i < 128; i += TPB) sBc[i] = bc[i];
    for (int r = tid; r < Pn; r += TPB) {
        sEx[r * 4 + 0] = load_[b * Pn + r];
        sEx[r * 4 + 1] = time_[b * Pn + r];
        sEx[r * 4 + 2] = len_[b * Pn + r];
        sEx[r * 4 + 3] = ropen[b * Pn + r];
    }

    const float* gE = eln + (size_t)b * Pn * EMBn;
    const float* gN = nodes + (size_t)b * Nn * EMBn;
    const float* gM = mask + (size_t)b * Pn * Nn;

    // ---- projections ----
    {
        float acc[2][4][4];
        // Q = eln @ Wq[0:128] (+extras correction) -> QB (hi/lo)
        gemm_core(smem8, sb, gE, EMBn, Pn, 0, acc);
#pragma unroll
        for (int m = 0; m < 2; m++)
#pragma unroll
            for (int n = 0; n < 4; n++) {
                int row = wm * 32 + m * 16 + (lane >> 2);
                int col = wn * 32 + n * 8 + ((lane & 3) << 1);
#pragma unroll
                for (int hh = 0; hh < 2; hh++) {
                    int r = row + 8 * hh;
                    if (r >= 112) continue;
                    float v0 = acc[m][n][2 * hh], v1 = acc[m][n][2 * hh + 1];
                    if (r < Pn) {
                        float e0 = sEx[r * 4], e1 = sEx[r * 4 + 1], e2 = sEx[r * 4 + 2], e3 = sEx[r * 4 + 3];
                        v0 += e0 * sWq4[col] + e1 * sWq4[128 + col] + e2 * sWq4[256 + col] + e3 * sWq4[384 + col];
                        v1 += e0 * sWq4[col + 1] + e1 * sWq4[128 + col + 1] + e2 * sWq4[256 + col + 1] + e3 * sWq4[384 + col + 1];
                    }
                    st_hilo(smem8 + QB, r, col, v0, v1);
                }
            }
        __syncthreads();
        // K = nodes @ Wk -> KB (hi only)
        gemm_core(smem8, sb, gN, EMBn, Nn, 1, acc);
#pragma unroll
        for (int m = 0; m < 2; m++)
#pragma unroll
            for (int n = 0; n < 4; n++) {
                int row = wm * 32 + m * 16 + (lane >> 2);
                int col = wn * 32 + n * 8 + ((lane & 3) << 1);
#pragma unroll
                for (int hh = 0; hh < 2; hh++) {
                    int r = row + 8 * hh;
                    if (r < 112) st_hi(smem8 + KB, r, col, acc[m][n][2 * hh], acc[m][n][2 * hh + 1]);
                }
            }
        __syncthreads();
        // V = nodes @ Wv -> VB (hi only)
        gemm_core(smem8, sb, gN, EMBn, Nn, 2, acc);
#pragma unroll
        for (int m = 0; m < 2; m++)
#pragma unroll
            for (int n = 0; n < 4; n++) {
                int row = wm * 32 + m * 16 + (lane >> 2);
                int col = wn * 32 + n * 8 + ((lane & 3) << 1);
#pragma unroll
                for (int hh = 0; hh < 2; hh++) {
                    int r = row + 8 * hh;
                    if (r < 112) st_hi(smem8 + VB, r, col, acc[m][n][2 * hh], acc[m][n][2 * hh + 1]);
                }
            }
        __syncthreads();
    }

    // ---- attention via mma.sync: item = (m16-tile mi, head h), 56 items / 16 warps ----
    for (int it = wid; it < 56; it += 16) {
        const int mi = it % 7, h = it / 7;
        const int r0 = mi * 16;
        uint32_t qa = sb + QB + swz(r0 + (lane & 15), (2 * h + (lane >> 4)) << 4);
        uint32_t qh[4], ql[4];
        LDSM4(qh[0], qh[1], qh[2], qh[3], qa);
        LDSM4(ql[0], ql[1], ql[2], ql[3], qa + HILO);

        float sf[14][4];
#pragma unroll
        for (int nt2 = 0; nt2 < 7; nt2++) {
            uint32_t ka = sb + KB + swz((2 * nt2 + ((lane >> 4) & 1)) * 8 + (lane & 7),
                                        (2 * h + ((lane >> 3) & 1)) << 4);
            uint32_t kh[4];
            LDSM4(kh[0], kh[1], kh[2], kh[3], ka);
            float c0[4] = {0.f, 0.f, 0.f, 0.f}, c1[4] = {0.f, 0.f, 0.f, 0.f};
            MMA16816(c0, qh, kh[0], kh[1]);
            MMA16816(c1, qh, kh[2], kh[3]);
            MMA16816(c0, ql, kh[0], kh[1]);
            MMA16816(c1, ql, kh[2], kh[3]);
#pragma unroll
            for (int j = 0; j < 4; j++) { sf[2 * nt2][j] = c0[j]; sf[2 * nt2 + 1][j] = c1[j]; }
        }
        const int rr0 = r0 + (lane >> 2), rr1 = rr0 + 8;
#pragma unroll
        for (int nt = 0; nt < 14; nt++) {
            int c0 = nt * 8 + ((lane & 3) << 1), c1 = c0 + 1;
            float m00 = (c0 < Nn) ? ((rr0 < Pn) ? gM[rr0 * Nn + c0] : 0.f) : -INFINITY;
            float m01 = (c1 < Nn) ? ((rr0 < Pn) ? gM[rr0 * Nn + c1] : 0.f) : -INFINITY;
            float m10 = (c0 < Nn) ? ((rr1 < Pn) ? gM[rr1 * Nn + c0] : 0.f) : -INFINITY;
            float m11 = (c1 < Nn) ? ((rr1 < Pn) ? gM[rr1 * Nn + c1] : 0.f) : -INFINITY;
            sf[nt][0] = sf[nt][0] * 0.25f + m00;
            sf[nt][1] = sf[nt][1] * 0.25f + m01;
            sf[nt][2] = sf[nt][2] * 0.25f + m10;
            sf[nt][3] = sf[nt][3] * 0.25f + m11;
        }
        float mx0 = -INFINITY, mx1 = -INFINITY;
#pragma unroll
        for (int nt = 0; nt < 14; nt++) {
            mx0 = fmaxf(mx0, fmaxf(sf[nt][0], sf[nt][1]));
            mx1 = fmaxf(mx1, fmaxf(sf[nt][2], sf[nt][3]));
        }
        mx0 = fmaxf(mx0, __shfl_xor_sync(0xffffffffu, mx0, 1));
        mx0 = fmaxf(mx0, __shfl_xor_sync(0xffffffffu, mx0, 2));
        mx1 = fmaxf(mx1, __shfl_xor_sync(0xffffffffu, mx1, 1));
        mx1 = fmaxf(mx1, __shfl_xor_sync(0xffffffffu, mx1, 2));
        float sum0 = 0.f, sum1 = 0.f;
#pragma unroll
        for (int nt = 0; nt < 14; nt++) {
            sf[nt][0] = __expf(sf[nt][0] - mx0); sum0 += sf[nt][0];
            sf[nt][1] = __expf(sf[nt][1] - mx0); sum0 += sf[nt][1];
            sf[nt][2] = __expf(sf[nt][2] - mx1); sum1 += sf[nt][2];
            sf[nt][3] = __expf(sf[nt][3] - mx1); sum1 += sf[nt][3];
        }
        sum0 += __shfl_xor_sync(0xffffffffu, sum0, 1);
        sum0 += __shfl_xor_sync(0xffffffffu, sum0, 2);
        sum1 += __shfl_xor_sync(0xffffffffu, sum1, 1);
        sum1 += __shfl_xor_sync(0xffffffffu, sum1, 2);
        const float inv0 = 1.f / sum0, inv1 = 1.f / sum1;

        // PV: 4 accumulator chains ([ng][kt-parity]); P split hi/lo, V hi only
        float accP[2][2][4];
#pragma unroll
        for (int g2 = 0; g2 < 2; g2++)
#pragma unroll
            for (int pr = 0; pr < 2; pr++)
#pragma unroll
                for (int j = 0; j < 4; j++) accP[g2][pr][j] = 0.f;
#pragma unroll
        for (int kt = 0; kt < 7; kt++) {
            const int pr = kt & 1;
            float p[8];
            p[0] = sf[2 * kt][0] * inv0;     p[1] = sf[2 * kt][1] * inv0;
            p[2] = sf[2 * kt][2] * inv1;     p[3] = sf[2 * kt][3] * inv1;
            p[4] = sf[2 * kt + 1][0] * inv0; p[5] = sf[2 * kt + 1][1] * inv0;
            p[6] = sf[2 * kt + 1][2] * inv1; p[7] = sf[2 * kt + 1][3] * inv1;
            uint32_t aH[4], aL[4];
#pragma unroll
            for (int q2 = 0; q2 < 4; q2++)
                cvt_hilo(p[2 * q2], p[2 * q2 + 1], aH[q2], aL[q2]);
            uint32_t va = sb + VB + swz(kt * 16 + (lane & 15), (2 * h + (lane >> 4)) << 4);
            uint32_t vh[4];
            LDSM4T(vh[0], vh[1], vh[2], vh[3], va);
            MMA16816(accP[0][pr], aH, vh[0], vh[1]);
            MMA16816(accP[1][pr], aH, vh[2], vh[3]);
            MMA16816(accP[0][pr], aL, vh[0], vh[1]);
            MMA16816(accP[1][pr], aL, vh[2], vh[3]);
        }
        // write O in place over this item's Q slot (hi/lo)
#pragma unroll
        for (int ng = 0; ng < 2; ng++) {
            int col = h * 16 + ng * 8 + ((lane & 3) << 1);
            st_hilo(smem8 + QB, rr0, col, accP[ng][0][0] + accP[ng][1][0],
                                          accP[ng][0][1] + accP[ng][1][1]);
            st_hilo(smem8 + QB, rr1, col, accP[ng][0][2] + accP[ng][1][2],
                                          accP[ng][0][3] + accP[ng][1][3]);
        }
    }
    __syncthreads();

    // ---- mh = O @ Wc + bc : A from QB (hi/lo), B = Wc (hi only); out -> KB tiles (hi/lo) ----
    {
        float acc2[2][4][4];
#pragma unroll
        for (int t = 0; t < 2; t++)
#pragma unroll
            for (int n = 0; n < 4; n++)
#pragma unroll
                for (int j = 0; j < 4; j++) acc2[t][n][j] = 0.f;

        for (int c = 0; c < 4; c++) {
            __syncthreads();
            {
                const uint4* src = (const uint4*)&g_wt[3][c * 5120];
                uint4* dst = (uint4*)(smem8 + SB_H);
                for (int i = tid; i < 640; i += TPB) dst[i] = src[i];
            }
            __syncthreads();
#pragma unroll
            for (int ks = 0; ks < 2; ks++) {
                const int kc = c * 2 + ks;
#pragma unroll
                for (int t = 0; t < 2; t++) {
                    const int it = wid + t * 16;
                    if (it >= 28) break;
                    const int mi = it % 7, ng = it / 7;
                    uint32_t aa = sb + QB + swz(mi * 16 + (lane & 15), (2 * kc + (lane >> 4)) << 4);
                    uint32_t ah[4], al[4];
                    LDSM4(ah[0], ah[1], ah[2], ah[3], aa);
                    LDSM4(al[0], al[1], al[2], al[3], aa + HILO);
                    uint32_t bH[4][2];
#pragma unroll
                    for (int tt = 0; tt < 2; tt++) {
                        const uint32_t ba = sb + SB_H +
                            (uint32_t)(((ng * 32 + tt * 16 + ((lane & 16) ? 8 : 0) + (lane & 7)) * STB
                                        + ks * 16 + ((lane & 8) ? 8 : 0)) << 1);
                        uint32_t r0, r1, r2, r3;
                        LDSM4(r0, r1, r2, r3, ba);
                        bH[2 * tt][0] = r0;     bH[2 * tt][1] = r1;
                        bH[2 * tt + 1][0] = r2; bH[2 * tt + 1][1] = r3;
                    }
#pragma unroll
                    for (int n = 0; n < 4; n++) {
                        MMA16816(acc2[t][n], ah, bH[n][0], bH[n][1]);
                        MMA16816(acc2[t][n], al, bH[n][0], bH[n][1]);
                    }
                }
            }
        }
        __syncthreads();
        // epilogue: mh (+bc) -> hi/lo tiles in KB (K/V tiles are dead; lo lands in VB region)
#pragma unroll
        for (int t = 0; t < 2; t++) {
            const int it = wid + t * 16;
            if (it >= 28) break;
            const int mi = it % 7, ng = it / 7;
#pragma unroll
            for (int n = 0; n < 4; n++) {
                int row = mi * 16 + (lane >> 2);
                int col = ng * 32 + n * 8 + ((lane & 3) << 1);
                float b0 = sBc[col], b1 = sBc[col + 1];
                st_hilo(smem8 + KB, row, col, acc2[t][n][0] + b0, acc2[t][n][1] + b1);
                st_hilo(smem8 + KB, row + 8, col, acc2[t][n][2] + b0, acc2[t][n][3] + b1);
            }
        }
        __syncthreads();
    }

    // ---- score2 = mh @ nodes^T : A from KB tiles (hi/lo), B = nodes (hi chunks); f32 -> QB ----
    {
        float acc[2][4][4];
#pragma unroll
        for (int m = 0; m < 2; m++)
#pragma unroll
            for (int n = 0; n < 4; n++)
#pragma unroll
                for (int j = 0; j < 4; j++) acc[m][n][j] = 0.f;

        for (int c = 0; c < 4; c++) {
            __syncthreads();
            build_hi((__half*)(smem8 + SB_H), gN, EMBn, Nn, c * 32);
            __syncthreads();
#pragma unroll
            for (int ks = 0; ks < 2; ks++) {
                const int kc = c * 2 + ks;
                uint32_t aH[2][4], aL[2][4];
#pragma unroll
                for (int m = 0; m < 2; m++) {
                    // rows 112..127 read adjacent finite smem; those output rows are discarded
                    uint32_t aa = sb + KB + swz(wm * 32 + m * 16 + (lane & 15), (2 * kc + (lane >> 4)) << 4);
                    LDSM4(aH[m][0], aH[m][1], aH[m][2], aH[m][3], aa);
                    LDSM4(aL[m][0], aL[m][1], aL[m][2], aL[m][3], aa + HILO);
                }
                uint32_t bH[4][2];
#pragma unroll
                for (int t = 0; t < 2; t++) {
                    const uint32_t ba = sb + SB_H +
                        (uint32_t)(((wn * 32 + t * 16 + ((lane & 16) ? 8 : 0) + (lane & 7)) * STB
                                    + ks * 16 + ((lane & 8) ? 8 : 0)) << 1);
                    uint32_t r0, r1, r2, r3;
                    LDSM4(r0, r1, r2, r3, ba);
                    bH[2 * t][0] = r0;     bH[2 * t][1] = r1;
                    bH[2 * t + 1][0] = r2; bH[2 * t + 1][1] = r3;
                }
#pragma unroll
                for (int m = 0; m < 2; m++)
#pragma unroll
                    for (int n = 0; n < 4; n++) {
                        MMA16816(acc[m][n], aH[m], bH[n][0], bH[n][1]);
                        MMA16816(acc[m][n], aL[m], bH[n][0], bH[n][1]);
                    }
            }
        }
        __syncthreads();
        float* SC = (float*)(smem8 + QB);   // QB region is dead after mh GEMM
#pragma unroll
        for (int m = 0; m < 2; m++)
#pragma unroll
            for (int n = 0; n < 4; n++) {
                int row = wm * 32 + m * 16 + (lane >> 2);
                int col = wn * 32 + n * 8 + ((lane & 3) << 1);
                if (row < Pn)
                    *(float2*)&SC[row * LDSR + col] = make_float2(acc[m][n][0], acc[m][n][1]);
                if (row + 8 < Pn)
                    *(float2*)&SC[(row + 8) * LDSR + col] = make_float2(acc[m][n][2], acc[m][n][3]);
            }
        __syncthreads();
    }

    // ---- final: clip*tanh(score2/sqrt(128)) + mask; softmax; store ----
    const float INV_SQRT_EMB = 0.08838834764831843f;
    const float* SC = (const float*)(smem8 + QB);
    float* gOut = out + (size_t)b * Pn * Nn;
    for (int pi = wid; pi < Pn / 2; pi += 16) {
        const int p0 = 2 * pi, p1 = p0 + 1;
        float s0[4], s1[4];
        int nn[4];
#pragma unroll
        for (int j = 0; j < 4; j++) {
            int n = lane + 32 * j;
            nn[j] = n;
            if (n < Nn) {
                s0[j] = tanh10(SC[p0 * LDSR + n] * INV_SQRT_EMB) + gM[p0 * Nn + n];
                s1[j] = tanh10(SC[p1 * LDSR + n] * INV_SQRT_EMB) + gM[p1 * Nn + n];
            } else { s0[j] = -INFINITY; s1[j] = -INFINITY; }
        }
        float mx0 = fmaxf(fmaxf(s0[0], s0[1]), fmaxf(s0[2], s0[3]));
        float mx1 = fmaxf(fmaxf(s1[0], s1[1]), fmaxf(s1[2], s1[3]));
#pragma unroll
        for (int off = 16; off; off >>= 1) {
            mx0 = fmaxf(mx0, __shfl_xor_sync(0xffffffffu, mx0, off));
            mx1 = fmaxf(mx1, __shfl_xor_sync(0xffffffffu, mx1, off));
        }
        float w0[4], w1[4], sum0 = 0.f, sum1 = 0.f;
#pragma unroll
        for (int j = 0; j < 4; j++) {
            w0[j] = __expf(s0[j] - mx0); sum0 += w0[j];
            w1[j] = __expf(s1[j] - mx1); sum1 += w1[j];
        }
#pragma unroll
        for (int off = 16; off; off >>= 1) {
            sum0 += __shfl_xor_sync(0xffffffffu, sum0, off);
            sum1 += __shfl_xor_sync(0xffffffffu, sum1, off);
        }
        const float i0 = 1.f / sum0, i1 = 1.f / sum1;
#pragma unroll
        for (int j = 0; j < 4; j++) {
            if (nn[j] < Nn) {
                gOut[p0 * Nn + nn[j]] = w0[j] * i0;
                gOut[p1 * Nn + nn[j]] = w1[j] * i1;
            }
        }
    }
}

extern "C" void kernel_launch(void* const* d_in, const int* in_sizes, int n_in,
                              void* d_out, int out_size) {
    const float* eln   = (const float*)d_in[0];
    const float* load_ = (const float*)d_in[1];
    const float* time_ = (const float*)d_in[2];
    const float* len_  = (const float*)d_in[3];
    const float* ropen = (const float*)d_in[4];
    const float* mask  = (const float*)d_in[5];
    const float* nodes = (const float*)d_in[6];
    const float* Wq    = (const float*)d_in[7];
    const float* Wk    = (const float*)d_in[8];
    const float* Wv    = (const float*)d_in[9];
    const float* Wc    = (const float*)d_in[10];
    const float* bc    = (const float*)d_in[11];
    float* out = (float*)d_out;

    prep_weights<<<4, 256>>>(Wq, Wk, Wv, Wc);
    cudaFuncSetAttribute(vrp_decoder_kernel,
                         cudaFuncAttributeMaxDynamicSharedMemorySize, SMEM_TOTAL);
    vrp_decoder_kernel<<<Bn, TPB, SMEM_TOTAL>>>(
        eln, load_, time_, len_, ropen, mask, nodes, bc, out);
}

// round 13
// speedup vs baseline: 2.2155x; 1.0695x over previous
#include <cuda_runtime.h>
#include <cuda_fp16.h>
#include <cstdint>

#define TPB 512
static constexpr int Bn = 1024, Pn = 100, Nn = 101, EMBn = 128;
static constexpr int Hn = 8, DKn = 16;

static constexpr int STB = 40;       // fp16 row stride inside chunk tiles
static constexpr int CHB = 10240;    // byte offset of lo half inside the A chunk buffer
static constexpr int MKW = 112;      // mask row width (covers attention reads up to col 110)
// ---- smem byte map ----
// Tiles: swizzled fp16, 112 rows x 128 cols; one "half" = 28672B.
static constexpr int QB = 0;              // Q/O hi+lo (57344B); later: score2 f32 [100][132]
static constexpr int KB = 57344;          // K hi only; later: mh hi
static constexpr int VB = 86016;          // V hi only; later: mh lo (== KB + HILO)
static constexpr int HILO = 28672;
static constexpr int SA_H = 114688;       // A chunk buffer hi+lo (20480B)
static constexpr int SB_H = 135168;       // B chunk buffer hi only (10240B)
static constexpr int SB2_H = 145408;      // second B chunk for fused KV (10240B)
static constexpr int MK   = 155648;       // mask fp16 [100][112] = 22400B
static constexpr int OFF_EX  = 178048;    // extras [100][4] f32
static constexpr int OFF_WQ4 = 179648;    // Wq rows 128..131 [4][128] f32
static constexpr int OFF_BC  = 181696;    // bc [128] f32
static constexpr int SMEM_TOTAL = 182208;
static constexpr int LDSR = 132;          // f32 row stride for scores buffer

// ---------------- prep: weights -> chunk-blocked fp16 (hi only), B^T layout ----
__device__ __half g_wt[4][20480];         // 4 chunks x 5120 halfs
__device__ float g_wq4[512];

__global__ void prep_weights(const float* __restrict__ Wq, const float* __restrict__ Wk,
                             const float* __restrict__ Wv, const float* __restrict__ Wc)
{
    const int w = blockIdx.x;
    const float* W = (w == 0) ? Wq : (w == 1) ? Wk : (w == 2) ? Wv : Wc;
    for (int idx = threadIdx.x; idx < 128 * 128; idx += blockDim.x) {
        int n = idx >> 7, k = idx & 127;
        g_wt[w][(k >> 5) * 5120 + n * STB + (k & 31)] = __float2half(W[k * 128 + n]);
    }
    if (w == 0) {
        for (int i = threadIdx.x; i < 512; i += blockDim.x)
            g_wq4[i] = Wq[128 * 128 + i];
    }
}

// ---------------- device helpers ----------------
__device__ __forceinline__ uint32_t smem_u32(const void* p) {
    uint32_t a;
    asm("{ .reg .u64 t; cvta.to.shared.u64 t, %1; cvt.u32.u64 %0, t; }" : "=r"(a) : "l"(p));
    return a;
}
__device__ __forceinline__ float tanh10(float x) {
    x = fminf(fmaxf(x, -20.f), 20.f);
    float t = __expf(2.f * x);
    return 10.f * (t - 1.f) / (t + 1.f);
}
// swizzled byte offset within a tile half: row r (0..111), byte col cb (0..255)
__device__ __forceinline__ uint32_t swz(int r, int cb) {
    return (uint32_t)(r * 256 + ((((cb >> 4) ^ (r & 7)) << 4) | (cb & 15)));
}

#define LDSM4(R0, R1, R2, R3, ADDR) \
    asm volatile("ldmatrix.sync.aligned.m8n8.x4.shared.b16 {%0,%1,%2,%3}, [%4];" \
        : "=r"(R0), "=r"(R1), "=r"(R2), "=r"(R3) : "r"(ADDR))
#define LDSM4T(R0, R1, R2, R3, ADDR) \
    asm volatile("ldmatrix.sync.aligned.m8n8.x4.trans.shared.b16 {%0,%1,%2,%3}, [%4];" \
        : "=r"(R0), "=r"(R1), "=r"(R2), "=r"(R3) : "r"(ADDR))
#define MMA16816(C, A, B0, B1) \
    asm volatile("mma.sync.aligned.m16n8k16.row.col.f32.f16.f16.f32 " \
        "{%0,%1,%2,%3}, {%4,%5,%6,%7}, {%8,%9}, {%0,%1,%2,%3};" \
        : "+f"((C)[0]), "+f"((C)[1]), "+f"((C)[2]), "+f"((C)[3]) \
        : "r"((A)[0]), "r"((A)[1]), "r"((A)[2]), "r"((A)[3]), "r"(B0), "r"(B1))

__device__ __forceinline__ void cvt_hilo(float a, float b, uint32_t& hi, uint32_t& lo) {
    __half2 h = __floats2half2_rn(a, b);
    __half2 l = __floats2half2_rn(a - __low2float(h), b - __high2float(h));
    hi = *reinterpret_cast<uint32_t*>(&h);
    lo = *reinterpret_cast<uint32_t*>(&l);
}
__device__ __forceinline__ void st_hilo(unsigned char* base, int r, int c, float v0, float v1) {
    uint32_t hi, lo;
    cvt_hilo(v0, v1, hi, lo);
    uint32_t off = swz(r, c * 2);
    *(uint32_t*)(base + off) = hi;
    *(uint32_t*)(base + HILO + off) = lo;
}
__device__ __forceinline__ void st_hi(unsigned char* base, int r, int c, float v0, float v1) {
    *(__half2*)(base + swz(r, c * 2)) = __floats2half2_rn(v0, v1);
}

// build one 128x32 hi/lo fp16 A-chunk from f32 row-major source
__device__ __forceinline__ void build_hilo(
    __half* __restrict__ dst, const float* __restrict__ src,
    int ld, int nrows, int k0)
{
    for (int i = threadIdx.x; i < 1024; i += TPB) {
        int r = i >> 3, q = (i & 7) << 2;
        float4 v = make_float4(0.f, 0.f, 0.f, 0.f);
        if (r < nrows) v = *(const float4*)&src[(size_t)r * ld + k0 + q];
        uint32_t h01, l01, h23, l23;
        cvt_hilo(v.x, v.y, h01, l01);
        cvt_hilo(v.z, v.w, h23, l23);
        int o = r * STB + q;
        *(uint32_t*)(dst + o)            = h01;
        *(uint32_t*)(dst + o + 2)        = h23;
        *(uint32_t*)(dst + 5120 + o)     = l01;
        *(uint32_t*)(dst + 5120 + o + 2) = l23;
    }
}
// build one 128x32 fp16 (hi only) B-chunk from f32 row-major source
__device__ __forceinline__ void build_hi(
    __half* __restrict__ dst, const float* __restrict__ src,
    int ld, int nrows, int k0)
{
    for (int i = threadIdx.x; i < 1024; i += TPB) {
        int r = i >> 3, q = (i & 7) << 2;
        float4 v = make_float4(0.f, 0.f, 0.f, 0.f);
        if (r < nrows) v = *(const float4*)&src[(size_t)r * ld + k0 + q];
        int o = r * STB + q;
        *(__half2*)(dst + o)     = __floats2half2_rn(v.x, v.y);
        *(__half2*)(dst + o + 2) = __floats2half2_rn(v.z, v.w);
    }
}

// GEMM mainloop: A (f32 src, split hi/lo) @ B (prepped fp16 weight wsel). 2 products.
__device__ __forceinline__ void gemm_core(
    unsigned char* smem8, uint32_t sb,
    const float* Asrc, int Ald, int Anrows, int wsel,
    float acc[2][4][4])
{
    const int tid = threadIdx.x, w = tid >> 5, lane = tid & 31;
    const int wm = w & 3, wn = w >> 2;
#pragma unroll
    for (int m = 0; m < 2; m++)
#pragma unroll
        for (int n = 0; n < 4; n++)
#pragma unroll
            for (int j = 0; j < 4; j++) acc[m][n][j] = 0.f;

    for (int c = 0; c < 4; c++) {
        __syncthreads();
        build_hilo((__half*)(smem8 + SA_H), Asrc, Ald, Anrows, c * 32);
        {
            const uint4* src = (const uint4*)&g_wt[wsel][c * 5120];
            uint4* dst = (uint4*)(smem8 + SB_H);
            for (int i = tid; i < 640; i += TPB) dst[i] = src[i];
        }
        __syncthreads();

#pragma unroll
        for (int ks = 0; ks < 2; ks++) {
            const int kb = ks * 16;
            uint32_t aH[2][4], aL[2][4];
#pragma unroll
            for (int m = 0; m < 2; m++) {
                uint32_t addr = sb + SA_H +
                    (uint32_t)(((wm * 32 + m * 16 + (lane & 15)) * STB
                                + kb + ((lane >> 4) << 3)) << 1);
                LDSM4(aH[m][0], aH[m][1], aH[m][2], aH[m][3], addr);
                LDSM4(aL[m][0], aL[m][1], aL[m][2], aL[m][3], addr + CHB);
            }
            uint32_t bH[4][2];
#pragma unroll
            for (int t = 0; t < 2; t++) {
                const uint32_t ba = sb + SB_H +
                    (uint32_t)(((wn * 32 + t * 16 + ((lane & 16) ? 8 : 0) + (lane & 7)) * STB
                                + kb + ((lane & 8) ? 8 : 0)) << 1);
                uint32_t r0, r1, r2, r3;
                LDSM4(r0, r1, r2, r3, ba);
                bH[2 * t][0] = r0;     bH[2 * t][1] = r1;
                bH[2 * t + 1][0] = r2; bH[2 * t + 1][1] = r3;
            }
#pragma unroll
            for (int m = 0; m < 2; m++)
#pragma unroll
                for (int n = 0; n < 4; n++) {
                    MMA16816(acc[m][n], aH[m], bH[n][0], bH[n][1]);
                    MMA16816(acc[m][n], aL[m], bH[n][0], bH[n][1]);
                }
        }
    }
    __syncthreads();
}

extern __shared__ __align__(16) unsigned char smem8[];

__global__ __launch_bounds__(TPB, 1)
void vrp_decoder_kernel(
    const float* __restrict__ eln,   const float* __restrict__ load_,
    const float* __restrict__ time_, const float* __restrict__ len_,
    const float* __restrict__ ropen, const float* __restrict__ mask,
    const float* __restrict__ nodes, const float* __restrict__ bc,
    float* __restrict__ out)
{
    const int b = blockIdx.x;
    const int tid = threadIdx.x;
    const int wid = tid >> 5, lane = tid & 31;
    const int wm = wid & 3, wn = wid >> 2;
    const uint32_t sb = smem_u32(smem8);

    float* sEx  = (float*)(smem8 + OFF_EX);
    float* sWq4 = (float*)(smem8 + OFF_WQ4);
    float* sBc  = (float*)(smem8 + OFF_BC);

    const float* gE = eln + (size_t)b * Pn * EMBn;
    const float* gN = nodes + (size_t)b * Nn * EMBn;
    const float* gM = mask + (size_t)b * Pn * Nn;

    // ---- stage aux + mask -> smem fp16 [100][112] (cols >= 101 = -inf) ----
    for (int i = tid; i < 512; i += TPB) sWq4[i] = g_wq4[i];
    for (int i = tid; i < 128; i += TPB) sBc[i] = bc[i];
    for (int r = tid; r < Pn; r += TPB) {
        sEx[r * 4 + 0] = load_[b * Pn + r];
        sEx[r * 4 + 1] = time_[b * Pn + r];
        sEx[r * 4 + 2] = len_[b * Pn + r];
        sEx[r * 4 + 3] = ropen[b * Pn + r];
    }
    for (int i = tid; i < Pn * (MKW / 2); i += TPB) {
        int r = i / (MKW / 2), j = i % (MKW / 2);
        int n0 = 2 * j, n1 = n0 + 1;
        float a  = (n0 < Nn) ? gM[r * Nn + n0] : -INFINITY;
        float bb = (n1 < Nn) ? gM[r * Nn + n1] : -INFINITY;
        *(__half2*)(smem8 + MK + (r * MKW + n0) * 2) = __floats2half2_rn(a, bb);
    }

    // ---- Q = eln @ Wq[0:128] (+extras correction) -> QB (hi/lo) ----
    {
        float acc[2][4][4];
        gemm_core(smem8, sb, gE, EMBn, Pn, 0, acc);
#pragma unroll
        for (int m = 0; m < 2; m++)
#pragma unroll
            for (int n = 0; n < 4; n++) {
                int row = wm * 32 + m * 16 + (lane >> 2);
                int col = wn * 32 + n * 8 + ((lane & 3) << 1);
#pragma unroll
                for (int hh = 0; hh < 2; hh++) {
                    int r = row + 8 * hh;
                    if (r >= 112) continue;
                    float v0 = acc[m][n][2 * hh], v1 = acc[m][n][2 * hh + 1];
                    if (r < Pn) {
                        float e0 = sEx[r * 4], e1 = sEx[r * 4 + 1], e2 = sEx[r * 4 + 2], e3 = sEx[r * 4 + 3];
                        v0 += e0 * sWq4[col] + e1 * sWq4[128 + col] + e2 * sWq4[256 + col] + e3 * sWq4[384 + col];
                        v1 += e0 * sWq4[col + 1] + e1 * sWq4[128 + col + 1] + e2 * sWq4[256 + col + 1] + e3 * sWq4[384 + col + 1];
                    }
                    st_hilo(smem8 + QB, r, col, v0, v1);
                }
            }
        __syncthreads();
    }

    // ---- fused K,V = nodes @ Wk / Wv -> KB / VB (hi only; shared hi/lo A chunks) ----
    {
        float accK[2][4][4], accV[2][4][4];
#pragma unroll
        for (int m = 0; m < 2; m++)
#pragma unroll
            for (int n = 0; n < 4; n++)
#pragma unroll
                for (int j = 0; j < 4; j++) { accK[m][n][j] = 0.f; accV[m][n][j] = 0.f; }

        for (int c = 0; c < 4; c++) {
            __syncthreads();
            build_hilo((__half*)(smem8 + SA_H), gN, EMBn, Nn, c * 32);
            {
                const uint4* s1 = (const uint4*)&g_wt[1][c * 5120];
                const uint4* s2 = (const uint4*)&g_wt[2][c * 5120];
                uint4* d1 = (uint4*)(smem8 + SB_H);
                uint4* d2 = (uint4*)(smem8 + SB2_H);
                for (int i = tid; i < 640; i += TPB) { d1[i] = s1[i]; d2[i] = s2[i]; }
            }
            __syncthreads();
#pragma unroll
            for (int ks = 0; ks < 2; ks++) {
                const int kb = ks * 16;
                uint32_t aH[2][4], aL[2][4];
#pragma unroll
                for (int m = 0; m < 2; m++) {
                    uint32_t addr = sb + SA_H +
                        (uint32_t)(((wm * 32 + m * 16 + (lane & 15)) * STB
                                    + kb + ((lane >> 4) << 3)) << 1);
                    LDSM4(aH[m][0], aH[m][1], aH[m][2], aH[m][3], addr);
                    LDSM4(aL[m][0], aL[m][1], aL[m][2], aL[m][3], addr + CHB);
                }
                const uint32_t brow = (uint32_t)(((wn * 32 + ((lane & 16) ? 8 : 0) + (lane & 7)) * STB
                                                 + kb + ((lane & 8) ? 8 : 0)) << 1);
                uint32_t bK[4][2], bV[4][2];
#pragma unroll
                for (int t = 0; t < 2; t++) {
                    uint32_t off = brow + (uint32_t)((t * 16 * STB) << 1);
                    uint32_t r0, r1, r2, r3;
                    LDSM4(r0, r1, r2, r3, sb + SB_H + off);
                    bK[2 * t][0] = r0;     bK[2 * t][1] = r1;
                    bK[2 * t + 1][0] = r2; bK[2 * t + 1][1] = r3;
                    LDSM4(r0, r1, r2, r3, sb + SB2_H + off);
                    bV[2 * t][0] = r0;     bV[2 * t][1] = r1;
                    bV[2 * t + 1][0] = r2; bV[2 * t + 1][1] = r3;
                }
#pragma unroll
                for (int m = 0; m < 2; m++)
#pragma unroll
                    for (int n = 0; n < 4; n++) {
                        MMA16816(accK[m][n], aH[m], bK[n][0], bK[n][1]);
                        MMA16816(accK[m][n], aL[m], bK[n][0], bK[n][1]);
                        MMA16816(accV[m][n], aH[m], bV[n][0], bV[n][1]);
                        MMA16816(accV[m][n], aL[m], bV[n][0], bV[n][1]);
                    }
            }
        }
        __syncthreads();
#pragma unroll
        for (int m = 0; m < 2; m++)
#pragma unroll
            for (int n = 0; n < 4; n++) {
                int row = wm * 32 + m * 16 + (lane >> 2);
                int col = wn * 32 + n * 8 + ((lane & 3) << 1);
#pragma unroll
                for (int hh = 0; hh < 2; hh++) {
                    int r = row + 8 * hh;
                    if (r < 112) {
                        st_hi(smem8 + KB, r, col, accK[m][n][2 * hh], accK[m][n][2 * hh + 1]);
                        st_hi(smem8 + VB, r, col, accV[m][n][2 * hh], accV[m][n][2 * hh + 1]);
                    }
                }
            }
        __syncthreads();
    }

    // ---- attention via mma.sync: item = (m16-tile mi, head h), 56 items / 16 warps ----
    for (int it = wid; it < 56; it += 16) {
        const int mi = it % 7, h = it / 7;
        const int r0 = mi * 16;
        uint32_t qa = sb + QB + swz(r0 + (lane & 15), (2 * h + (lane >> 4)) << 4);
        uint32_t qh[4], ql[4];
        LDSM4(qh[0], qh[1], qh[2], qh[3], qa);
        LDSM4(ql[0], ql[1], ql[2], ql[3], qa + HILO);

        float sf[14][4];
#pragma unroll
        for (int nt2 = 0; nt2 < 7; nt2++) {
            uint32_t ka = sb + KB + swz((2 * nt2 + ((lane >> 4) & 1)) * 8 + (lane & 7),
                                        (2 * h + ((lane >> 3) & 1)) << 4);
            uint32_t kh[4];
            LDSM4(kh[0], kh[1], kh[2], kh[3], ka);
            float c0[4] = {0.f, 0.f, 0.f, 0.f}, c1[4] = {0.f, 0.f, 0.f, 0.f};
            MMA16816(c0, qh, kh[0], kh[1]);
            MMA16816(c1, qh, kh[2], kh[3]);
            MMA16816(c0, ql, kh[0], kh[1]);
            MMA16816(c1, ql, kh[2], kh[3]);
#pragma unroll
            for (int j = 0; j < 4; j++) { sf[2 * nt2][j] = c0[j]; sf[2 * nt2 + 1][j] = c1[j]; }
        }
        const int rr0 = r0 + (lane >> 2), rr1 = rr0 + 8;
#pragma unroll
        for (int nt = 0; nt < 14; nt++) {
            const int cc = nt * 8 + ((lane & 3) << 1);   // up to 110 < MKW
            float2 mA, mB;
            if (rr0 < Pn) mA = __half22float2(*(__half2*)(smem8 + MK + (rr0 * MKW + cc) * 2));
            else { mA.x = (cc < Nn) ? 0.f : -INFINITY; mA.y = (cc + 1 < Nn) ? 0.f : -INFINITY; }
            if (rr1 < Pn) mB = __half22float2(*(__half2*)(smem8 + MK + (rr1 * MKW + cc) * 2));
            else { mB.x = (cc < Nn) ? 0.f : -INFINITY; mB.y = (cc + 1 < Nn) ? 0.f : -INFINITY; }
            sf[nt][0] = sf[nt][0] * 0.25f + mA.x;
            sf[nt][1] = sf[nt][1] * 0.25f + mA.y;
            sf[nt][2] = sf[nt][2] * 0.25f + mB.x;
            sf[nt][3] = sf[nt][3] * 0.25f + mB.y;
        }
        float mx0 = -INFINITY, mx1 = -INFINITY;
#pragma unroll
        for (int nt = 0; nt < 14; nt++) {
            mx0 = fmaxf(mx0, fmaxf(sf[nt][0], sf[nt][1]));
            mx1 = fmaxf(mx1, fmaxf(sf[nt][2], sf[nt][3]));
        }
        mx0 = fmaxf(mx0, __shfl_xor_sync(0xffffffffu, mx0, 1));
        mx0 = fmaxf(mx0, __shfl_xor_sync(0xffffffffu, mx0, 2));
        mx1 = fmaxf(mx1, __shfl_xor_sync(0xffffffffu, mx1, 1));
        mx1 = fmaxf(mx1, __shfl_xor_sync(0xffffffffu, mx1, 2));
        float sum0 = 0.f, sum1 = 0.f;
#pragma unroll
        for (int nt = 0; nt < 14; nt++) {
            sf[nt][0] = __expf(sf[nt][0] - mx0); sum0 += sf[nt][0];
            sf[nt][1] = __expf(sf[nt][1] - mx0); sum0 += sf[nt][1];
            sf[nt][2] = __expf(sf[nt][2] - mx1); sum1 += sf[nt][2];
            sf[nt][3] = __expf(sf[nt][3] - mx1); sum1 += sf[nt][3];
        }
        sum0 += __shfl_xor_sync(0xffffffffu, sum0, 1);
        sum0 += __shfl_xor_sync(0xffffffffu, sum0, 2);
        sum1 += __shfl_xor_sync(0xffffffffu, sum1, 1);
        sum1 += __shfl_xor_sync(0xffffffffu, sum1, 2);
        const float inv0 = 1.f / sum0, inv1 = 1.f / sum1;

        // PV: 4 accumulator chains ([ng][kt-parity]); P split hi/lo, V hi only
        float accP[2][2][4];
#pragma unroll
        for (int g2 = 0; g2 < 2; g2++)
#pragma unroll
            for (int pr = 0; pr < 2; pr++)
#pragma unroll
                for (int j = 0; j < 4; j++) accP[g2][pr][j] = 0.f;
#pragma unroll
        for (int kt = 0; kt < 7; kt++) {
            const int pr = kt & 1;
            float p[8];
            p[0] = sf[2 * kt][0] * inv0;     p[1] = sf[2 * kt][1] * inv0;
            p[2] = sf[2 * kt][2] * inv1;     p[3] = sf[2 * kt][3] * inv1;
            p[4] = sf[2 * kt + 1][0] * inv0; p[5] = sf[2 * kt + 1][1] * inv0;
            p[6] = sf[2 * kt + 1][2] * inv1; p[7] = sf[2 * kt + 1][3] * inv1;
            uint32_t aH[4], aL[4];
#pragma unroll
            for (int q2 = 0; q2 < 4; q2++)
                cvt_hilo(p[2 * q2], p[2 * q2 + 1], aH[q2], aL[q2]);
            uint32_t va = sb + VB + swz(kt * 16 + (lane & 15), (2 * h + (lane >> 4)) << 4);
            uint32_t vh[4];
            LDSM4T(vh[0], vh[1], vh[2], vh[3], va);
            MMA16816(accP[0][pr], aH, vh[0], vh[1]);
            MMA16816(accP[1][pr], aH, vh[2], vh[3]);
            MMA16816(accP[0][pr], aL, vh[0], vh[1]);
            MMA16816(accP[1][pr], aL, vh[2], vh[3]);
        }
        // write O in place over this item's Q slot (hi/lo)
#pragma unroll
        for (int ng = 0; ng < 2; ng++) {
            int col = h * 16 + ng * 8 + ((lane & 3) << 1);
            st_hilo(smem8 + QB, rr0, col, accP[ng][0][0] + accP[ng][1][0],
                                          accP[ng][0][1] + accP[ng][1][1]);
            st_hilo(smem8 + QB, rr1, col, accP[ng][0][2] + accP[ng][1][2],
                                          accP[ng][0][3] + accP[ng][1][3]);
        }
    }
    __syncthreads();

    // ---- mh = O @ Wc + bc : A from QB (hi/lo), B = Wc (hi only); out -> KB tiles (hi/lo) ----
    {
        float acc2[2][4][4];
#pragma unroll
        for (int t = 0; t < 2; t++)
#pragma unroll
            for (int n = 0; n < 4; n++)
#pragma unroll
                for (int j = 0; j < 4; j++) acc2[t][n][j] = 0.f;

        for (int c = 0; c < 4; c++) {
            __syncthreads();
            {
                const uint4* src = (const uint4*)&g_wt[3][c * 5120];
                uint4* dst = (uint4*)(smem8 + SB_H);
                for (int i = tid; i < 640; i += TPB) dst[i] = src[i];
            }
            __syncthreads();
#pragma unroll
            for (int ks = 0; ks < 2; ks++) {
                const int kc = c * 2 + ks;
#pragma unroll
                for (int t = 0; t < 2; t++) {
                    const int it = wid + t * 16;
                    if (it >= 28) break;
                    const int mi = it % 7, ng = it / 7;
                    uint32_t aa = sb + QB + swz(mi * 16 + (lane & 15), (2 * kc + (lane >> 4)) << 4);
                    uint32_t ah[4], al[4];
                    LDSM4(ah[0], ah[1], ah[2], ah[3], aa);
                    LDSM4(al[0], al[1], al[2], al[3], aa + HILO);
                    uint32_t bH[4][2];
#pragma unroll
                    for (int tt = 0; tt < 2; tt++) {
                        const uint32_t ba = sb + SB_H +
                            (uint32_t)(((ng * 32 + tt * 16 + ((lane & 16) ? 8 : 0) + (lane & 7)) * STB
                                        + ks * 16 + ((lane & 8) ? 8 : 0)) << 1);
                        uint32_t r0, r1, r2, r3;
                        LDSM4(r0, r1, r2, r3, ba);
                        bH[2 * tt][0] = r0;     bH[2 * tt][1] = r1;
                        bH[2 * tt + 1][0] = r2; bH[2 * tt + 1][1] = r3;
                    }
#pragma unroll
                    for (int n = 0; n < 4; n++) {
                        MMA16816(acc2[t][n], ah, bH[n][0], bH[n][1]);
                        MMA16816(acc2[t][n], al, bH[n][0], bH[n][1]);
                    }
                }
            }
        }
        __syncthreads();
        // epilogue: mh (+bc) -> hi/lo tiles in KB (K/V tiles dead; lo lands in VB region)
#pragma unroll
        for (int t = 0; t < 2; t++) {
            const int it = wid + t * 16;
            if (it >= 28) break;
            const int mi = it % 7, ng = it / 7;
#pragma unroll
            for (int n = 0; n < 4; n++) {
                int row = mi * 16 + (lane >> 2);
                int col = ng * 32 + n * 8 + ((lane & 3) << 1);
                float b0 = sBc[col], b1 = sBc[col + 1];
                st_hilo(smem8 + KB, row, col, acc2[t][n][0] + b0, acc2[t][n][1] + b1);
                st_hilo(smem8 + KB, row + 8, col, acc2[t][n][2] + b0, acc2[t][n][3] + b1);
            }
        }
        __syncthreads();
    }

    // ---- score2 = mh @ nodes^T : A from KB tiles (hi/lo), B = nodes (hi chunks); f32 -> QB ----
    {
        float acc[2][4][4];
#pragma unroll
        for (int m = 0; m < 2; m++)
#pragma unroll
            for (int n = 0; n < 4; n++)
#pragma unroll
                for (int j = 0; j < 4; j++) acc[m][n][j] = 0.f;

        for (int c = 0; c < 4; c++) {
            __syncthreads();
            build_hi((__half*)(smem8 + SB_H), gN, EMBn, Nn, c * 32);
            __syncthreads();
#pragma unroll
            for (int ks = 0; ks < 2; ks++) {
                const int kc = c * 2 + ks;
                uint32_t aH[2][4], aL[2][4];
#pragma unroll
                for (int m = 0; m < 2; m++) {
                    // rows 112..127 read adjacent finite smem; those output rows are discarded
                    uint32_t aa = sb + KB + swz(wm * 32 + m * 16 + (lane & 15), (2 * kc + (lane >> 4)) << 4);
                    LDSM4(aH[m][0], aH[m][1], aH[m][2], aH[m][3], aa);
                    LDSM4(aL[m][0], aL[m][1], aL[m][2], aL[m][3], aa + HILO);
                }
                uint32_t bH[4][2];
#pragma unroll
                for (int t = 0; t < 2; t++) {
                    const uint32_t ba = sb + SB_H +
                        (uint32_t)(((wn * 32 + t * 16 + ((lane & 16) ? 8 : 0) + (lane & 7)) * STB
                                    + ks * 16 + ((lane & 8) ? 8 : 0)) << 1);
                    uint32_t r0, r1, r2, r3;
                    LDSM4(r0, r1, r2, r3, ba);
                    bH[2 * t][0] = r0;     bH[2 * t][1] = r1;
                    bH[2 * t + 1][0] = r2; bH[2 * t + 1][1] = r3;
                }
#pragma unroll
                for (int m = 0; m < 2; m++)
#pragma unroll
                    for (int n = 0; n < 4; n++) {
                        MMA16816(acc[m][n], aH[m], bH[n][0], bH[n][1]);
                        MMA16816(acc[m][n], aL[m], bH[n][0], bH[n][1]);
                    }
            }
        }
        __syncthreads();
        float* SCp = (float*)(smem8 + QB);   // QB region is dead after mh GEMM
#pragma unroll
        for (int m = 0; m < 2; m++)
#pragma unroll
            for (int n = 0; n < 4; n++) {
                int row = wm * 32 + m * 16 + (lane >> 2);
                int col = wn * 32 + n * 8 + ((lane & 3) << 1);
                if (row < Pn)
                    *(float2*)&SCp[row * LDSR + col] = make_float2(acc[m][n][0], acc[m][n][1]);
                if (row + 8 < Pn)
                    *(float2*)&SCp[(row + 8) * LDSR + col] = make_float2(acc[m][n][2], acc[m][n][3]);
            }
        __syncthreads();
    }

    // ---- final: clip*tanh(score2/sqrt(128)) + mask; softmax; store ----
    const float INV_SQRT_EMB = 0.08838834764831843f;
    const float* SCp = (const float*)(smem8 + QB);
    float* gOut = out + (size_t)b * Pn * Nn;
    for (int pi = wid; pi < Pn / 2; pi += 16) {
        const int p0 = 2 * pi, p1 = p0 + 1;
        float s0[4], s1[4];
        int nn[4];
#pragma unroll
        for (int j = 0; j < 4; j++) {
            int n = lane + 32 * j;
            nn[j] = n;
            if (n < Nn) {
                float m0 = __half2float(*(__half*)(smem8 + MK + (p0 * MKW + n) * 2));
                float m1 = __half2float(*(__half*)(smem8 + MK + (p1 * MKW + n) * 2));
                s0[j] = tanh10(SCp[p0 * LDSR + n] * INV_SQRT_EMB) + m0;
                s1[j] = tanh10(SCp[p1 * LDSR + n] * INV_SQRT_EMB) + m1;
            } else { s0[j] = -INFINITY; s1[j] = -INFINITY; }
        }
        float mx0 = fmaxf(fmaxf(s0[0], s0[1]), fmaxf(s0[2], s0[3]));
        float mx1 = fmaxf(fmaxf(s1[0], s1[1]), fmaxf(s1[2], s1[3]));
#pragma unroll
        for (int off = 16; off; off >>= 1) {
            mx0 = fmaxf(mx0, __shfl_xor_sync(0xffffffffu, mx0, off));
            mx1 = fmaxf(mx1, __shfl_xor_sync(0xffffffffu, mx1, off));
        }
        float w0[4], w1[4], sum0 = 0.f, sum1 = 0.f;
#pragma unroll
        for (int j = 0; j < 4; j++) {
            w0[j] = __expf(s0[j] - mx0); sum0 += w0[j];
            w1[j] = __expf(s1[j] - mx1); sum1 += w1[j];
        }
#pragma unroll
        for (int off = 16; off; off >>= 1) {
            sum0 += __shfl_xor_sync(0xffffffffu, sum0, off);
            sum1 += __shfl_xor_sync(0xffffffffu, sum1, off);
        }
        const float i0 = 1.f / sum0, i1 = 1.f / sum1;
#pragma unroll
        for (int j = 0; j < 4; j++) {
            if (nn[j] < Nn) {
                gOut[p0 * Nn + nn[j]] = w0[j] * i0;
                gOut[p1 * Nn + nn[j]] = w1[j] * i1;
            }
        }
    }
}

extern "C" void kernel_launch(void* const* d_in, const int* in_sizes, int n_in,
                              void* d_out, int out_size) {
    const float* eln   = (const float*)d_in[0];
    const float* load_ = (const float*)d_in[1];
    const float* time_ = (const float*)d_in[2];
    const float* len_  = (const float*)d_in[3];
    const float* ropen = (const float*)d_in[4];
    const float* mask  = (const float*)d_in[5];
    const float* nodes = (const float*)d_in[6];
    const float* Wq    = (const float*)d_in[7];
    const float* Wk    = (const float*)d_in[8];
    const float* Wv    = (const float*)d_in[9];
    const float* Wc    = (const float*)d_in[10];
    const float* bc    = (const float*)d_in[11];
    float* out = (float*)d_out;

    prep_weights<<<4, 256>>>(Wq, Wk, Wv, Wc);
    cudaFuncSetAttribute(vrp_decoder_kernel,
                         cudaFuncAttributeMaxDynamicSharedMemorySize, SMEM_TOTAL);
    vrp_decoder_kernel<<<Bn, TPB, SMEM_TOTAL>>>(
        eln, load_, time_, len_, ropen, mask, nodes, bc, out);
}

// round 14
// speedup vs baseline: 2.6306x; 1.1873x over previous
#include <cuda_runtime.h>
#include <cuda_fp16.h>
#include <cstdint>

#define TPB 512
static constexpr int Bn = 1024, Pn = 100, Nn = 101, EMBn = 128;
static constexpr int Hn = 8, DKn = 16;

static constexpr int STB = 40;       // fp16 row stride inside chunk tiles
static constexpr int MKW = 112;      // mask row width (covers attention reads up to col 110)
// ---- smem byte map ----
// Tiles: swizzled fp16 (hi only), 112 rows x 128 cols = 28672B each.
static constexpr int QB = 0;              // Q -> O tiles
static constexpr int KB = 28672;          // K tiles -> mh tiles
static constexpr int VB = 57344;          // V tiles
static constexpr int SC = 57344;          // score2 f32 [100][132] (V dead by then) -> ends 110144
static constexpr int SA  = 110592;        // A chunk (10240B)
static constexpr int SB  = 120832;        // B chunk (10240B)
static constexpr int SB2 = 131072;        // second B chunk for fused KV (10240B)
static constexpr int MK  = 141312;        // mask fp16 [100][112] = 22400B
static constexpr int OFF_EX  = 163712;    // extras [100][4] f32
static constexpr int OFF_WQ4 = 165312;    // Wq rows 128..131 [4][128] f32
static constexpr int OFF_BC  = 167360;    // bc [128] f32
static constexpr int SMEM_TOTAL = 167872;
static constexpr int LDSR = 132;          // f32 row stride for scores buffer

// ---------------- prep: weights -> chunk-blocked fp16, B^T layout ----
__device__ __half g_wt[4][20480];         // 4 chunks x 5120 halfs
__device__ float g_wq4[512];

__global__ void prep_weights(const float* __restrict__ Wq, const float* __restrict__ Wk,
                             const float* __restrict__ Wv, const float* __restrict__ Wc)
{
    const int w = blockIdx.x;
    const float* W = (w == 0) ? Wq : (w == 1) ? Wk : (w == 2) ? Wv : Wc;
    for (int idx = threadIdx.x; idx < 128 * 128; idx += blockDim.x) {
        int n = idx >> 7, k = idx & 127;
        g_wt[w][(k >> 5) * 5120 + n * STB + (k & 31)] = __float2half(W[k * 128 + n]);
    }
    if (w == 0) {
        for (int i = threadIdx.x; i < 512; i += blockDim.x)
            g_wq4[i] = Wq[128 * 128 + i];
    }
}

// ---------------- device helpers ----------------
__device__ __forceinline__ uint32_t smem_u32(const void* p) {
    uint32_t a;
    asm("{ .reg .u64 t; cvta.to.shared.u64 t, %1; cvt.u32.u64 %0, t; }" : "=r"(a) : "l"(p));
    return a;
}
__device__ __forceinline__ float tanh10(float x) {
    x = fminf(fmaxf(x, -20.f), 20.f);
    float t = __expf(2.f * x);
    return 10.f * (t - 1.f) / (t + 1.f);
}
// swizzled byte offset within a tile: row r (0..111), byte col cb (0..255)
__device__ __forceinline__ uint32_t swz(int r, int cb) {
    return (uint32_t)(r * 256 + ((((cb >> 4) ^ (r & 7)) << 4) | (cb & 15)));
}

#define LDSM4(R0, R1, R2, R3, ADDR) \
    asm volatile("ldmatrix.sync.aligned.m8n8.x4.shared.b16 {%0,%1,%2,%3}, [%4];" \
        : "=r"(R0), "=r"(R1), "=r"(R2), "=r"(R3) : "r"(ADDR))
#define LDSM4T(R0, R1, R2, R3, ADDR) \
    asm volatile("ldmatrix.sync.aligned.m8n8.x4.trans.shared.b16 {%0,%1,%2,%3}, [%4];" \
        : "=r"(R0), "=r"(R1), "=r"(R2), "=r"(R3) : "r"(ADDR))
#define MMA16816(C, A, B0, B1) \
    asm volatile("mma.sync.aligned.m16n8k16.row.col.f32.f16.f16.f32 " \
        "{%0,%1,%2,%3}, {%4,%5,%6,%7}, {%8,%9}, {%0,%1,%2,%3};" \
        : "+f"((C)[0]), "+f"((C)[1]), "+f"((C)[2]), "+f"((C)[3]) \
        : "r"((A)[0]), "r"((A)[1]), "r"((A)[2]), "r"((A)[3]), "r"(B0), "r"(B1))

// write (v0,v1) as fp16 into a swizzled tile at (row r, fp16 col c)
__device__ __forceinline__ void st_hi(unsigned char* base, int r, int c, float v0, float v1) {
    *(__half2*)(base + swz(r, c * 2)) = __floats2half2_rn(v0, v1);
}

// build one 128x32 fp16 chunk from f32 row-major source (zero-padded rows)
__device__ __forceinline__ void build_hi(
    __half* __restrict__ dst, const float* __restrict__ src,
    int ld, int nrows, int k0)
{
    for (int i = threadIdx.x; i < 1024; i += TPB) {
        int r = i >> 3, q = (i & 7) << 2;
        float4 v = make_float4(0.f, 0.f, 0.f, 0.f);
        if (r < nrows) v = *(const float4*)&src[(size_t)r * ld + k0 + q];
        int o = r * STB + q;
        *(__half2*)(dst + o)     = __floats2half2_rn(v.x, v.y);
        *(__half2*)(dst + o + 2) = __floats2half2_rn(v.z, v.w);
    }
}

// GEMM mainloop (1 product): A (f32 src -> fp16) @ B (prepped fp16 weight wsel).
__device__ __forceinline__ void gemm_core(
    unsigned char* smem8, uint32_t sb,
    const float* Asrc, int Ald, int Anrows, int wsel,
    float acc[2][4][4])
{
    const int tid = threadIdx.x, w = tid >> 5, lane = tid & 31;
    const int wm = w & 3, wn = w >> 2;
#pragma unroll
    for (int m = 0; m < 2; m++)
#pragma unroll
        for (int n = 0; n < 4; n++)
#pragma unroll
            for (int j = 0; j < 4; j++) acc[m][n][j] = 0.f;

    for (int c = 0; c < 4; c++) {
        __syncthreads();
        build_hi((__half*)(smem8 + SA), Asrc, Ald, Anrows, c * 32);
        {
            const uint4* src = (const uint4*)&g_wt[wsel][c * 5120];
            uint4* dst = (uint4*)(smem8 + SB);
            for (int i = tid; i < 640; i += TPB) dst[i] = src[i];
        }
        __syncthreads();

#pragma unroll
        for (int ks = 0; ks < 2; ks++) {
            const int kb = ks * 16;
            uint32_t aH[2][4];
#pragma unroll
            for (int m = 0; m < 2; m++) {
                uint32_t addr = sb + SA +
                    (uint32_t)(((wm * 32 + m * 16 + (lane & 15)) * STB
                                + kb + ((lane >> 4) << 3)) << 1);
                LDSM4(aH[m][0], aH[m][1], aH[m][2], aH[m][3], addr);
            }
            uint32_t bH[4][2];
#pragma unroll
            for (int t = 0; t < 2; t++) {
                const uint32_t ba = sb + SB +
                    (uint32_t)(((wn * 32 + t * 16 + ((lane & 16) ? 8 : 0) + (lane & 7)) * STB
                                + kb + ((lane & 8) ? 8 : 0)) << 1);
                uint32_t r0, r1, r2, r3;
                LDSM4(r0, r1, r2, r3, ba);
                bH[2 * t][0] = r0;     bH[2 * t][1] = r1;
                bH[2 * t + 1][0] = r2; bH[2 * t + 1][1] = r3;
            }
#pragma unroll
            for (int m = 0; m < 2; m++)
#pragma unroll
                for (int n = 0; n < 4; n++)
                    MMA16816(acc[m][n], aH[m], bH[n][0], bH[n][1]);
        }
    }
    __syncthreads();
}

extern __shared__ __align__(16) unsigned char smem8[];

__global__ __launch_bounds__(TPB, 1)
void vrp_decoder_kernel(
    const float* __restrict__ eln,   const float* __restrict__ load_,
    const float* __restrict__ time_, const float* __restrict__ len_,
    const float* __restrict__ ropen, const float* __restrict__ mask,
    const float* __restrict__ nodes, const float* __restrict__ bc,
    float* __restrict__ out)
{
    const int b = blockIdx.x;
    const int tid = threadIdx.x;
    const int wid = tid >> 5, lane = tid & 31;
    const int wm = wid & 3, wn = wid >> 2;
    const uint32_t sb = smem_u32(smem8);

    float* sEx  = (float*)(smem8 + OFF_EX);
    float* sWq4 = (float*)(smem8 + OFF_WQ4);
    float* sBc  = (float*)(smem8 + OFF_BC);

    const float* gE = eln + (size_t)b * Pn * EMBn;
    const float* gN = nodes + (size_t)b * Nn * EMBn;
    const float* gM = mask + (size_t)b * Pn * Nn;

    // ---- stage aux + mask -> smem fp16 [100][112] (cols >= 101 = -inf) ----
    for (int i = tid; i < 512; i += TPB) sWq4[i] = g_wq4[i];
    for (int i = tid; i < 128; i += TPB) sBc[i] = bc[i];
    for (int r = tid; r < Pn; r += TPB) {
        sEx[r * 4 + 0] = load_[b * Pn + r];
        sEx[r * 4 + 1] = time_[b * Pn + r];
        sEx[r * 4 + 2] = len_[b * Pn + r];
        sEx[r * 4 + 3] = ropen[b * Pn + r];
    }
    for (int i = tid; i < Pn * (MKW / 2); i += TPB) {
        int r = i / (MKW / 2), j = i % (MKW / 2);
        int n0 = 2 * j, n1 = n0 + 1;
        float a  = (n0 < Nn) ? gM[r * Nn + n0] : -INFINITY;
        float bb = (n1 < Nn) ? gM[r * Nn + n1] : -INFINITY;
        *(__half2*)(smem8 + MK + (r * MKW + n0) * 2) = __floats2half2_rn(a, bb);
    }

    // ---- Q = eln @ Wq[0:128] (+extras) -> QB ----
    {
        float acc[2][4][4];
        gemm_core(smem8, sb, gE, EMBn, Pn, 0, acc);
#pragma unroll
        for (int m = 0; m < 2; m++)
#pragma unroll
            for (int n = 0; n < 4; n++) {
                int row = wm * 32 + m * 16 + (lane >> 2);
                int col = wn * 32 + n * 8 + ((lane & 3) << 1);
#pragma unroll
                for (int hh = 0; hh < 2; hh++) {
                    int r = row + 8 * hh;
                    if (r >= 112) continue;
                    float v0 = acc[m][n][2 * hh], v1 = acc[m][n][2 * hh + 1];
                    if (r < Pn) {
                        float e0 = sEx[r * 4], e1 = sEx[r * 4 + 1], e2 = sEx[r * 4 + 2], e3 = sEx[r * 4 + 3];
                        v0 += e0 * sWq4[col] + e1 * sWq4[128 + col] + e2 * sWq4[256 + col] + e3 * sWq4[384 + col];
                        v1 += e0 * sWq4[col + 1] + e1 * sWq4[128 + col + 1] + e2 * sWq4[256 + col + 1] + e3 * sWq4[384 + col + 1];
                    }
                    st_hi(smem8 + QB, r, col, v0, v1);
                }
            }
        __syncthreads();
    }

    // ---- fused K,V = nodes @ Wk / Wv -> KB / VB (shared A chunks) ----
    {
        float accK[2][4][4], accV[2][4][4];
#pragma unroll
        for (int m = 0; m < 2; m++)
#pragma unroll
            for (int n = 0; n < 4; n++)
#pragma unroll
                for (int j = 0; j < 4; j++) { accK[m][n][j] = 0.f; accV[m][n][j] = 0.f; }

        for (int c = 0; c < 4; c++) {
            __syncthreads();
            build_hi((__half*)(smem8 + SA), gN, EMBn, Nn, c * 32);
            {
                const uint4* s1 = (const uint4*)&g_wt[1][c * 5120];
                const uint4* s2 = (const uint4*)&g_wt[2][c * 5120];
                uint4* d1 = (uint4*)(smem8 + SB);
                uint4* d2 = (uint4*)(smem8 + SB2);
                for (int i = tid; i < 640; i += TPB) { d1[i] = s1[i]; d2[i] = s2[i]; }
            }
            __syncthreads();
#pragma unroll
            for (int ks = 0; ks < 2; ks++) {
                const int kb = ks * 16;
                uint32_t aH[2][4];
#pragma unroll
                for (int m = 0; m < 2; m++) {
                    uint32_t addr = sb + SA +
                        (uint32_t)(((wm * 32 + m * 16 + (lane & 15)) * STB
                                    + kb + ((lane >> 4) << 3)) << 1);
                    LDSM4(aH[m][0], aH[m][1], aH[m][2], aH[m][3], addr);
                }
                const uint32_t brow = (uint32_t)(((wn * 32 + ((lane & 16) ? 8 : 0) + (lane & 7)) * STB
                                                 + kb + ((lane & 8) ? 8 : 0)) << 1);
                uint32_t bK[4][2], bV[4][2];
#pragma unroll
                for (int t = 0; t < 2; t++) {
                    uint32_t off = brow + (uint32_t)((t * 16 * STB) << 1);
                    uint32_t r0, r1, r2, r3;
                    LDSM4(r0, r1, r2, r3, sb + SB + off);
                    bK[2 * t][0] = r0;     bK[2 * t][1] = r1;
                    bK[2 * t + 1][0] = r2; bK[2 * t + 1][1] = r3;
                    LDSM4(r0, r1, r2, r3, sb + SB2 + off);
                    bV[2 * t][0] = r0;     bV[2 * t][1] = r1;
                    bV[2 * t + 1][0] = r2; bV[2 * t + 1][1] = r3;
                }
#pragma unroll
                for (int m = 0; m < 2; m++)
#pragma unroll
                    for (int n = 0; n < 4; n++) {
                        MMA16816(accK[m][n], aH[m], bK[n][0], bK[n][1]);
                        MMA16816(accV[m][n], aH[m], bV[n][0], bV[n][1]);
                    }
            }
        }
        __syncthreads();
#pragma unroll
        for (int m = 0; m < 2; m++)
#pragma unroll
            for (int n = 0; n < 4; n++) {
                int row = wm * 32 + m * 16 + (lane >> 2);
                int col = wn * 32 + n * 8 + ((lane & 3) << 1);
#pragma unroll
                for (int hh = 0; hh < 2; hh++) {
                    int r = row + 8 * hh;
                    if (r < 112) {
                        st_hi(smem8 + KB, r, col, accK[m][n][2 * hh], accK[m][n][2 * hh + 1]);
                        st_hi(smem8 + VB, r, col, accV[m][n][2 * hh], accV[m][n][2 * hh + 1]);
                    }
                }
            }
        __syncthreads();
    }

    // ---- attention: item = (m16-tile mi, head h), 56 items / 16 warps ----
    for (int it = wid; it < 56; it += 16) {
        const int mi = it % 7, h = it / 7;
        const int r0 = mi * 16;
        uint32_t qa = sb + QB + swz(r0 + (lane & 15), (2 * h + (lane >> 4)) << 4);
        uint32_t qh[4];
        LDSM4(qh[0], qh[1], qh[2], qh[3], qa);

        float sf[14][4];
#pragma unroll
        for (int nt2 = 0; nt2 < 7; nt2++) {
            uint32_t ka = sb + KB + swz((2 * nt2 + ((lane >> 4) & 1)) * 8 + (lane & 7),
                                        (2 * h + ((lane >> 3) & 1)) << 4);
            uint32_t kh[4];
            LDSM4(kh[0], kh[1], kh[2], kh[3], ka);
            float c0[4] = {0.f, 0.f, 0.f, 0.f}, c1[4] = {0.f, 0.f, 0.f, 0.f};
            MMA16816(c0, qh, kh[0], kh[1]);
            MMA16816(c1, qh, kh[2], kh[3]);
#pragma unroll
            for (int j = 0; j < 4; j++) { sf[2 * nt2][j] = c0[j]; sf[2 * nt2 + 1][j] = c1[j]; }
        }
        const int rr0 = r0 + (lane >> 2), rr1 = rr0 + 8;
#pragma unroll
        for (int nt = 0; nt < 14; nt++) {
            const int cc = nt * 8 + ((lane & 3) << 1);   // up to 110 < MKW
            float2 mA, mB;
            if (rr0 < Pn) mA = __half22float2(*(__half2*)(smem8 + MK + (rr0 * MKW + cc) * 2));
            else { mA.x = (cc < Nn) ? 0.f : -INFINITY; mA.y = (cc + 1 < Nn) ? 0.f : -INFINITY; }
            if (rr1 < Pn) mB = __half22float2(*(__half2*)(smem8 + MK + (rr1 * MKW + cc) * 2));
            else { mB.x = (cc < Nn) ? 0.f : -INFINITY; mB.y = (cc + 1 < Nn) ? 0.f : -INFINITY; }
            sf[nt][0] = sf[nt][0] * 0.25f + mA.x;
            sf[nt][1] = sf[nt][1] * 0.25f + mA.y;
            sf[nt][2] = sf[nt][2] * 0.25f + mB.x;
            sf[nt][3] = sf[nt][3] * 0.25f + mB.y;
        }
        float mx0 = -INFINITY, mx1 = -INFINITY;
#pragma unroll
        for (int nt = 0; nt < 14; nt++) {
            mx0 = fmaxf(mx0, fmaxf(sf[nt][0], sf[nt][1]));
            mx1 = fmaxf(mx1, fmaxf(sf[nt][2], sf[nt][3]));
        }
        mx0 = fmaxf(mx0, __shfl_xor_sync(0xffffffffu, mx0, 1));
        mx0 = fmaxf(mx0, __shfl_xor_sync(0xffffffffu, mx0, 2));
        mx1 = fmaxf(mx1, __shfl_xor_sync(0xffffffffu, mx1, 1));
        mx1 = fmaxf(mx1, __shfl_xor_sync(0xffffffffu, mx1, 2));
        float sum0 = 0.f, sum1 = 0.f;
#pragma unroll
        for (int nt = 0; nt < 14; nt++) {
            sf[nt][0] = __expf(sf[nt][0] - mx0); sum0 += sf[nt][0];
            sf[nt][1] = __expf(sf[nt][1] - mx0); sum0 += sf[nt][1];
            sf[nt][2] = __expf(sf[nt][2] - mx1); sum1 += sf[nt][2];
            sf[nt][3] = __expf(sf[nt][3] - mx1); sum1 += sf[nt][3];
        }
        sum0 += __shfl_xor_sync(0xffffffffu, sum0, 1);
        sum0 += __shfl_xor_sync(0xffffffffu, sum0, 2);
        sum1 += __shfl_xor_sync(0xffffffffu, sum1, 1);
        sum1 += __shfl_xor_sync(0xffffffffu, sum1, 2);
        const float inv0 = 1.f / sum0, inv1 = 1.f / sum1;

        // PV: 4 accumulator chains ([ng][kt-parity]); P and V fp16
        float accP[2][2][4];
#pragma unroll
        for (int g2 = 0; g2 < 2; g2++)
#pragma unroll
            for (int pr = 0; pr < 2; pr++)
#pragma unroll
                for (int j = 0; j < 4; j++) accP[g2][pr][j] = 0.f;
#pragma unroll
        for (int kt = 0; kt < 7; kt++) {
            const int pr = kt & 1;
            uint32_t aH[4];
            {
                __half2 h0 = __floats2half2_rn(sf[2 * kt][0] * inv0,     sf[2 * kt][1] * inv0);
                __half2 h1 = __floats2half2_rn(sf[2 * kt][2] * inv1,     sf[2 * kt][3] * inv1);
                __half2 h2 = __floats2half2_rn(sf[2 * kt + 1][0] * inv0, sf[2 * kt + 1][1] * inv0);
                __half2 h3 = __floats2half2_rn(sf[2 * kt + 1][2] * inv1, sf[2 * kt + 1][3] * inv1);
                aH[0] = *reinterpret_cast<uint32_t*>(&h0);
                aH[1] = *reinterpret_cast<uint32_t*>(&h1);
                aH[2] = *reinterpret_cast<uint32_t*>(&h2);
                aH[3] = *reinterpret_cast<uint32_t*>(&h3);
            }
            uint32_t va = sb + VB + swz(kt * 16 + (lane & 15), (2 * h + (lane >> 4)) << 4);
            uint32_t vh[4];
            LDSM4T(vh[0], vh[1], vh[2], vh[3], va);
            MMA16816(accP[0][pr], aH, vh[0], vh[1]);
            MMA16816(accP[1][pr], aH, vh[2], vh[3]);
        }
#pragma unroll
        for (int ng = 0; ng < 2; ng++) {
            int col = h * 16 + ng * 8 + ((lane & 3) << 1);
            st_hi(smem8 + QB, rr0, col, accP[ng][0][0] + accP[ng][1][0],
                                        accP[ng][0][1] + accP[ng][1][1]);
            st_hi(smem8 + QB, rr1, col, accP[ng][0][2] + accP[ng][1][2],
                                        accP[ng][0][3] + accP[ng][1][3]);
        }
    }
    __syncthreads();

    // ---- mh = O @ Wc + bc : A from QB tiles, B = Wc chunks; out -> KB tiles ----
    {
        float acc2[2][4][4];
#pragma unroll
        for (int t = 0; t < 2; t++)
#pragma unroll
            for (int n = 0; n < 4; n++)
#pragma unroll
                for (int j = 0; j < 4; j++) acc2[t][n][j] = 0.f;

        for (int c = 0; c < 4; c++) {
            __syncthreads();
            {
                const uint4* src = (const uint4*)&g_wt[3][c * 5120];
                uint4* dst = (uint4*)(smem8 + SB);
                for (int i = tid; i < 640; i += TPB) dst[i] = src[i];
            }
            __syncthreads();
#pragma unroll
            for (int ks = 0; ks < 2; ks++) {
                const int kc = c * 2 + ks;
#pragma unroll
                for (int t = 0; t < 2; t++) {
                    const int it = wid + t * 16;
                    if (it >= 28) break;
                    const int mi = it % 7, ng = it / 7;
                    uint32_t aa = sb + QB + swz(mi * 16 + (lane & 15), (2 * kc + (lane >> 4)) << 4);
                    uint32_t ah[4];
                    LDSM4(ah[0], ah[1], ah[2], ah[3], aa);
                    uint32_t bH[4][2];
#pragma unroll
                    for (int tt = 0; tt < 2; tt++) {
                        const uint32_t ba = sb + SB +
                            (uint32_t)(((ng * 32 + tt * 16 + ((lane & 16) ? 8 : 0) + (lane & 7)) * STB
                                        + ks * 16 + ((lane & 8) ? 8 : 0)) << 1);
                        uint32_t r0, r1, r2, r3;
                        LDSM4(r0, r1, r2, r3, ba);
                        bH[2 * tt][0] = r0;     bH[2 * tt][1] = r1;
                        bH[2 * tt + 1][0] = r2; bH[2 * tt + 1][1] = r3;
                    }
#pragma unroll
                    for (int n = 0; n < 4; n++)
                        MMA16816(acc2[t][n], ah, bH[n][0], bH[n][1]);
                }
            }
        }
        __syncthreads();
#pragma unroll
        for (int t = 0; t < 2; t++) {
            const int it = wid + t * 16;
            if (it >= 28) break;
            const int mi = it % 7, ng = it / 7;
#pragma unroll
            for (int n = 0; n < 4; n++) {
                int row = mi * 16 + (lane >> 2);
                int col = ng * 32 + n * 8 + ((lane & 3) << 1);
                float b0 = sBc[col], b1 = sBc[col + 1];
                st_hi(smem8 + KB, row, col, acc2[t][n][0] + b0, acc2[t][n][1] + b1);
                st_hi(smem8 + KB, row + 8, col, acc2[t][n][2] + b0, acc2[t][n][3] + b1);
            }
        }
        __syncthreads();
    }

    // ---- score2 = mh @ nodes^T : A from KB tiles, B = nodes chunks; f32 -> SC ----
    {
        float acc[2][4][4];
#pragma unroll
        for (int m = 0; m < 2; m++)
#pragma unroll
            for (int n = 0; n < 4; n++)
#pragma unroll
                for (int j = 0; j < 4; j++) acc[m][n][j] = 0.f;

        for (int c = 0; c < 4; c++) {
            __syncthreads();
            build_hi((__half*)(smem8 + SB), gN, EMBn, Nn, c * 32);
            __syncthreads();
#pragma unroll
            for (int ks = 0; ks < 2; ks++) {
                const int kc = c * 2 + ks;
                uint32_t aH[2][4];
#pragma unroll
                for (int m = 0; m < 2; m++) {
                    uint32_t aa = sb + KB + swz(wm * 32 + m * 16 + (lane & 15), (2 * kc + (lane >> 4)) << 4);
                    LDSM4(aH[m][0], aH[m][1], aH[m][2], aH[m][3], aa);
                }
                uint32_t bH[4][2];
#pragma unroll
                for (int t = 0; t < 2; t++) {
                    const uint32_t ba = sb + SB +
                        (uint32_t)(((wn * 32 + t * 16 + ((lane & 16) ? 8 : 0) + (lane & 7)) * STB
                                    + ks * 16 + ((lane & 8) ? 8 : 0)) << 1);
                    uint32_t r0, r1, r2, r3;
                    LDSM4(r0, r1, r2, r3, ba);
                    bH[2 * t][0] = r0;     bH[2 * t][1] = r1;
                    bH[2 * t + 1][0] = r2; bH[2 * t + 1][1] = r3;
                }
#pragma unroll
                for (int m = 0; m < 2; m++)
#pragma unroll
                    for (int n = 0; n < 4; n++)
                        MMA16816(acc[m][n], aH[m], bH[n][0], bH[n][1]);
            }
        }
        __syncthreads();
        float* SCp = (float*)(smem8 + SC);
#pragma unroll
        for (int m = 0; m < 2; m++)
#pragma unroll
            for (int n = 0; n < 4; n++) {
                int row = wm * 32 + m * 16 + (lane >> 2);
                int col = wn * 32 + n * 8 + ((lane & 3) << 1);
                if (row < Pn)
                    *(float2*)&SCp[row * LDSR + col] = make_float2(acc[m][n][0], acc[m][n][1]);
                if (row + 8 < Pn)
                    *(float2*)&SCp[(row + 8) * LDSR + col] = make_float2(acc[m][n][2], acc[m][n][3]);
            }
        __syncthreads();
    }

    // ---- final: clip*tanh(score2/sqrt(128)) + mask; softmax; store ----
    const float INV_SQRT_EMB = 0.08838834764831843f;
    const float* SCp = (const float*)(smem8 + SC);
    float* gOut = out + (size_t)b * Pn * Nn;
    for (int pi = wid; pi < Pn / 2; pi += 16) {
        const int p0 = 2 * pi, p1 = p0 + 1;
        float s0[4], s1[4];
        int nn[4];
#pragma unroll
        for (int j = 0; j < 4; j++) {
            int n = lane + 32 * j;
            nn[j] = n;
            if (n < Nn) {
                float m0 = __half2float(*(__half*)(smem8 + MK + (p0 * MKW + n) * 2));
                float m1 = __half2float(*(__half*)(smem8 + MK + (p1 * MKW + n) * 2));
                s0[j] = tanh10(SCp[p0 * LDSR + n] * INV_SQRT_EMB) + m0;
                s1[j] = tanh10(SCp[p1 * LDSR + n] * INV_SQRT_EMB) + m1;
            } else { s0[j] = -INFINITY; s1[j] = -INFINITY; }
        }
        float mx0 = fmaxf(fmaxf(s0[0], s0[1]), fmaxf(s0[2], s0[3]));
        float mx1 = fmaxf(fmaxf(s1[0], s1[1]), fmaxf(s1[2], s1[3]));
#pragma unroll
        for (int off = 16; off; off >>= 1) {
            mx0 = fmaxf(mx0, __shfl_xor_sync(0xffffffffu, mx0, off));
            mx1 = fmaxf(mx1, __shfl_xor_sync(0xffffffffu, mx1, off));
        }
        float w0[4], w1[4], sum0 = 0.f, sum1 = 0.f;
#pragma unroll
        for (int j = 0; j < 4; j++) {
            w0[j] = __expf(s0[j] - mx0); sum0 += w0[j];
            w1[j] = __expf(s1[j] - mx1); sum1 += w1[j];
        }
#pragma unroll
        for (int off = 16; off; off >>= 1) {
            sum0 += __shfl_xor_sync(0xffffffffu, sum0, off);
            sum1 += __shfl_xor_sync(0xffffffffu, sum1, off);
        }
        const float i0 = 1.f / sum0, i1 = 1.f / sum1;
#pragma unroll
        for (int j = 0; j < 4; j++) {
            if (nn[j] < Nn) {
                gOut[p0 * Nn + nn[j]] = w0[j] * i0;
                gOut[p1 * Nn + nn[j]] = w1[j] * i1;
            }
        }
    }
}

extern "C" void kernel_launch(void* const* d_in, const int* in_sizes, int n_in,
                              void* d_out, int out_size) {
    const float* eln   = (const float*)d_in[0];
    const float* load_ = (const float*)d_in[1];
    const float* time_ = (const float*)d_in[2];
    const float* len_  = (const float*)d_in[3];
    const float* ropen = (const float*)d_in[4];
    const float* mask  = (const float*)d_in[5];
    const float* nodes = (const float*)d_in[6];
    const float* Wq    = (const float*)d_in[7];
    const float* Wk    = (const float*)d_in[8];
    const float* Wv    = (const float*)d_in[9];
    const float* Wc    = (const float*)d_in[10];
    const float* bc    = (const float*)d_in[11];
    float* out = (float*)d_out;

    prep_weights<<<4, 256>>>(Wq, Wk, Wv, Wc);
    cudaFuncSetAttribute(vrp_decoder_kernel,
                         cudaFuncAttributeMaxDynamicSharedMemorySize, SMEM_TOTAL);
    vrp_decoder_kernel<<<Bn, TPB, SMEM_TOTAL>>>(
        eln, load_, time_, len_, ropen, mask, nodes, bc, out);
}

// round 15
// speedup vs baseline: 3.0560x; 1.1617x over previous
#include <cuda_runtime.h>
#include <cuda_fp16.h>
#include <cstdint>

#define TPB 512
static constexpr int Bn = 1024, Pn = 100, Nn = 101, EMBn = 128;
static constexpr int Hn = 8, DKn = 16;

static constexpr int MKW = 112;      // mask row width (covers attention reads up to col 110)
// ---- smem byte map ----
// Tiles: swizzled fp16, 112 rows x 128 cols = 28672B (weight tiles: 128 rows = 32768B)
static constexpr int QB = 0;              // Q -> O tiles; later: score2 f32 [100][132] from byte 0
static constexpr int KB = 28672;          // K tiles -> mh tiles
static constexpr int VB = 57344;          // V tiles
static constexpr int NT = 86016;          // nodes tile (A for K/V proj, B for score2)
static constexpr int S1 = 114688;         // eln A-tile, then Wv weight tile (32768)
static constexpr int S2 = 147456;         // weight tile slot (Wq/Wk/Wc) (32768)
static constexpr int MK = 180224;         // mask fp16 [100][112] = 22400B
static constexpr int OFF_EX  = 202624;    // extras [100][4] f32
static constexpr int OFF_WQ4 = 204224;    // Wq rows 128..131 [4][128] f32
static constexpr int OFF_BC  = 206272;    // bc [128] f32
static constexpr int SMEM_TOTAL = 206784;
static constexpr int LDSR = 132;          // f32 row stride for scores buffer

// swizzled byte offset within a tile: row r, byte col cb (0..255)
__device__ __forceinline__ uint32_t swz(int r, int cb) {
    return (uint32_t)(r * 256 + ((((cb >> 4) ^ (r & 7)) << 4) | (cb & 15)));
}

// ---------------- prep: weights -> full swizzled fp16 tiles (B^T layout, 128 rows) ----
__device__ __align__(16) unsigned char g_wtile[4][32768];
__device__ float g_wq4[512];

__global__ void prep_weights(const float* __restrict__ Wq, const float* __restrict__ Wk,
                             const float* __restrict__ Wv, const float* __restrict__ Wc)
{
    const int w = blockIdx.x;
    const float* W = (w == 0) ? Wq : (w == 1) ? Wk : (w == 2) ? Wv : Wc;
    for (int idx = threadIdx.x; idx < 128 * 128; idx += blockDim.x) {
        int n = idx >> 7, k = idx & 127;
        *(__half*)(g_wtile[w] + swz(n, k * 2)) = __float2half(W[k * 128 + n]);
    }
    if (w == 0) {
        for (int i = threadIdx.x; i < 512; i += blockDim.x)
            g_wq4[i] = Wq[128 * 128 + i];
    }
}

// ---------------- device helpers ----------------
__device__ __forceinline__ uint32_t smem_u32(const void* p) {
    uint32_t a;
    asm("{ .reg .u64 t; cvta.to.shared.u64 t, %1; cvt.u32.u64 %0, t; }" : "=r"(a) : "l"(p));
    return a;
}
__device__ __forceinline__ float tanh10(float x) {
    x = fminf(fmaxf(x, -20.f), 20.f);
    float t = __expf(2.f * x);
    return 10.f * (t - 1.f) / (t + 1.f);
}

#define LDSM4(R0, R1, R2, R3, ADDR) \
    asm volatile("ldmatrix.sync.aligned.m8n8.x4.shared.b16 {%0,%1,%2,%3}, [%4];" \
        : "=r"(R0), "=r"(R1), "=r"(R2), "=r"(R3) : "r"(ADDR))
#define LDSM4T(R0, R1, R2, R3, ADDR) \
    asm volatile("ldmatrix.sync.aligned.m8n8.x4.trans.shared.b16 {%0,%1,%2,%3}, [%4];" \
        : "=r"(R0), "=r"(R1), "=r"(R2), "=r"(R3) : "r"(ADDR))
#define MMA16816(C, A, B0, B1) \
    asm volatile("mma.sync.aligned.m16n8k16.row.col.f32.f16.f16.f32 " \
        "{%0,%1,%2,%3}, {%4,%5,%6,%7}, {%8,%9}, {%0,%1,%2,%3};" \
        : "+f"((C)[0]), "+f"((C)[1]), "+f"((C)[2]), "+f"((C)[3]) \
        : "r"((A)[0]), "r"((A)[1]), "r"((A)[2]), "r"((A)[3]), "r"(B0), "r"(B1))

__device__ __forceinline__ void st_hi(unsigned char* base, int r, int c, float v0, float v1) {
    *(__half2*)(base + swz(r, c * 2)) = __floats2half2_rn(v0, v1);
}

// build a 112-row swizzled fp16 tile from f32 row-major source (zero-padded rows)
__device__ __forceinline__ void build_tile(
    unsigned char* __restrict__ dst, const float* __restrict__ src, int ld, int nrows)
{
    for (int i = threadIdx.x; i < 112 * 32; i += TPB) {
        int r = i >> 5, q = (i & 31) << 2;       // fp16 cols q..q+3
        float4 v = make_float4(0.f, 0.f, 0.f, 0.f);
        if (r < nrows) v = *(const float4*)&src[(size_t)r * ld + q];
        uint32_t off = swz(r, q * 2);
        *(__half2*)(dst + off)     = __floats2half2_rn(v.x, v.y);
        *(__half2*)(dst + off + 4) = __floats2half2_rn(v.z, v.w);
    }
}

// copy a 32KB weight tile gmem -> smem
__device__ __forceinline__ void copy_wtile(unsigned char* dst, const unsigned char* src) {
    const uint4* s = (const uint4*)src;
    uint4* d = (uint4*)dst;
    for (int i = threadIdx.x; i < 2048; i += TPB) d[i] = s[i];
}

// full-K GEMM mainloop on swizzled tiles: C[wm rows 32][wn cols 32] += A @ B
__device__ __forceinline__ void gemm_tiles(
    uint32_t sb, uint32_t Aoff, uint32_t Boff, int wm, int wn, int lane,
    float acc[2][4][4])
{
#pragma unroll
    for (int m = 0; m < 2; m++)
#pragma unroll
        for (int n = 0; n < 4; n++)
#pragma unroll
            for (int j = 0; j < 4; j++) acc[m][n][j] = 0.f;
#pragma unroll
    for (int kc = 0; kc < 8; kc++) {
        uint32_t aH[2][4];
#pragma unroll
        for (int m = 0; m < 2; m++) {
            uint32_t aa = sb + Aoff + swz(wm * 32 + m * 16 + (lane & 15),
                                          (2 * kc + (lane >> 4)) << 4);
            LDSM4(aH[m][0], aH[m][1], aH[m][2], aH[m][3], aa);
        }
        uint32_t bH[4][2];
#pragma unroll
        for (int t = 0; t < 2; t++) {
            uint32_t ba = sb + Boff + swz(wn * 32 + t * 16 + ((lane & 16) ? 8 : 0) + (lane & 7),
                                          (2 * kc + ((lane & 8) ? 1 : 0)) << 4);
            uint32_t r0, r1, r2, r3;
            LDSM4(r0, r1, r2, r3, ba);
            bH[2 * t][0] = r0;     bH[2 * t][1] = r1;
            bH[2 * t + 1][0] = r2; bH[2 * t + 1][1] = r3;
        }
#pragma unroll
        for (int m = 0; m < 2; m++)
#pragma unroll
            for (int n = 0; n < 4; n++)
                MMA16816(acc[m][n], aH[m], bH[n][0], bH[n][1]);
    }
}

extern __shared__ __align__(16) unsigned char smem8[];

__global__ __launch_bounds__(TPB, 1)
void vrp_decoder_kernel(
    const float* __restrict__ eln,   const float* __restrict__ load_,
    const float* __restrict__ time_, const float* __restrict__ len_,
    const float* __restrict__ ropen, const float* __restrict__ mask,
    const float* __restrict__ nodes, const float* __restrict__ bc,
    float* __restrict__ out)
{
    const int b = blockIdx.x;
    const int tid = threadIdx.x;
    const int wid = tid >> 5, lane = tid & 31;
    const int wm = wid & 3, wn = wid >> 2;
    const uint32_t sb = smem_u32(smem8);

    float* sEx  = (float*)(smem8 + OFF_EX);
    float* sWq4 = (float*)(smem8 + OFF_WQ4);
    float* sBc  = (float*)(smem8 + OFF_BC);

    const float* gE = eln + (size_t)b * Pn * EMBn;
    const float* gN = nodes + (size_t)b * Nn * EMBn;
    const float* gM = mask + (size_t)b * Pn * Nn;

    // ---- stage aux + mask + A tiles + Wq tile ----
    for (int i = tid; i < 512; i += TPB) sWq4[i] = g_wq4[i];
    for (int i = tid; i < 128; i += TPB) sBc[i] = bc[i];
    for (int r = tid; r < Pn; r += TPB) {
        sEx[r * 4 + 0] = load_[b * Pn + r];
        sEx[r * 4 + 1] = time_[b * Pn + r];
        sEx[r * 4 + 2] = len_[b * Pn + r];
        sEx[r * 4 + 3] = ropen[b * Pn + r];
    }
    for (int i = tid; i < Pn * (MKW / 2); i += TPB) {
        int r = i / (MKW / 2), j = i % (MKW / 2);
        int n0 = 2 * j, n1 = n0 + 1;
        float a  = (n0 < Nn) ? gM[r * Nn + n0] : -INFINITY;
        float bb = (n1 < Nn) ? gM[r * Nn + n1] : -INFINITY;
        *(__half2*)(smem8 + MK + (r * MKW + n0) * 2) = __floats2half2_rn(a, bb);
    }
    build_tile(smem8 + S1, gE, EMBn, Pn);   // eln A-tile
    build_tile(smem8 + NT, gN, EMBn, Nn);   // nodes tile (KV A; score2 B)
    copy_wtile(smem8 + S2, g_wtile[0]);     // Wq
    __syncthreads();

    // ---- Q = eln @ Wq[0:128] (+extras) -> QB ----
    {
        float acc[2][4][4];
        gemm_tiles(sb, S1, S2, wm, wn, lane, acc);
#pragma unroll
        for (int m = 0; m < 2; m++)
#pragma unroll
            for (int n = 0; n < 4; n++) {
                int row = wm * 32 + m * 16 + (lane >> 2);
                int col = wn * 32 + n * 8 + ((lane & 3) << 1);
#pragma unroll
                for (int hh = 0; hh < 2; hh++) {
                    int r = row + 8 * hh;
                    if (r >= 112) continue;
                    float v0 = acc[m][n][2 * hh], v1 = acc[m][n][2 * hh + 1];
                    if (r < Pn) {
                        float e0 = sEx[r * 4], e1 = sEx[r * 4 + 1], e2 = sEx[r * 4 + 2], e3 = sEx[r * 4 + 3];
                        v0 += e0 * sWq4[col] + e1 * sWq4[128 + col] + e2 * sWq4[256 + col] + e3 * sWq4[384 + col];
                        v1 += e0 * sWq4[col + 1] + e1 * sWq4[128 + col + 1] + e2 * sWq4[256 + col + 1] + e3 * sWq4[384 + col + 1];
                    }
                    st_hi(smem8 + QB, r, col, v0, v1);
                }
            }
        __syncthreads();
    }

    // ---- fused K,V = nodes @ Wk / Wv -> KB / VB ----
    copy_wtile(smem8 + S2, g_wtile[1]);     // Wk
    copy_wtile(smem8 + S1, g_wtile[2]);     // Wv (eln tile dead)
    __syncthreads();
    {
        float accK[2][4][4], accV[2][4][4];
#pragma unroll
        for (int m = 0; m < 2; m++)
#pragma unroll
            for (int n = 0; n < 4; n++)
#pragma unroll
                for (int j = 0; j < 4; j++) { accK[m][n][j] = 0.f; accV[m][n][j] = 0.f; }
#pragma unroll
        for (int kc = 0; kc < 8; kc++) {
            uint32_t aH[2][4];
#pragma unroll
            for (int m = 0; m < 2; m++) {
                uint32_t aa = sb + NT + swz(wm * 32 + m * 16 + (lane & 15),
                                            (2 * kc + (lane >> 4)) << 4);
                LDSM4(aH[m][0], aH[m][1], aH[m][2], aH[m][3], aa);
            }
            const uint32_t boff = swz(wn * 32 + ((lane & 16) ? 8 : 0) + (lane & 7),
                                      (2 * kc + ((lane & 8) ? 1 : 0)) << 4);
            uint32_t bK[4][2], bV[4][2];
#pragma unroll
            for (int t = 0; t < 2; t++) {
                const uint32_t radd = (uint32_t)(t * 16 * 256);   // +16 rows in tile
                uint32_t r0, r1, r2, r3;
                LDSM4(r0, r1, r2, r3, sb + S2 + boff + radd);
                bK[2 * t][0] = r0;     bK[2 * t][1] = r1;
                bK[2 * t + 1][0] = r2; bK[2 * t + 1][1] = r3;
                LDSM4(r0, r1, r2, r3, sb + S1 + boff + radd);
                bV[2 * t][0] = r0;     bV[2 * t][1] = r1;
                bV[2 * t + 1][0] = r2; bV[2 * t + 1][1] = r3;
            }
#pragma unroll
            for (int m = 0; m < 2; m++)
#pragma unroll
                for (int n = 0; n < 4; n++) {
                    MMA16816(accK[m][n], aH[m], bK[n][0], bK[n][1]);
                    MMA16816(accV[m][n], aH[m], bV[n][0], bV[n][1]);
                }
        }
#pragma unroll
        for (int m = 0; m < 2; m++)
#pragma unroll
            for (int n = 0; n < 4; n++) {
                int row = wm * 32 + m * 16 + (lane >> 2);
                int col = wn * 32 + n * 8 + ((lane & 3) << 1);
#pragma unroll
                for (int hh = 0; hh < 2; hh++) {
                    int r = row + 8 * hh;
                    if (r < 112) {
                        st_hi(smem8 + KB, r, col, accK[m][n][2 * hh], accK[m][n][2 * hh + 1]);
                        st_hi(smem8 + VB, r, col, accV[m][n][2 * hh], accV[m][n][2 * hh + 1]);
                    }
                }
            }
        __syncthreads();
    }

    // ---- attention: item = (m16-tile mi, head h), 56 items / 16 warps ----
    for (int it = wid; it < 56; it += 16) {
        const int mi = it % 7, h = it / 7;
        const int r0 = mi * 16;
        uint32_t qa = sb + QB + swz(r0 + (lane & 15), (2 * h + (lane >> 4)) << 4);
        uint32_t qh[4];
        LDSM4(qh[0], qh[1], qh[2], qh[3], qa);

        float sf[14][4];
#pragma unroll
        for (int nt2 = 0; nt2 < 7; nt2++) {
            uint32_t ka = sb + KB + swz((2 * nt2 + ((lane >> 4) & 1)) * 8 + (lane & 7),
                                        (2 * h + ((lane >> 3) & 1)) << 4);
            uint32_t kh[4];
            LDSM4(kh[0], kh[1], kh[2], kh[3], ka);
            float c0[4] = {0.f, 0.f, 0.f, 0.f}, c1[4] = {0.f, 0.f, 0.f, 0.f};
            MMA16816(c0, qh, kh[0], kh[1]);
            MMA16816(c1, qh, kh[2], kh[3]);
#pragma unroll
            for (int j = 0; j < 4; j++) { sf[2 * nt2][j] = c0[j]; sf[2 * nt2 + 1][j] = c1[j]; }
        }
        const int rr0 = r0 + (lane >> 2), rr1 = rr0 + 8;
#pragma unroll
        for (int nt = 0; nt < 14; nt++) {
            const int cc = nt * 8 + ((lane & 3) << 1);   // up to 110 < MKW
            float2 mA, mB;
            if (rr0 < Pn) mA = __half22float2(*(__half2*)(smem8 + MK + (rr0 * MKW + cc) * 2));
            else { mA.x = (cc < Nn) ? 0.f : -INFINITY; mA.y = (cc + 1 < Nn) ? 0.f : -INFINITY; }
            if (rr1 < Pn) mB = __half22float2(*(__half2*)(smem8 + MK + (rr1 * MKW + cc) * 2));
            else { mB.x = (cc < Nn) ? 0.f : -INFINITY; mB.y = (cc + 1 < Nn) ? 0.f : -INFINITY; }
            sf[nt][0] = sf[nt][0] * 0.25f + mA.x;
            sf[nt][1] = sf[nt][1] * 0.25f + mA.y;
            sf[nt][2] = sf[nt][2] * 0.25f + mB.x;
            sf[nt][3] = sf[nt][3] * 0.25f + mB.y;
        }
        float mx0 = -INFINITY, mx1 = -INFINITY;
#pragma unroll
        for (int nt = 0; nt < 14; nt++) {
            mx0 = fmaxf(mx0, fmaxf(sf[nt][0], sf[nt][1]));
            mx1 = fmaxf(mx1, fmaxf(sf[nt][2], sf[nt][3]));
        }
        mx0 = fmaxf(mx0, __shfl_xor_sync(0xffffffffu, mx0, 1));
        mx0 = fmaxf(mx0, __shfl_xor_sync(0xffffffffu, mx0, 2));
        mx1 = fmaxf(mx1, __shfl_xor_sync(0xffffffffu, mx1, 1));
        mx1 = fmaxf(mx1, __shfl_xor_sync(0xffffffffu, mx1, 2));
        float sum0 = 0.f, sum1 = 0.f;
#pragma unroll
        for (int nt = 0; nt < 14; nt++) {
            sf[nt][0] = __expf(sf[nt][0] - mx0); sum0 += sf[nt][0];
            sf[nt][1] = __expf(sf[nt][1] - mx0); sum0 += sf[nt][1];
            sf[nt][2] = __expf(sf[nt][2] - mx1); sum1 += sf[nt][2];
            sf[nt][3] = __expf(sf[nt][3] - mx1); sum1 += sf[nt][3];
        }
        sum0 += __shfl_xor_sync(0xffffffffu, sum0, 1);
        sum0 += __shfl_xor_sync(0xffffffffu, sum0, 2);
        sum1 += __shfl_xor_sync(0xffffffffu, sum1, 1);
        sum1 += __shfl_xor_sync(0xffffffffu, sum1, 2);
        const float inv0 = 1.f / sum0, inv1 = 1.f / sum1;

        float accP[2][2][4];
#pragma unroll
        for (int g2 = 0; g2 < 2; g2++)
#pragma unroll
            for (int pr = 0; pr < 2; pr++)
#pragma unroll
                for (int j = 0; j < 4; j++) accP[g2][pr][j] = 0.f;
#pragma unroll
        for (int kt = 0; kt < 7; kt++) {
            const int pr = kt & 1;
            uint32_t aH[4];
            {
                __half2 h0 = __floats2half2_rn(sf[2 * kt][0] * inv0,     sf[2 * kt][1] * inv0);
                __half2 h1 = __floats2half2_rn(sf[2 * kt][2] * inv1,     sf[2 * kt][3] * inv1);
                __half2 h2 = __floats2half2_rn(sf[2 * kt + 1][0] * inv0, sf[2 * kt + 1][1] * inv0);
                __half2 h3 = __floats2half2_rn(sf[2 * kt + 1][2] * inv1, sf[2 * kt + 1][3] * inv1);
                aH[0] = *reinterpret_cast<uint32_t*>(&h0);
                aH[1] = *reinterpret_cast<uint32_t*>(&h1);
                aH[2] = *reinterpret_cast<uint32_t*>(&h2);
                aH[3] = *reinterpret_cast<uint32_t*>(&h3);
            }
            uint32_t va = sb + VB + swz(kt * 16 + (lane & 15), (2 * h + (lane >> 4)) << 4);
            uint32_t vh[4];
            LDSM4T(vh[0], vh[1], vh[2], vh[3], va);
            MMA16816(accP[0][pr], aH, vh[0], vh[1]);
            MMA16816(accP[1][pr], aH, vh[2], vh[3]);
        }
#pragma unroll
        for (int ng = 0; ng < 2; ng++) {
            int col = h * 16 + ng * 8 + ((lane & 3) << 1);
            st_hi(smem8 + QB, rr0, col, accP[ng][0][0] + accP[ng][1][0],
                                        accP[ng][0][1] + accP[ng][1][1]);
            st_hi(smem8 + QB, rr1, col, accP[ng][0][2] + accP[ng][1][2],
                                        accP[ng][0][3] + accP[ng][1][3]);
        }
    }
    __syncthreads();

    // ---- mh = O @ Wc + bc : A = QB tiles, B = Wc tile; out -> KB tiles ----
    copy_wtile(smem8 + S2, g_wtile[3]);     // Wc
    __syncthreads();
    {
        float acc[2][4][4];
        gemm_tiles(sb, QB, S2, wm, wn, lane, acc);
#pragma unroll
        for (int m = 0; m < 2; m++)
#pragma unroll
            for (int n = 0; n < 4; n++) {
                int row = wm * 32 + m * 16 + (lane >> 2);
                int col = wn * 32 + n * 8 + ((lane & 3) << 1);
                float b0 = sBc[col], b1 = sBc[col + 1];
#pragma unroll
                for (int hh = 0; hh < 2; hh++) {
                    int r = row + 8 * hh;
                    if (r < 112)
                        st_hi(smem8 + KB, r, col, acc[m][n][2 * hh] + b0, acc[m][n][2 * hh + 1] + b1);
                }
            }
        __syncthreads();
    }

    // ---- score2 = mh @ nodes^T : A = KB tiles, B = NT tile; f32 -> smem byte 0 ----
    {
        float acc[2][4][4];
        gemm_tiles(sb, KB, NT, wm, wn, lane, acc);
        __syncthreads();   // all KB/NT reads complete before SC overwrites QB/KB region
        float* SCp = (float*)smem8;
#pragma unroll
        for (int m = 0; m < 2; m++)
#pragma unroll
            for (int n = 0; n < 4; n++) {
                int row = wm * 32 + m * 16 + (lane >> 2);
                int col = wn * 32 + n * 8 + ((lane & 3) << 1);
                if (row < Pn)
                    *(float2*)&SCp[row * LDSR + col] = make_float2(acc[m][n][0], acc[m][n][1]);
                if (row + 8 < Pn)
                    *(float2*)&SCp[(row + 8) * LDSR + col] = make_float2(acc[m][n][2], acc[m][n][3]);
            }
        __syncthreads();
    }

    // ---- final: clip*tanh(score2/sqrt(128)) + mask; softmax; store ----
    const float INV_SQRT_EMB = 0.08838834764831843f;
    const float* SCp = (const float*)smem8;
    float* gOut = out + (size_t)b * Pn * Nn;
    for (int pi = wid; pi < Pn / 2; pi += 16) {
        const int p0 = 2 * pi, p1 = p0 + 1;
        float s0[4], s1[4];
        int nn[4];
#pragma unroll
        for (int j = 0; j < 4; j++) {
            int n = lane + 32 * j;
            nn[j] = n;
            if (n < Nn) {
                float m0 = __half2float(*(__half*)(smem8 + MK + (p0 * MKW + n) * 2));
                float m1 = __half2float(*(__half*)(smem8 + MK + (p1 * MKW + n) * 2));
                s0[j] = tanh10(SCp[p0 * LDSR + n] * INV_SQRT_EMB) + m0;
                s1[j] = tanh10(SCp[p1 * LDSR + n] * INV_SQRT_EMB) + m1;
            } else { s0[j] = -INFINITY; s1[j] = -INFINITY; }
        }
        float mx0 = fmaxf(fmaxf(s0[0], s0[1]), fmaxf(s0[2], s0[3]));
        float mx1 = fmaxf(fmaxf(s1[0], s1[1]), fmaxf(s1[2], s1[3]));
#pragma unroll
        for (int off = 16; off; off >>= 1) {
            mx0 = fmaxf(mx0, __shfl_xor_sync(0xffffffffu, mx0, off));
            mx1 = fmaxf(mx1, __shfl_xor_sync(0xffffffffu, mx1, off));
        }
        float w0[4], w1[4], sum0 = 0.f, sum1 = 0.f;
#pragma unroll
        for (int j = 0; j < 4; j++) {
            w0[j] = __expf(s0[j] - mx0); sum0 += w0[j];
            w1[j] = __expf(s1[j] - mx1); sum1 += w1[j];
        }
#pragma unroll
        for (int off = 16; off; off >>= 1) {
            sum0 += __shfl_xor_sync(0xffffffffu, sum0, off);
            sum1 += __shfl_xor_sync(0xffffffffu, sum1, off);
        }
        const float i0 = 1.f / sum0, i1 = 1.f / sum1;
#pragma unroll
        for (int j = 0; j < 4; j++) {
            if (nn[j] < Nn) {
                gOut[p0 * Nn + nn[j]] = w0[j] * i0;
                gOut[p1 * Nn + nn[j]] = w1[j] * i1;
            }
        }
    }
}

extern "C" void kernel_launch(void* const* d_in, const int* in_sizes, int n_in,
                              void* d_out, int out_size) {
    const float* eln   = (const float*)d_in[0];
    const float* load_ = (const float*)d_in[1];
    const float* time_ = (const float*)d_in[2];
    const float* len_  = (const float*)d_in[3];
    const float* ropen = (const float*)d_in[4];
    const float* mask  = (const float*)d_in[5];
    const float* nodes = (const float*)d_in[6];
    const float* Wq    = (const float*)d_in[7];
    const float* Wk    = (const float*)d_in[8];
    const float* Wv    = (const float*)d_in[9];
    const float* Wc    = (const float*)d_in[10];
    const float* bc    = (const float*)d_in[11];
    float* out = (float*)d_out;

    prep_weights<<<4, 256>>>(Wq, Wk, Wv, Wc);
    cudaFuncSetAttribute(vrp_decoder_kernel,
                         cudaFuncAttributeMaxDynamicSharedMemorySize, SMEM_TOTAL);
    vrp_decoder_kernel<<<Bn, TPB, SMEM_TOTAL>>>(
        eln, load_, time_, len_, ropen, mask, nodes, bc, out);
}

// round 16
// speedup vs baseline: 3.1542x; 1.0321x over previous
#include <cuda_runtime.h>
#include <cuda_fp16.h>
#include <cstdint>

#define TPB 512
static constexpr int Bn = 1024, Pn = 100, Nn = 101, EMBn = 128;
static constexpr int Hn = 8, DKn = 16;

static constexpr int MKW = 112;      // mask row width (covers attention reads up to col 110)
// ---- smem byte map ----
static constexpr int QB = 0;              // Q -> O tiles; later: score2 f32 [100][132] from byte 0
static constexpr int KB = 28672;          // K tiles -> mh tiles
static constexpr int VB = 57344;          // V tiles
static constexpr int NT = 86016;          // nodes tile (A for K/V proj, B for score2)
static constexpr int S1 = 114688;         // eln A-tile, then Wv weight tile (32768)
static constexpr int S2 = 147456;         // weight tile slot (Wq/Wk/Wc) (32768)
static constexpr int MK = 180224;         // mask fp16 [100][112] = 22400B
static constexpr int OFF_EX  = 202624;    // extras [100][4] f32
static constexpr int OFF_WQ4 = 204224;    // Wq rows 128..131 [4][128] f32
static constexpr int OFF_BC  = 206272;    // bc [128] f32
static constexpr int SMEM_TOTAL = 206784;
static constexpr int LDSR = 132;          // f32 row stride for scores buffer

// swizzled byte offset within a tile: row r, byte col cb (0..255)
__device__ __forceinline__ uint32_t swz(int r, int cb) {
    return (uint32_t)(r * 256 + ((((cb >> 4) ^ (r & 7)) << 4) | (cb & 15)));
}

// ---------------- prep: weights -> full swizzled fp16 tiles (B^T layout, 128 rows) ----
__device__ __align__(16) unsigned char g_wtile[4][32768];
__device__ float g_wq4[512];

__global__ void prep_weights(const float* __restrict__ Wq, const float* __restrict__ Wk,
                             const float* __restrict__ Wv, const float* __restrict__ Wc)
{
    const int w = blockIdx.x;
    const int nbase = blockIdx.y * 32;
    const float* W = (w == 0) ? Wq : (w == 1) ? Wk : (w == 2) ? Wv : Wc;
    for (int idx = threadIdx.x; idx < 32 * 128; idx += blockDim.x) {
        int n = nbase + (idx >> 7), k = idx & 127;
        *(__half*)(g_wtile[w] + swz(n, k * 2)) = __float2half(W[k * 128 + n]);
    }
    if (w == 0 && blockIdx.y == 0) {
        for (int i = threadIdx.x; i < 512; i += blockDim.x)
            g_wq4[i] = Wq[128 * 128 + i];
    }
}

// ---------------- device helpers ----------------
__device__ __forceinline__ uint32_t smem_u32(const void* p) {
    uint32_t a;
    asm("{ .reg .u64 t; cvta.to.shared.u64 t, %1; cvt.u32.u64 %0, t; }" : "=r"(a) : "l"(p));
    return a;
}
__device__ __forceinline__ float tanh10(float x) {
    x = fminf(fmaxf(x, -20.f), 20.f);
    float t = __expf(2.f * x);
    return 10.f * (t - 1.f) / (t + 1.f);
}

#define LDSM4(R0, R1, R2, R3, ADDR) \
    asm volatile("ldmatrix.sync.aligned.m8n8.x4.shared.b16 {%0,%1,%2,%3}, [%4];" \
        : "=r"(R0), "=r"(R1), "=r"(R2), "=r"(R3) : "r"(ADDR))
#define LDSM4T(R0, R1, R2, R3, ADDR) \
    asm volatile("ldmatrix.sync.aligned.m8n8.x4.trans.shared.b16 {%0,%1,%2,%3}, [%4];" \
        : "=r"(R0), "=r"(R1), "=r"(R2), "=r"(R3) : "r"(ADDR))
#define MMA16816(C, A, B0, B1) \
    asm volatile("mma.sync.aligned.m16n8k16.row.col.f32.f16.f16.f32 " \
        "{%0,%1,%2,%3}, {%4,%5,%6,%7}, {%8,%9}, {%0,%1,%2,%3};" \
        : "+f"((C)[0]), "+f"((C)[1]), "+f"((C)[2]), "+f"((C)[3]) \
        : "r"((A)[0]), "r"((A)[1]), "r"((A)[2]), "r"((A)[3]), "r"(B0), "r"(B1))

__device__ __forceinline__ void st_hi(unsigned char* base, int r, int c, float v0, float v1) {
    *(__half2*)(base + swz(r, c * 2)) = __floats2half2_rn(v0, v1);
}

// build a 112-row swizzled fp16 tile from f32 row-major source (zero-padded rows)
__device__ __forceinline__ void build_tile(
    unsigned char* __restrict__ dst, const float* __restrict__ src, int ld, int nrows)
{
    for (int i = threadIdx.x; i < 112 * 32; i += TPB) {
        int r = i >> 5, q = (i & 31) << 2;
        float4 v = make_float4(0.f, 0.f, 0.f, 0.f);
        if (r < nrows) v = *(const float4*)&src[(size_t)r * ld + q];
        uint32_t off = swz(r, q * 2);
        *(__half2*)(dst + off)     = __floats2half2_rn(v.x, v.y);
        *(__half2*)(dst + off + 4) = __floats2half2_rn(v.z, v.w);
    }
}

// copy a 32KB weight tile gmem -> smem (all threads)
__device__ __forceinline__ void copy_wtile(unsigned char* dst, const unsigned char* src) {
    const uint4* s = (const uint4*)src;
    uint4* d = (uint4*)dst;
    for (int i = threadIdx.x; i < 2048; i += TPB) d[i] = s[i];
}

// full-K GEMM mainloop on swizzled tiles: C[wm rows 32][wn cols 32] += A @ B
__device__ __forceinline__ void gemm_tiles(
    uint32_t sb, uint32_t Aoff, uint32_t Boff, int wm, int wn, int lane,
    float acc[2][4][4])
{
#pragma unroll
    for (int m = 0; m < 2; m++)
#pragma unroll
        for (int n = 0; n < 4; n++)
#pragma unroll
            for (int j = 0; j < 4; j++) acc[m][n][j] = 0.f;
#pragma unroll
    for (int kc = 0; kc < 8; kc++) {
        uint32_t aH[2][4];
#pragma unroll
        for (int m = 0; m < 2; m++) {
            uint32_t aa = sb + Aoff + swz(wm * 32 + m * 16 + (lane & 15),
                                          (2 * kc + (lane >> 4)) << 4);
            LDSM4(aH[m][0], aH[m][1], aH[m][2], aH[m][3], aa);
        }
        uint32_t bH[4][2];
#pragma unroll
        for (int t = 0; t < 2; t++) {
            uint32_t ba = sb + Boff + swz(wn * 32 + t * 16 + ((lane & 16) ? 8 : 0) + (lane & 7),
                                          (2 * kc + ((lane & 8) ? 1 : 0)) << 4);
            uint32_t r0, r1, r2, r3;
            LDSM4(r0, r1, r2, r3, ba);
            bH[2 * t][0] = r0;     bH[2 * t][1] = r1;
            bH[2 * t + 1][0] = r2; bH[2 * t + 1][1] = r3;
        }
#pragma unroll
        for (int m = 0; m < 2; m++)
#pragma unroll
            for (int n = 0; n < 4; n++)
                MMA16816(acc[m][n], aH[m], bH[n][0], bH[n][1]);
    }
}

extern __shared__ __align__(16) unsigned char smem8[];

__global__ __launch_bounds__(TPB, 1)
void vrp_decoder_kernel(
    const float* __restrict__ eln,   const float* __restrict__ load_,
    const float* __restrict__ time_, const float* __restrict__ len_,
    const float* __restrict__ ropen, const float* __restrict__ mask,
    const float* __restrict__ nodes, const float* __restrict__ bc,
    float* __restrict__ out)
{
    const int b = blockIdx.x;
    const int tid = threadIdx.x;
    const int wid = tid >> 5, lane = tid & 31;
    const int wm = wid & 3, wn = wid >> 2;
    const uint32_t sb = smem_u32(smem8);

    float* sEx  = (float*)(smem8 + OFF_EX);
    float* sWq4 = (float*)(smem8 + OFF_WQ4);
    float* sBc  = (float*)(smem8 + OFF_BC);

    const float* gE = eln + (size_t)b * Pn * EMBn;
    const float* gN = nodes + (size_t)b * Nn * EMBn;
    const float* gM = mask + (size_t)b * Pn * Nn;

    // ---- stage aux + mask + A tiles + Wq tile ----
    for (int i = tid; i < 512; i += TPB) sWq4[i] = g_wq4[i];
    for (int i = tid; i < 128; i += TPB) sBc[i] = bc[i];
    for (int r = tid; r < Pn; r += TPB) {
        sEx[r * 4 + 0] = load_[b * Pn + r];
        sEx[r * 4 + 1] = time_[b * Pn + r];
        sEx[r * 4 + 2] = len_[b * Pn + r];
        sEx[r * 4 + 3] = ropen[b * Pn + r];
    }
    for (int i = tid; i < Pn * (MKW / 2); i += TPB) {
        int r = i / (MKW / 2), j = i % (MKW / 2);
        int n0 = 2 * j, n1 = n0 + 1;
        float a  = (n0 < Nn) ? gM[r * Nn + n0] : -INFINITY;
        float bb = (n1 < Nn) ? gM[r * Nn + n1] : -INFINITY;
        *(__half2*)(smem8 + MK + (r * MKW + n0) * 2) = __floats2half2_rn(a, bb);
    }
    build_tile(smem8 + S1, gE, EMBn, Pn);   // eln A-tile
    build_tile(smem8 + NT, gN, EMBn, Nn);   // nodes tile (KV A; score2 B)
    copy_wtile(smem8 + S2, g_wtile[0]);     // Wq
    __syncthreads();

    // ---- Q = eln @ Wq[0:128] (+extras) -> QB ----
    {
        float acc[2][4][4];
        gemm_tiles(sb, S1, S2, wm, wn, lane, acc);
#pragma unroll
        for (int m = 0; m < 2; m++)
#pragma unroll
            for (int n = 0; n < 4; n++) {
                int row = wm * 32 + m * 16 + (lane >> 2);
                int col = wn * 32 + n * 8 + ((lane & 3) << 1);
#pragma unroll
                for (int hh = 0; hh < 2; hh++) {
                    int r = row + 8 * hh;
                    if (r >= 112) continue;
                    float v0 = acc[m][n][2 * hh], v1 = acc[m][n][2 * hh + 1];
                    if (r < Pn) {
                        float e0 = sEx[r * 4], e1 = sEx[r * 4 + 1], e2 = sEx[r * 4 + 2], e3 = sEx[r * 4 + 3];
                        v0 += e0 * sWq4[col] + e1 * sWq4[128 + col] + e2 * sWq4[256 + col] + e3 * sWq4[384 + col];
                        v1 += e0 * sWq4[col + 1] + e1 * sWq4[128 + col + 1] + e2 * sWq4[256 + col + 1] + e3 * sWq4[384 + col + 1];
                    }
                    st_hi(smem8 + QB, r, col, v0, v1);
                }
            }
        __syncthreads();
    }

    // ---- fused K,V = nodes @ Wk / Wv -> KB / VB ----
    copy_wtile(smem8 + S2, g_wtile[1]);     // Wk
    copy_wtile(smem8 + S1, g_wtile[2]);     // Wv (eln tile dead)
    __syncthreads();
    {
        float accK[2][4][4], accV[2][4][4];
#pragma unroll
        for (int m = 0; m < 2; m++)
#pragma unroll
            for (int n = 0; n < 4; n++)
#pragma unroll
                for (int j = 0; j < 4; j++) { accK[m][n][j] = 0.f; accV[m][n][j] = 0.f; }
#pragma unroll
        for (int kc = 0; kc < 8; kc++) {
            uint32_t aH[2][4];
#pragma unroll
            for (int m = 0; m < 2; m++) {
                uint32_t aa = sb + NT + swz(wm * 32 + m * 16 + (lane & 15),
                                            (2 * kc + (lane >> 4)) << 4);
                LDSM4(aH[m][0], aH[m][1], aH[m][2], aH[m][3], aa);
            }
            const uint32_t boff = swz(wn * 32 + ((lane & 16) ? 8 : 0) + (lane & 7),
                                      (2 * kc + ((lane & 8) ? 1 : 0)) << 4);
            uint32_t bK[4][2], bV[4][2];
#pragma unroll
            for (int t = 0; t < 2; t++) {
                const uint32_t radd = (uint32_t)(t * 16 * 256);
                uint32_t r0, r1, r2, r3;
                LDSM4(r0, r1, r2, r3, sb + S2 + boff + radd);
                bK[2 * t][0] = r0;     bK[2 * t][1] = r1;
                bK[2 * t + 1][0] = r2; bK[2 * t + 1][1] = r3;
                LDSM4(r0, r1, r2, r3, sb + S1 + boff + radd);
                bV[2 * t][0] = r0;     bV[2 * t][1] = r1;
                bV[2 * t + 1][0] = r2; bV[2 * t + 1][1] = r3;
            }
#pragma unroll
            for (int m = 0; m < 2; m++)
#pragma unroll
                for (int n = 0; n < 4; n++) {
                    MMA16816(accK[m][n], aH[m], bK[n][0], bK[n][1]);
                    MMA16816(accV[m][n], aH[m], bV[n][0], bV[n][1]);
                }
        }
#pragma unroll
        for (int m = 0; m < 2; m++)
#pragma unroll
            for (int n = 0; n < 4; n++) {
                int row = wm * 32 + m * 16 + (lane >> 2);
                int col = wn * 32 + n * 8 + ((lane & 3) << 1);
#pragma unroll
                for (int hh = 0; hh < 2; hh++) {
                    int r = row + 8 * hh;
                    if (r < 112) {
                        st_hi(smem8 + KB, r, col, accK[m][n][2 * hh], accK[m][n][2 * hh + 1]);
                        st_hi(smem8 + VB, r, col, accV[m][n][2 * hh], accV[m][n][2 * hh + 1]);
                    }
                }
            }
        __syncthreads();
    }

    // ---- attention: item = (m16-tile mi, head h), 56 items / 16 warps.
    // Warps 0-7 run 4 items; warps 8-15 run 3 items + copy the Wc tile into S2
    // (S2 is dead during attention) — fills the imbalance slack, removes a barrier pair.
    for (int it = wid; it < 56; it += 16) {
        const int mi = it % 7, h = it / 7;
        const int r0 = mi * 16;
        uint32_t qa = sb + QB + swz(r0 + (lane & 15), (2 * h + (lane >> 4)) << 4);
        uint32_t qh[4];
        LDSM4(qh[0], qh[1], qh[2], qh[3], qa);

        float sf[14][4];
#pragma unroll
        for (int nt2 = 0; nt2 < 7; nt2++) {
            uint32_t ka = sb + KB + swz((2 * nt2 + ((lane >> 4) & 1)) * 8 + (lane & 7),
                                        (2 * h + ((lane >> 3) & 1)) << 4);
            uint32_t kh[4];
            LDSM4(kh[0], kh[1], kh[2], kh[3], ka);
            float c0[4] = {0.f, 0.f, 0.f, 0.f}, c1[4] = {0.f, 0.f, 0.f, 0.f};
            MMA16816(c0, qh, kh[0], kh[1]);
            MMA16816(c1, qh, kh[2], kh[3]);
#pragma unroll
            for (int j = 0; j < 4; j++) { sf[2 * nt2][j] = c0[j]; sf[2 * nt2 + 1][j] = c1[j]; }
        }
        const int rr0 = r0 + (lane >> 2), rr1 = rr0 + 8;
#pragma unroll
        for (int nt = 0; nt < 14; nt++) {
            const int cc = nt * 8 + ((lane & 3) << 1);   // up to 110 < MKW
            float2 mA, mB;
            if (rr0 < Pn) mA = __half22float2(*(__half2*)(smem8 + MK + (rr0 * MKW + cc) * 2));
            else { mA.x = (cc < Nn) ? 0.f : -INFINITY; mA.y = (cc + 1 < Nn) ? 0.f : -INFINITY; }
            if (rr1 < Pn) mB = __half22float2(*(__half2*)(smem8 + MK + (rr1 * MKW + cc) * 2));
            else { mB.x = (cc < Nn) ? 0.f : -INFINITY; mB.y = (cc + 1 < Nn) ? 0.f : -INFINITY; }
            sf[nt][0] = sf[nt][0] * 0.25f + mA.x;
            sf[nt][1] = sf[nt][1] * 0.25f + mA.y;
            sf[nt][2] = sf[nt][2] * 0.25f + mB.x;
            sf[nt][3] = sf[nt][3] * 0.25f + mB.y;
        }
        float mx0 = -INFINITY, mx1 = -INFINITY;
#pragma unroll
        for (int nt = 0; nt < 14; nt++) {
            mx0 = fmaxf(mx0, fmaxf(sf[nt][0], sf[nt][1]));
            mx1 = fmaxf(mx1, fmaxf(sf[nt][2], sf[nt][3]));
        }
        mx0 = fmaxf(mx0, __shfl_xor_sync(0xffffffffu, mx0, 1));
        mx0 = fmaxf(mx0, __shfl_xor_sync(0xffffffffu, mx0, 2));
        mx1 = fmaxf(mx1, __shfl_xor_sync(0xffffffffu, mx1, 1));
        mx1 = fmaxf(mx1, __shfl_xor_sync(0xffffffffu, mx1, 2));
        float sum0 = 0.f, sum1 = 0.f;
#pragma unroll
        for (int nt = 0; nt < 14; nt++) {
            sf[nt][0] = __expf(sf[nt][0] - mx0); sum0 += sf[nt][0];
            sf[nt][1] = __expf(sf[nt][1] - mx0); sum0 += sf[nt][1];
            sf[nt][2] = __expf(sf[nt][2] - mx1); sum1 += sf[nt][2];
            sf[nt][3] = __expf(sf[nt][3] - mx1); sum1 += sf[nt][3];
        }
        sum0 += __shfl_xor_sync(0xffffffffu, sum0, 1);
        sum0 += __shfl_xor_sync(0xffffffffu, sum0, 2);
        sum1 += __shfl_xor_sync(0xffffffffu, sum1, 1);
        sum1 += __shfl_xor_sync(0xffffffffu, sum1, 2);
        const float inv0 = 1.f / sum0, inv1 = 1.f / sum1;

        float accP[2][2][4];
#pragma unroll
        for (int g2 = 0; g2 < 2; g2++)
#pragma unroll
            for (int pr = 0; pr < 2; pr++)
#pragma unroll
                for (int j = 0; j < 4; j++) accP[g2][pr][j] = 0.f;
#pragma unroll
        for (int kt = 0; kt < 7; kt++) {
            const int pr = kt & 1;
            uint32_t aH[4];
            {
                __half2 h0 = __floats2half2_rn(sf[2 * kt][0] * inv0,     sf[2 * kt][1] * inv0);
                __half2 h1 = __floats2half2_rn(sf[2 * kt][2] * inv1,     sf[2 * kt][3] * inv1);
                __half2 h2 = __floats2half2_rn(sf[2 * kt + 1][0] * inv0, sf[2 * kt + 1][1] * inv0);
                __half2 h3 = __floats2half2_rn(sf[2 * kt + 1][2] * inv1, sf[2 * kt + 1][3] * inv1);
                aH[0] = *reinterpret_cast<uint32_t*>(&h0);
                aH[1] = *reinterpret_cast<uint32_t*>(&h1);
                aH[2] = *reinterpret_cast<uint32_t*>(&h2);
                aH[3] = *reinterpret_cast<uint32_t*>(&h3);
            }
            uint32_t va = sb + VB + swz(kt * 16 + (lane & 15), (2 * h + (lane >> 4)) << 4);
            uint32_t vh[4];
            LDSM4T(vh[0], vh[1], vh[2], vh[3], va);
            MMA16816(accP[0][pr], aH, vh[0], vh[1]);
            MMA16816(accP[1][pr], aH, vh[2], vh[3]);
        }
#pragma unroll
        for (int ng = 0; ng < 2; ng++) {
            int col = h * 16 + ng * 8 + ((lane & 3) << 1);
            st_hi(smem8 + QB, rr0, col, accP[ng][0][0] + accP[ng][1][0],
                                        accP[ng][0][1] + accP[ng][1][1]);
            st_hi(smem8 + QB, rr1, col, accP[ng][0][2] + accP[ng][1][2],
                                        accP[ng][0][3] + accP[ng][1][3]);
        }
    }
    // warps 8-15 (3 items) copy Wc -> S2 in the slack
    if (wid >= 8) {
        const uint4* s = (const uint4*)g_wtile[3];
        uint4* d = (uint4*)(smem8 + S2);
        for (int i = (wid - 8) * 32 + lane; i < 2048; i += 256) d[i] = s[i];
    }
    __syncthreads();

    // ---- mh = O @ Wc + bc : A = QB tiles, B = Wc tile (already in S2); out -> KB tiles ----
    {
        float acc[2][4][4];
        gemm_tiles(sb, QB, S2, wm, wn, lane, acc);
#pragma unroll
        for (int m = 0; m < 2; m++)
#pragma unroll
            for (int n = 0; n < 4; n++) {
                int row = wm * 32 + m * 16 + (lane >> 2);
                int col = wn * 32 + n * 8 + ((lane & 3) << 1);
                float b0 = sBc[col], b1 = sBc[col + 1];
#pragma unroll
                for (int hh = 0; hh < 2; hh++) {
                    int r = row + 8 * hh;
                    if (r < 112)
                        st_hi(smem8 + KB, r, col, acc[m][n][2 * hh] + b0, acc[m][n][2 * hh + 1] + b1);
                }
            }
        __syncthreads();
    }

    // ---- score2 = mh @ nodes^T; epilogue folds clip*tanh + mask; f32 logits -> smem byte 0 ----
    const float INV_SQRT_EMB = 0.08838834764831843f;
    {
        float acc[2][4][4];
        gemm_tiles(sb, KB, NT, wm, wn, lane, acc);
        __syncthreads();   // all KB/NT reads complete before logits overwrite QB region
        float* SCp = (float*)smem8;
#pragma unroll
        for (int m = 0; m < 2; m++)
#pragma unroll
            for (int n = 0; n < 4; n++) {
                int row = wm * 32 + m * 16 + (lane >> 2);
                int col = wn * 32 + n * 8 + ((lane & 3) << 1);
#pragma unroll
                for (int hh = 0; hh < 2; hh++) {
                    int r = row + 8 * hh;
                    if (r >= Pn) continue;
                    float v0, v1;
                    if (col < Nn) {
                        float m0 = __half2float(*(__half*)(smem8 + MK + (r * MKW + col) * 2));
                        v0 = tanh10(acc[m][n][2 * hh] * INV_SQRT_EMB) + m0;
                    } else v0 = -INFINITY;
                    if (col + 1 < Nn) {
                        float m1 = __half2float(*(__half*)(smem8 + MK + (r * MKW + col + 1) * 2));
                        v1 = tanh10(acc[m][n][2 * hh + 1] * INV_SQRT_EMB) + m1;
                    } else v1 = -INFINITY;
                    *(float2*)&SCp[r * LDSR + col] = make_float2(v0, v1);
                }
            }
        __syncthreads();
    }

    // ---- final: softmax over precomputed logits; store ----
    const float* SCp = (const float*)smem8;
    float* gOut = out + (size_t)b * Pn * Nn;
    for (int pi = wid; pi < Pn / 2; pi += 16) {
        const int p0 = 2 * pi, p1 = p0 + 1;
        float s0[4], s1[4];
        int nn[4];
#pragma unroll
        for (int j = 0; j < 4; j++) {
            int n = lane + 32 * j;
            nn[j] = n;
            if (n < Nn) {
                s0[j] = SCp[p0 * LDSR + n];
                s1[j] = SCp[p1 * LDSR + n];
            } else { s0[j] = -INFINITY; s1[j] = -INFINITY; }
        }
        float mx0 = fmaxf(fmaxf(s0[0], s0[1]), fmaxf(s0[2], s0[3]));
        float mx1 = fmaxf(fmaxf(s1[0], s1[1]), fmaxf(s1[2], s1[3]));
#pragma unroll
        for (int off = 16; off; off >>= 1) {
            mx0 = fmaxf(mx0, __shfl_xor_sync(0xffffffffu, mx0, off));
            mx1 = fmaxf(mx1, __shfl_xor_sync(0xffffffffu, mx1, off));
        }
        float w0[4], w1[4], sum0 = 0.f, sum1 = 0.f;
#pragma unroll
        for (int j = 0; j < 4; j++) {
            w0[j] = __expf(s0[j] - mx0); sum0 += w0[j];
            w1[j] = __expf(s1[j] - mx1); sum1 += w1[j];
        }
#pragma unroll
        for (int off = 16; off; off >>= 1) {
            sum0 += __shfl_xor_sync(0xffffffffu, sum0, off);
            sum1 += __shfl_xor_sync(0xffffffffu, sum1, off);
        }
        const float i0 = 1.f / sum0, i1 = 1.f / sum1;
#pragma unroll
        for (int j = 0; j < 4; j++) {
            if (nn[j] < Nn) {
                gOut[p0 * Nn + nn[j]] = w0[j] * i0;
                gOut[p1 * Nn + nn[j]] = w1[j] * i1;
            }
        }
    }
}

extern "C" void kernel_launch(void* const* d_in, const int* in_sizes, int n_in,
                              void* d_out, int out_size) {
    const float* eln   = (const float*)d_in[0];
    const float* load_ = (const float*)d_in[1];
    const float* time_ = (const float*)d_in[2];
    const float* len_  = (const float*)d_in[3];
    const float* ropen = (const float*)d_in[4];
    const float* mask  = (const float*)d_in[5];
    const float* nodes = (const float*)d_in[6];
    const float* Wq    = (const float*)d_in[7];
    const float* Wk    = (const float*)d_in[8];
    const float* Wv    = (const float*)d_in[9];
    const float* Wc    = (const float*)d_in[10];
    const float* bc    = (const float*)d_in[11];
    float* out = (float*)d_out;

    prep_weights<<<dim3(4, 4), 256>>>(Wq, Wk, Wv, Wc);
    cudaFuncSetAttribute(vrp_decoder_kernel,
                         cudaFuncAttributeMaxDynamicSharedMemorySize, SMEM_TOTAL);
    vrp_decoder_kernel<<<Bn, TPB, SMEM_TOTAL>>>(
        eln, load_, time_, len_, ropen, mask, nodes, bc, out);
}

// round 17
// speedup vs baseline: 3.5544x; 1.1269x over previous
#include <cuda_runtime.h>
#include <cuda_fp16.h>
#include <cstdint>

#define TPB 1024
static constexpr int Bn = 1024, Pn = 100, Nn = 101, EMBn = 128;
static constexpr int Hn = 8, DKn = 16;

static constexpr int MKW = 112;      // mask row width
// ---- smem byte map ----
static constexpr int QB = 0;              // Q -> O tiles; later: score2 logits f32 from byte 0
static constexpr int KB = 28672;          // K tiles -> mh tiles
static constexpr int VB = 57344;          // V tiles
static constexpr int NT = 86016;          // nodes tile (A for K/V proj, B for score2)
static constexpr int S1 = 114688;         // eln A-tile, then Wv weight tile (32768)
static constexpr int S2 = 147456;         // weight tile slot (Wq/Wk/Wc) (32768)
static constexpr int MK = 180224;         // mask fp16 [100][112] = 22400B
static constexpr int OFF_EX  = 202624;    // extras [100][4] f32
static constexpr int OFF_WQ4 = 204224;    // Wq rows 128..131 [4][128] f32
static constexpr int OFF_BC  = 206272;    // bc [128] f32
static constexpr int SMEM_TOTAL = 206784;
static constexpr int LDSR = 132;          // f32 row stride for logits buffer

__device__ __forceinline__ uint32_t swz(int r, int cb) {
    return (uint32_t)(r * 256 + ((((cb >> 4) ^ (r & 7)) << 4) | (cb & 15)));
}

// ---------------- prep: weights -> full swizzled fp16 tiles (B^T layout) ----
__device__ __align__(16) unsigned char g_wtile[4][32768];
__device__ float g_wq4[512];

__global__ void prep_weights(const float* __restrict__ Wq, const float* __restrict__ Wk,
                             const float* __restrict__ Wv, const float* __restrict__ Wc)
{
    const int w = blockIdx.x;
    const int nbase = blockIdx.y * 32;
    const float* W = (w == 0) ? Wq : (w == 1) ? Wk : (w == 2) ? Wv : Wc;
    for (int idx = threadIdx.x; idx < 32 * 128; idx += blockDim.x) {
        int n = nbase + (idx >> 7), k = idx & 127;
        *(__half*)(g_wtile[w] + swz(n, k * 2)) = __float2half(W[k * 128 + n]);
    }
    if (w == 0 && blockIdx.y == 0) {
        for (int i = threadIdx.x; i < 512; i += blockDim.x)
            g_wq4[i] = Wq[128 * 128 + i];
    }
}

// ---------------- device helpers ----------------
__device__ __forceinline__ uint32_t smem_u32(const void* p) {
    uint32_t a;
    asm("{ .reg .u64 t; cvta.to.shared.u64 t, %1; cvt.u32.u64 %0, t; }" : "=r"(a) : "l"(p));
    return a;
}
__device__ __forceinline__ float tanh10(float x) {
    x = fminf(fmaxf(x, -20.f), 20.f);
    float t = __expf(2.f * x);
    return 10.f * (t - 1.f) / (t + 1.f);
}

#define LDSM4(R0, R1, R2, R3, ADDR) \
    asm volatile("ldmatrix.sync.aligned.m8n8.x4.shared.b16 {%0,%1,%2,%3}, [%4];" \
        : "=r"(R0), "=r"(R1), "=r"(R2), "=r"(R3) : "r"(ADDR))
#define LDSM4T(R0, R1, R2, R3, ADDR) \
    asm volatile("ldmatrix.sync.aligned.m8n8.x4.trans.shared.b16 {%0,%1,%2,%3}, [%4];" \
        : "=r"(R0), "=r"(R1), "=r"(R2), "=r"(R3) : "r"(ADDR))
#define MMA16816(C, A, B0, B1) \
    asm volatile("mma.sync.aligned.m16n8k16.row.col.f32.f16.f16.f32 " \
        "{%0,%1,%2,%3}, {%4,%5,%6,%7}, {%8,%9}, {%0,%1,%2,%3};" \
        : "+f"((C)[0]), "+f"((C)[1]), "+f"((C)[2]), "+f"((C)[3]) \
        : "r"((A)[0]), "r"((A)[1]), "r"((A)[2]), "r"((A)[3]), "r"(B0), "r"(B1))

__device__ __forceinline__ void st_hi(unsigned char* base, int r, int c, float v0, float v1) {
    *(__half2*)(base + swz(r, c * 2)) = __floats2half2_rn(v0, v1);
}

// build a 112-row swizzled fp16 tile from f32 row-major source (zero-padded rows)
__device__ __forceinline__ void build_tile(
    unsigned char* __restrict__ dst, const float* __restrict__ src, int ld, int nrows)
{
    for (int i = threadIdx.x; i < 112 * 32; i += TPB) {
        int r = i >> 5, q = (i & 31) << 2;
        float4 v = make_float4(0.f, 0.f, 0.f, 0.f);
        if (r < nrows) v = *(const float4*)&src[(size_t)r * ld + q];
        uint32_t off = swz(r, q * 2);
        *(__half2*)(dst + off)     = __floats2half2_rn(v.x, v.y);
        *(__half2*)(dst + off + 4) = __floats2half2_rn(v.z, v.w);
    }
}

__device__ __forceinline__ void copy_wtile(unsigned char* dst, const unsigned char* src) {
    const uint4* s = (const uint4*)src;
    uint4* d = (uint4*)dst;
    for (int i = threadIdx.x; i < 2048; i += TPB) d[i] = s[i];
}

// 32-warp full-K GEMM: warp (wm rows 16, wn cols 32); acc[4][4]
__device__ __forceinline__ void gemm_tiles(
    uint32_t sb, uint32_t Aoff, uint32_t Boff, int wm, int wn, int lane,
    float acc[4][4])
{
#pragma unroll
    for (int n = 0; n < 4; n++)
#pragma unroll
        for (int j = 0; j < 4; j++) acc[n][j] = 0.f;
#pragma unroll
    for (int kc = 0; kc < 8; kc++) {
        uint32_t aH[4];
        uint32_t aa = sb + Aoff + swz(wm * 16 + (lane & 15), (2 * kc + (lane >> 4)) << 4);
        LDSM4(aH[0], aH[1], aH[2], aH[3], aa);
        uint32_t bH[4][2];
#pragma unroll
        for (int t = 0; t < 2; t++) {
            uint32_t ba = sb + Boff + swz(wn * 32 + t * 16 + ((lane & 16) ? 8 : 0) + (lane & 7),
                                          (2 * kc + ((lane & 8) ? 1 : 0)) << 4);
            uint32_t r0, r1, r2, r3;
            LDSM4(r0, r1, r2, r3, ba);
            bH[2 * t][0] = r0;     bH[2 * t][1] = r1;
            bH[2 * t + 1][0] = r2; bH[2 * t + 1][1] = r3;
        }
#pragma unroll
        for (int n = 0; n < 4; n++)
            MMA16816(acc[n], aH, bH[n][0], bH[n][1]);
    }
}

extern __shared__ __align__(16) unsigned char smem8[];

__global__ __launch_bounds__(TPB, 1)
void vrp_decoder_kernel(
    const float* __restrict__ eln,   const float* __restrict__ load_,
    const float* __restrict__ time_, const float* __restrict__ len_,
    const float* __restrict__ ropen, const float* __restrict__ mask,
    const float* __restrict__ nodes, const float* __restrict__ bc,
    float* __restrict__ out)
{
    const int b = blockIdx.x;
    const int tid = threadIdx.x;
    const int wid = tid >> 5, lane = tid & 31;
    const int wm = wid & 7, wn = wid >> 3;
    const uint32_t sb = smem_u32(smem8);

    float* sEx  = (float*)(smem8 + OFF_EX);
    float* sWq4 = (float*)(smem8 + OFF_WQ4);
    float* sBc  = (float*)(smem8 + OFF_BC);

    const float* gE = eln + (size_t)b * Pn * EMBn;
    const float* gN = nodes + (size_t)b * Nn * EMBn;
    const float* gM = mask + (size_t)b * Pn * Nn;

    // ---- stage aux + mask + A tiles + Wq tile ----
    for (int i = tid; i < 512; i += TPB) sWq4[i] = g_wq4[i];
    for (int i = tid; i < 128; i += TPB) sBc[i] = bc[i];
    for (int r = tid; r < Pn; r += TPB) {
        sEx[r * 4 + 0] = load_[b * Pn + r];
        sEx[r * 4 + 1] = time_[b * Pn + r];
        sEx[r * 4 + 2] = len_[b * Pn + r];
        sEx[r * 4 + 3] = ropen[b * Pn + r];
    }
    for (int i = tid; i < Pn * (MKW / 2); i += TPB) {
        int r = i / (MKW / 2), j = i % (MKW / 2);
        int n0 = 2 * j, n1 = n0 + 1;
        float a  = (n0 < Nn) ? gM[r * Nn + n0] : -INFINITY;
        float bb = (n1 < Nn) ? gM[r * Nn + n1] : -INFINITY;
        *(__half2*)(smem8 + MK + (r * MKW + n0) * 2) = __floats2half2_rn(a, bb);
    }
    build_tile(smem8 + S1, gE, EMBn, Pn);
    build_tile(smem8 + NT, gN, EMBn, Nn);
    copy_wtile(smem8 + S2, g_wtile[0]);
    __syncthreads();

    // ---- Q = eln @ Wq[0:128] (+extras) -> QB ----
    {
        float acc[4][4];
        gemm_tiles(sb, S1, S2, wm, wn, lane, acc);
#pragma unroll
        for (int n = 0; n < 4; n++) {
            int row = wm * 16 + (lane >> 2);
            int col = wn * 32 + n * 8 + ((lane & 3) << 1);
#pragma unroll
            for (int hh = 0; hh < 2; hh++) {
                int r = row + 8 * hh;
                if (r >= 112) continue;
                float v0 = acc[n][2 * hh], v1 = acc[n][2 * hh + 1];
                if (r < Pn) {
                    float e0 = sEx[r * 4], e1 = sEx[r * 4 + 1], e2 = sEx[r * 4 + 2], e3 = sEx[r * 4 + 3];
                    v0 += e0 * sWq4[col] + e1 * sWq4[128 + col] + e2 * sWq4[256 + col] + e3 * sWq4[384 + col];
                    v1 += e0 * sWq4[col + 1] + e1 * sWq4[128 + col + 1] + e2 * sWq4[256 + col + 1] + e3 * sWq4[384 + col + 1];
                }
                st_hi(smem8 + QB, r, col, v0, v1);
            }
        }
        __syncthreads();
    }

    // ---- fused K,V = nodes @ Wk / Wv -> KB / VB ----
    copy_wtile(smem8 + S2, g_wtile[1]);
    copy_wtile(smem8 + S1, g_wtile[2]);
    __syncthreads();
    {
        float accK[4][4], accV[4][4];
#pragma unroll
        for (int n = 0; n < 4; n++)
#pragma unroll
            for (int j = 0; j < 4; j++) { accK[n][j] = 0.f; accV[n][j] = 0.f; }
#pragma unroll
        for (int kc = 0; kc < 8; kc++) {
            uint32_t aH[4];
            uint32_t aa = sb + NT + swz(wm * 16 + (lane & 15), (2 * kc + (lane >> 4)) << 4);
            LDSM4(aH[0], aH[1], aH[2], aH[3], aa);
            const uint32_t boff = swz(wn * 32 + ((lane & 16) ? 8 : 0) + (lane & 7),
                                      (2 * kc + ((lane & 8) ? 1 : 0)) << 4);
            uint32_t bK[4][2], bV[4][2];
#pragma unroll
            for (int t = 0; t < 2; t++) {
                const uint32_t radd = (uint32_t)(t * 16 * 256);
                uint32_t r0, r1, r2, r3;
                LDSM4(r0, r1, r2, r3, sb + S2 + boff + radd);
                bK[2 * t][0] = r0;     bK[2 * t][1] = r1;
                bK[2 * t + 1][0] = r2; bK[2 * t + 1][1] = r3;
                LDSM4(r0, r1, r2, r3, sb + S1 + boff + radd);
                bV[2 * t][0] = r0;     bV[2 * t][1] = r1;
                bV[2 * t + 1][0] = r2; bV[2 * t + 1][1] = r3;
            }
#pragma unroll
            for (int n = 0; n < 4; n++) {
                MMA16816(accK[n], aH, bK[n][0], bK[n][1]);
                MMA16816(accV[n], aH, bV[n][0], bV[n][1]);
            }
        }
#pragma unroll
        for (int n = 0; n < 4; n++) {
            int row = wm * 16 + (lane >> 2);
            int col = wn * 32 + n * 8 + ((lane & 3) << 1);
#pragma unroll
            for (int hh = 0; hh < 2; hh++) {
                int r = row + 8 * hh;
                if (r < 112) {
                    st_hi(smem8 + KB, r, col, accK[n][2 * hh], accK[n][2 * hh + 1]);
                    st_hi(smem8 + VB, r, col, accV[n][2 * hh], accV[n][2 * hh + 1]);
                }
            }
        }
        __syncthreads();
    }

    // ---- attention (flash-style online softmax): 56 items / 32 warps ----
    for (int it = wid; it < 56; it += 32) {
        const int mi = it % 7, h = it / 7;
        const int r0 = mi * 16;
        const int rr0 = r0 + (lane >> 2), rr1 = rr0 + 8;
        uint32_t qa = sb + QB + swz(r0 + (lane & 15), (2 * h + (lane >> 4)) << 4);
        uint32_t qh[4];
        LDSM4(qh[0], qh[1], qh[2], qh[3], qa);

        float m0 = -INFINITY, m1 = -INFINITY, l0 = 0.f, l1 = 0.f;
        float accP[2][4];
#pragma unroll
        for (int ng = 0; ng < 2; ng++)
#pragma unroll
            for (int j = 0; j < 4; j++) accP[ng][j] = 0.f;

#pragma unroll
        for (int nt2 = 0; nt2 < 7; nt2++) {
            // scores for 16 cols
            uint32_t ka = sb + KB + swz((2 * nt2 + ((lane >> 4) & 1)) * 8 + (lane & 7),
                                        (2 * h + ((lane >> 3) & 1)) << 4);
            uint32_t kh[4];
            LDSM4(kh[0], kh[1], kh[2], kh[3], ka);
            float c0[4] = {0.f, 0.f, 0.f, 0.f}, c1[4] = {0.f, 0.f, 0.f, 0.f};
            MMA16816(c0, qh, kh[0], kh[1]);
            MMA16816(c1, qh, kh[2], kh[3]);
            // mask + scale
            const int cc = nt2 * 16 + ((lane & 3) << 1);
            {
                float2 mA, mB;
                if (rr0 < Pn) mA = __half22float2(*(__half2*)(smem8 + MK + (rr0 * MKW + cc) * 2));
                else { mA.x = (cc < Nn) ? 0.f : -INFINITY; mA.y = (cc + 1 < Nn) ? 0.f : -INFINITY; }
                if (rr1 < Pn) mB = __half22float2(*(__half2*)(smem8 + MK + (rr1 * MKW + cc) * 2));
                else { mB.x = (cc < Nn) ? 0.f : -INFINITY; mB.y = (cc + 1 < Nn) ? 0.f : -INFINITY; }
                c0[0] = c0[0] * 0.25f + mA.x; c0[1] = c0[1] * 0.25f + mA.y;
                c0[2] = c0[2] * 0.25f + mB.x; c0[3] = c0[3] * 0.25f + mB.y;
            }
            {
                const int cd = cc + 8;
                float2 mA, mB;
                if (rr0 < Pn) mA = __half22float2(*(__half2*)(smem8 + MK + (rr0 * MKW + cd) * 2));
                else { mA.x = (cd < Nn) ? 0.f : -INFINITY; mA.y = (cd + 1 < Nn) ? 0.f : -INFINITY; }
                if (rr1 < Pn) mB = __half22float2(*(__half2*)(smem8 + MK + (rr1 * MKW + cd) * 2));
                else { mB.x = (cd < Nn) ? 0.f : -INFINITY; mB.y = (cd + 1 < Nn) ? 0.f : -INFINITY; }
                c1[0] = c1[0] * 0.25f + mA.x; c1[1] = c1[1] * 0.25f + mA.y;
                c1[2] = c1[2] * 0.25f + mB.x; c1[3] = c1[3] * 0.25f + mB.y;
            }
            // block max per row (quad reduce)
            float bm0 = fmaxf(fmaxf(c0[0], c0[1]), fmaxf(c1[0], c1[1]));
            float bm1 = fmaxf(fmaxf(c0[2], c0[3]), fmaxf(c1[2], c1[3]));
            bm0 = fmaxf(bm0, __shfl_xor_sync(0xffffffffu, bm0, 1));
            bm0 = fmaxf(bm0, __shfl_xor_sync(0xffffffffu, bm0, 2));
            bm1 = fmaxf(bm1, __shfl_xor_sync(0xffffffffu, bm1, 1));
            bm1 = fmaxf(bm1, __shfl_xor_sync(0xffffffffu, bm1, 2));
            const float m0n = fmaxf(m0, bm0), m1n = fmaxf(m1, bm1);
            const float sc0 = __expf(m0 - m0n), sc1 = __expf(m1 - m1n);
            // exponentials
            float e00 = __expf(c0[0] - m0n), e01 = __expf(c0[1] - m0n);
            float e02 = __expf(c0[2] - m1n), e03 = __expf(c0[3] - m1n);
            float e10 = __expf(c1[0] - m0n), e11 = __expf(c1[1] - m0n);
            float e12 = __expf(c1[2] - m1n), e13 = __expf(c1[3] - m1n);
            float bs0 = e00 + e01 + e10 + e11;
            float bs1 = e02 + e03 + e12 + e13;
            bs0 += __shfl_xor_sync(0xffffffffu, bs0, 1);
            bs0 += __shfl_xor_sync(0xffffffffu, bs0, 2);
            bs1 += __shfl_xor_sync(0xffffffffu, bs1, 1);
            bs1 += __shfl_xor_sync(0xffffffffu, bs1, 2);
            l0 = l0 * sc0 + bs0;
            l1 = l1 * sc1 + bs1;
            m0 = m0n; m1 = m1n;
            // rescale accumulators
#pragma unroll
            for (int ng = 0; ng < 2; ng++) {
                accP[ng][0] *= sc0; accP[ng][1] *= sc0;
                accP[ng][2] *= sc1; accP[ng][3] *= sc1;
            }
            // P fragment (fp16), V fragment, PV MMAs
            uint32_t aH[4];
            {
                __half2 h0 = __floats2half2_rn(e00, e01);
                __half2 h1 = __floats2half2_rn(e02, e03);
                __half2 h2 = __floats2half2_rn(e10, e11);
                __half2 h3 = __floats2half2_rn(e12, e13);
                aH[0] = *reinterpret_cast<uint32_t*>(&h0);
                aH[1] = *reinterpret_cast<uint32_t*>(&h1);
                aH[2] = *reinterpret_cast<uint32_t*>(&h2);
                aH[3] = *reinterpret_cast<uint32_t*>(&h3);
            }
            uint32_t va = sb + VB + swz(nt2 * 16 + (lane & 15), (2 * h + (lane >> 4)) << 4);
            uint32_t vh[4];
            LDSM4T(vh[0], vh[1], vh[2], vh[3], va);
            MMA16816(accP[0], aH, vh[0], vh[1]);
            MMA16816(accP[1], aH, vh[2], vh[3]);
        }
        const float inv0 = 1.f / l0, inv1 = 1.f / l1;
#pragma unroll
        for (int ng = 0; ng < 2; ng++) {
            int col = h * 16 + ng * 8 + ((lane & 3) << 1);
            st_hi(smem8 + QB, rr0, col, accP[ng][0] * inv0, accP[ng][1] * inv0);
            st_hi(smem8 + QB, rr1, col, accP[ng][2] * inv1, accP[ng][3] * inv1);
        }
    }
    // warps 24-31 (single attention item) copy Wc -> S2 in the slack
    if (wid >= 24) {
        const uint4* s = (const uint4*)g_wtile[3];
        uint4* d = (uint4*)(smem8 + S2);
        for (int i = (wid - 24) * 32 + lane; i < 2048; i += 256) d[i] = s[i];
    }
    __syncthreads();

    // ---- mh = O @ Wc + bc : A = QB tiles, B = Wc tile (in S2); out -> KB tiles ----
    {
        float acc[4][4];
        gemm_tiles(sb, QB, S2, wm, wn, lane, acc);
#pragma unroll
        for (int n = 0; n < 4; n++) {
            int row = wm * 16 + (lane >> 2);
            int col = wn * 32 + n * 8 + ((lane & 3) << 1);
            float b0 = sBc[col], b1 = sBc[col + 1];
#pragma unroll
            for (int hh = 0; hh < 2; hh++) {
                int r = row + 8 * hh;
                if (r < 112)
                    st_hi(smem8 + KB, r, col, acc[n][2 * hh] + b0, acc[n][2 * hh + 1] + b1);
            }
        }
        __syncthreads();
    }

    // ---- score2 = mh @ nodes^T; epilogue folds clip*tanh + mask; logits -> smem byte 0 ----
    const float INV_SQRT_EMB = 0.08838834764831843f;
    {
        float acc[4][4];
        gemm_tiles(sb, KB, NT, wm, wn, lane, acc);
        __syncthreads();
        float* SCp = (float*)smem8;
#pragma unroll
        for (int n = 0; n < 4; n++) {
            int row = wm * 16 + (lane >> 2);
            int col = wn * 32 + n * 8 + ((lane & 3) << 1);
#pragma unroll
            for (int hh = 0; hh < 2; hh++) {
                int r = row + 8 * hh;
                if (r >= Pn) continue;
                float v0, v1;
                if (col < Nn) {
                    float m0 = __half2float(*(__half*)(smem8 + MK + (r * MKW + col) * 2));
                    v0 = tanh10(acc[n][2 * hh] * INV_SQRT_EMB) + m0;
                } else v0 = -INFINITY;
                if (col + 1 < Nn) {
                    float m1 = __half2float(*(__half*)(smem8 + MK + (r * MKW + col + 1) * 2));
                    v1 = tanh10(acc[n][2 * hh + 1] * INV_SQRT_EMB) + m1;
                } else v1 = -INFINITY;
                *(float2*)&SCp[r * LDSR + col] = make_float2(v0, v1);
            }
        }
        __syncthreads();
    }

    // ---- final: softmax over precomputed logits (1 row per warp) ----
    const float* SCp = (const float*)smem8;
    float* gOut = out + (size_t)b * Pn * Nn;
    for (int p = wid; p < Pn; p += 32) {
        float s[4];
        int nn[4];
#pragma unroll
        for (int j = 0; j < 4; j++) {
            int n = lane + 32 * j;
            nn[j] = n;
            s[j] = (n < Nn) ? SCp[p * LDSR + n] : -INFINITY;
        }
        float mx = fmaxf(fmaxf(s[0], s[1]), fmaxf(s[2], s[3]));
#pragma unroll
        for (int off = 16; off; off >>= 1)
            mx = fmaxf(mx, __shfl_xor_sync(0xffffffffu, mx, off));
        float sum = 0.f;
#pragma unroll
        for (int j = 0; j < 4; j++) { s[j] = __expf(s[j] - mx); sum += s[j]; }
#pragma unroll
        for (int off = 16; off; off >>= 1)
            sum += __shfl_xor_sync(0xffffffffu, sum, off);
        const float inv = 1.f / sum;
#pragma unroll
        for (int j = 0; j < 4; j++)
            if (nn[j] < Nn) gOut[p * Nn + nn[j]] = s[j] * inv;
    }
}

extern "C" void kernel_launch(void* const* d_in, const int* in_sizes, int n_in,
                              void* d_out, int out_size) {
    const float* eln   = (const float*)d_in[0];
    const float* load_ = (const float*)d_in[1];
    const float* time_ = (const float*)d_in[2];
    const float* len_  = (const float*)d_in[3];
    const float* ropen = (const float*)d_in[4];
    const float* mask  = (const float*)d_in[5];
    const float* nodes = (const float*)d_in[6];
    const float* Wq    = (const float*)d_in[7];
    const float* Wk    = (const float*)d_in[8];
    const float* Wv    = (const float*)d_in[9];
    const float* Wc    = (const float*)d_in[10];
    const float* bc    = (const float*)d_in[11];
    float* out = (float*)d_out;

    prep_weights<<<dim3(4, 4), 256>>>(Wq, Wk, Wv, Wc);
    cudaFuncSetAttribute(vrp_decoder_kernel,
                         cudaFuncAttributeMaxDynamicSharedMemorySize, SMEM_TOTAL);
    vrp_decoder_kernel<<<Bn, TPB, SMEM_TOTAL>>>(
        eln, load_, time_, len_, ropen, mask, nodes, bc, out);
}